// round 12
// baseline (speedup 1.0000x reference)
#include <cuda_runtime.h>
#include <cuda_bf16.h>
#include <math_constants.h>
#include <cstdint>

#define Bsz 4
#define Nn 1024
#define Dd 1024
#define Hh 16
#define QKd 64
#define HIDd 4096
#define BH 64           // B*H
#define BNr 4096        // B*N
#define HQ 1024         // H*QK
#define BETA 0.125f
#define LSE_PARTS 256

typedef unsigned long long u64;
typedef __nv_bfloat16 bf16;

__device__ __forceinline__ uint32_t smem_u32(const void* p) {
    uint32_t a;
    asm("{ .reg .u64 t; cvta.to.shared.u64 t, %1; cvt.u32.u64 %0, t; }" : "=r"(a) : "l"(p));
    return a;
}
__device__ __forceinline__ void split2(float v, bf16& h, bf16& l) {
    h = __float2bfloat16(v);
    l = __float2bfloat16(v - __bfloat162float(h));
}
__device__ __forceinline__ uint32_t pack_bf2(float a, float b) {
    bf16 t[2] = {__float2bfloat16(a), __float2bfloat16(b)};
    return *(const uint32_t*)t;
}

// -------- device scratch --------
__device__ bf16   g_Sb [(size_t)BH * Nn * Nn];    // beta*scores bf16 (128MB)
__device__ float  g_lse [BH * Nn];
__device__ float  g_pmax[(size_t)BH * 8 * Nn];
__device__ float  g_psum[(size_t)BH * 8 * Nn];
__device__ double g_lse_part[LSE_PARTS];
__device__ double g_h2_part [(BNr / 128) * (HIDd / 128)];

__device__ bf16 g_x1 [(size_t)BNr * Dd],   g_x2 [(size_t)BNr * Dd];
__device__ bf16 g_wq1[(size_t)HQ * Dd];
__device__ bf16 g_wk1[(size_t)HQ * Dd];
__device__ bf16 g_wt [(size_t)Dd * 2048];                  // [d][ WqT | WkT ]
__device__ bf16 g_wh1[(size_t)Dd * HIDd],  g_wh2[(size_t)Dd * HIDd];
__device__ bf16 g_wht1[(size_t)HIDd * Dd], g_wht2[(size_t)HIDd * Dd];
__device__ bf16 g_hb1[(size_t)BNr * HIDd], g_hb2[(size_t)BNr * HIDd];
__device__ bf16 g_dm [(size_t)BNr * 2048];                 // [b*n][ dqm | dkm ]
__device__ bf16 g_q1[(size_t)BH * Nn * QKd];
__device__ bf16 g_k1[(size_t)BH * Nn * QKd];
__device__ bf16 g_qt[(size_t)BH * QKd * Nn], g_kt[(size_t)BH * QKd * Nn];

// ============================================================================
// Converters / transposes
// ============================================================================
__global__ void __launch_bounds__(256) split_plain4(
    const float* __restrict__ in, bf16* __restrict__ o1, bf16* __restrict__ o2)
{
    size_t i = ((size_t)blockIdx.x * 256 + threadIdx.x) * 4;
    float4 v = *(const float4*)(in + i);
    bf16 h[4], l[4];
    split2(v.x, h[0], l[0]); split2(v.y, h[1], l[1]);
    split2(v.z, h[2], l[2]); split2(v.w, h[3], l[3]);
    *(u64*)(o1 + i) = *(const u64*)h;
    *(u64*)(o2 + i) = *(const u64*)l;
}
__global__ void __launch_bounds__(256) cvt_plain4(
    const float* __restrict__ in, bf16* __restrict__ o1)
{
    size_t i = ((size_t)blockIdx.x * 256 + threadIdx.x) * 4;
    float4 v = *(const float4*)(in + i);
    bf16 h[4] = {__float2bfloat16(v.x), __float2bfloat16(v.y),
                 __float2bfloat16(v.z), __float2bfloat16(v.w)};
    *(u64*)(o1 + i) = *(const u64*)h;
}
__global__ void __launch_bounds__(256) trans_cvt1(
    const float* __restrict__ in, bf16* __restrict__ out, int R, int C, int OS)
{
    __shared__ float tile[32][33];
    const int c0 = blockIdx.x * 32, r0 = blockIdx.y * 32;
    const int tx = threadIdx.x & 31, ty = threadIdx.x >> 5;
    #pragma unroll
    for (int i = 0; i < 4; i++)
        tile[ty + i * 8][tx] = in[(size_t)(r0 + ty + i * 8) * C + c0 + tx];
    __syncthreads();
    #pragma unroll
    for (int i = 0; i < 4; i++)
        out[(size_t)(c0 + ty + i * 8) * OS + r0 + tx] = __float2bfloat16(tile[tx][ty + i * 8]);
}
__global__ void __launch_bounds__(256) trans_split(
    const float* __restrict__ in, bf16* __restrict__ o1, bf16* __restrict__ o2,
    int R, int C, int OS)
{
    __shared__ float tile[32][33];
    const int c0 = blockIdx.x * 32, r0 = blockIdx.y * 32;
    const int tx = threadIdx.x & 31, ty = threadIdx.x >> 5;
    #pragma unroll
    for (int i = 0; i < 4; i++)
        tile[ty + i * 8][tx] = in[(size_t)(r0 + ty + i * 8) * C + c0 + tx];
    __syncthreads();
    #pragma unroll
    for (int i = 0; i < 4; i++) {
        bf16 h, l; split2(tile[tx][ty + i * 8], h, l);
        size_t off = (size_t)(c0 + ty + i * 8) * OS + r0 + tx;
        o1[off] = h; o2[off] = l;
    }
}
__global__ void __launch_bounds__(256) trans_qk(
    const bf16* __restrict__ Q, const bf16* __restrict__ K,
    bf16* __restrict__ Qt, bf16* __restrict__ Kt)
{
    __shared__ bf16 tq[32][34], tk[32][34];
    const int n0 = blockIdx.x * 32, q0 = blockIdx.y * 32, bh = blockIdx.z;
    const bf16* Qb = Q + (size_t)bh * Nn * QKd;
    const bf16* Kb = K + (size_t)bh * Nn * QKd;
    const int tx = threadIdx.x & 31, ty = threadIdx.x >> 5;
    #pragma unroll
    for (int i = 0; i < 4; i++) {
        int n = ty + i * 8;
        tq[n][tx] = Qb[(size_t)(n0 + n) * QKd + q0 + tx];
        tk[n][tx] = Kb[(size_t)(n0 + n) * QKd + q0 + tx];
    }
    __syncthreads();
    #pragma unroll
    for (int i = 0; i < 4; i++) {
        int r = ty + i * 8;
        Qt[((size_t)bh * QKd + q0 + r) * Nn + n0 + tx] = tq[tx][r];
        Kt[((size_t)bh * QKd + q0 + r) * Nn + n0 + tx] = tk[tx][r];
    }
}

// ============================================================================
// HMMA GEMM, NS-sweep hi/lo split, 3-stage cp.async pipeline.
//   EPI=0: fp32 C (+)= alpha*D
//   EPI=1: bf16 scatter to [bh][n][qk] (O1)
//   EPI=2: relu; bf16-split to O1/O2; sum(v^2) partials
//   EPI=4: bf16 out O1 = bf16(alpha*D) + per-row (max, expsum) partials
// ============================================================================
#define TILE_B 36864
#define ROWSTR 144
#define TG_SMEM (3 * TILE_B)

template<int EPI, int NS>
__global__ void __launch_bounds__(256) tgemm(
    const bf16* __restrict__ A1, const bf16* __restrict__ A2,
    const bf16* __restrict__ B1, const bf16* __restrict__ B2,
    float* __restrict__ C, int Ncols, int Kglob, float alpha, int accFlag,
    bf16* __restrict__ O1, bf16* __restrict__ O2, double* __restrict__ part,
    float* __restrict__ pmax, float* __restrict__ psum,
    size_t zsA, size_t zsB, size_t zsC)
{
    extern __shared__ char dsm[];
    __shared__ double sred[256];
    __shared__ float smax[128][5], ssum[128][5];
    const uint32_t sbase = smem_u32(dsm);

    const size_t zA = (size_t)blockIdx.z * zsA;
    const size_t zB = (size_t)blockIdx.z * zsB;
    A1 += zA; B1 += zB;
    if (NS == 3) { A2 += zA; B2 += zB; }
    if (EPI == 1 || EPI == 4) O1 += (size_t)blockIdx.z * zsC;
    else                      C  += (size_t)blockIdx.z * zsC;

    const int t = threadIdx.x;
    const int wid = t >> 5, lane = t & 31;
    const int m0 = blockIdx.y * 128, n0 = blockIdx.x * 128;
    const int wm = wid >> 2, wn = wid & 3;

    const int KC = Kglob >> 6;
    const int TOT = NS * KC;

    float acc[4][4][4];
    #pragma unroll
    for (int i = 0; i < 4; i++)
        #pragma unroll
        for (int j = 0; j < 4; j++)
            #pragma unroll
            for (int r = 0; r < 4; r++) acc[i][j][r] = 0.f;

    const int lrow = t >> 3;
    const int lseg = (t & 7) * 8;

    auto issue_load = [&](int c) {
        const int p = (NS == 3) ? (c / KC) : 0;
        const int kb = c - p * KC;
        const bf16* Ap = (NS == 3 && p == 2) ? A2 : A1;
        const bf16* Bp = (NS == 3 && p == 1) ? B2 : B1;
        const uint32_t abase = sbase + (uint32_t)(c % 3) * TILE_B;
        const uint32_t bbase = abase + 18432;
        const size_t kEl = (size_t)(kb << 6) + lseg;
        #pragma unroll
        for (int i = 0; i < 4; i++) {
            const int row = lrow + i * 32;
            asm volatile("cp.async.cg.shared.global [%0], [%1], 16;"
                :: "r"(abase + row * ROWSTR + lseg * 2), "l"(Ap + (size_t)(m0 + row) * Kglob + kEl));
            asm volatile("cp.async.cg.shared.global [%0], [%1], 16;"
                :: "r"(bbase + row * ROWSTR + lseg * 2), "l"(Bp + (size_t)(n0 + row) * Kglob + kEl));
        }
        asm volatile("cp.async.commit_group;" ::: "memory");
    };

    issue_load(0);
    issue_load(1);

    for (int c = 0; c < TOT; c++) {
        if (c + 2 < TOT) {
            issue_load(c + 2);
            asm volatile("cp.async.wait_group 2;" ::: "memory");
        } else if (c + 1 < TOT) {
            asm volatile("cp.async.wait_group 1;" ::: "memory");
        } else {
            asm volatile("cp.async.wait_group 0;" ::: "memory");
        }
        __syncthreads();

        const uint32_t abase = sbase + (uint32_t)(c % 3) * TILE_B;
        const uint32_t bbase = abase + 18432;
        const int acol = ((lane >> 4) * 8) * 2;
        const int arow = (lane & 15);
        const int brow = (lane & 7) + ((lane >> 3) & 1) * 8;

        #pragma unroll
        for (int kk = 0; kk < 4; kk++) {
            const int kbyte = kk * 32 + acol;
            uint32_t a[4][4];
            #pragma unroll
            for (int mf = 0; mf < 4; mf++) {
                const uint32_t ad = abase + (wm * 64 + mf * 16 + arow) * ROWSTR + kbyte;
                asm volatile("ldmatrix.sync.aligned.m8n8.x4.shared.b16 {%0,%1,%2,%3}, [%4];"
                    : "=r"(a[mf][0]), "=r"(a[mf][1]), "=r"(a[mf][2]), "=r"(a[mf][3]) : "r"(ad));
            }
            uint32_t b[4][2];
            #pragma unroll
            for (int nfp = 0; nfp < 2; nfp++) {
                const uint32_t bd = bbase + (wn * 32 + nfp * 16 + brow) * ROWSTR + kbyte;
                uint32_t r0, r1, r2, r3;
                asm volatile("ldmatrix.sync.aligned.m8n8.x4.shared.b16 {%0,%1,%2,%3}, [%4];"
                    : "=r"(r0), "=r"(r1), "=r"(r2), "=r"(r3) : "r"(bd));
                b[nfp * 2 + 0][0] = r0; b[nfp * 2 + 0][1] = r2;
                b[nfp * 2 + 1][0] = r1; b[nfp * 2 + 1][1] = r3;
            }
            #pragma unroll
            for (int mf = 0; mf < 4; mf++)
                #pragma unroll
                for (int nf = 0; nf < 4; nf++)
                    asm volatile(
                        "mma.sync.aligned.m16n8k16.row.col.f32.bf16.bf16.f32 "
                        "{%0,%1,%2,%3}, {%4,%5,%6,%7}, {%8,%9}, {%0,%1,%2,%3};"
                        : "+f"(acc[mf][nf][0]), "+f"(acc[mf][nf][1]),
                          "+f"(acc[mf][nf][2]), "+f"(acc[mf][nf][3])
                        : "r"(a[mf][0]), "r"(a[mf][1]), "r"(a[mf][2]), "r"(a[mf][3]),
                          "r"(b[nf][0]), "r"(b[nf][1]));
        }
        __syncthreads();
    }

    const int gr = lane >> 2;
    const int gc = (lane & 3) * 2;
    float hs = 0.f;

    if (EPI == 4) {
        // store bf16(alpha*D) + per-row online-softmax partials
        float rmax[8];
        #pragma unroll
        for (int i = 0; i < 8; i++) rmax[i] = -CUDART_INF_F;
        #pragma unroll
        for (int mf = 0; mf < 4; mf++)
            #pragma unroll
            for (int nf = 0; nf < 4; nf++) {
                const int col = n0 + wn * 32 + nf * 8 + gc;
                #pragma unroll
                for (int half = 0; half < 2; half++) {
                    const int row = m0 + wm * 64 + mf * 16 + gr + half * 8;
                    bf16 ba = __float2bfloat16(acc[mf][nf][half * 2] * alpha);
                    bf16 bb = __float2bfloat16(acc[mf][nf][half * 2 + 1] * alpha);
                    bf16 pr[2] = {ba, bb};
                    *(uint32_t*)&O1[(size_t)row * Ncols + col] = *(const uint32_t*)pr;
                    float fa = __bfloat162float(ba), fb = __bfloat162float(bb);
                    acc[mf][nf][half * 2] = fa; acc[mf][nf][half * 2 + 1] = fb;
                    rmax[mf * 2 + half] = fmaxf(rmax[mf * 2 + half], fmaxf(fa, fb));
                }
            }
        float rsum[8];
        #pragma unroll
        for (int i = 0; i < 8; i++) rsum[i] = 0.f;
        #pragma unroll
        for (int mf = 0; mf < 4; mf++)
            #pragma unroll
            for (int nf = 0; nf < 4; nf++)
                #pragma unroll
                for (int half = 0; half < 2; half++)
                    rsum[mf * 2 + half] += __expf(acc[mf][nf][half * 2]     - rmax[mf * 2 + half])
                                         + __expf(acc[mf][nf][half * 2 + 1] - rmax[mf * 2 + half]);
        // lane-group (4 lanes per row) reduce
        #pragma unroll
        for (int o = 1; o <= 2; o <<= 1)
            #pragma unroll
            for (int i = 0; i < 8; i++) {
                float m2 = __shfl_xor_sync(0xffffffffu, rmax[i], o);
                float s2 = __shfl_xor_sync(0xffffffffu, rsum[i], o);
                float nm = fmaxf(rmax[i], m2);
                rsum[i] = rsum[i] * __expf(rmax[i] - nm) + s2 * __expf(m2 - nm);
                rmax[i] = nm;
            }
        if ((lane & 3) == 0) {
            #pragma unroll
            for (int mf = 0; mf < 4; mf++)
                #pragma unroll
                for (int half = 0; half < 2; half++) {
                    int rl = wm * 64 + mf * 16 + gr + half * 8;
                    smax[rl][wn] = rmax[mf * 2 + half];
                    ssum[rl][wn] = rsum[mf * 2 + half];
                }
        }
        __syncthreads();
        if (t < 128) {
            float m = smax[t][0];
            #pragma unroll
            for (int w = 1; w < 4; w++) m = fmaxf(m, smax[t][w]);
            float s = 0.f;
            #pragma unroll
            for (int w = 0; w < 4; w++) s += ssum[t][w] * __expf(smax[t][w] - m);
            size_t pidx = ((size_t)blockIdx.z * gridDim.x + blockIdx.x) * (size_t)(gridDim.y * 128)
                        + m0 + t;
            pmax[pidx] = m; psum[pidx] = s;
        }
        return;
    }

    #pragma unroll
    for (int mf = 0; mf < 4; mf++) {
        #pragma unroll
        for (int nf = 0; nf < 4; nf++) {
            const int col = n0 + wn * 32 + nf * 8 + gc;
            #pragma unroll
            for (int half = 0; half < 2; half++) {
                const int row = m0 + wm * 64 + mf * 16 + gr + half * 8;
                const float va = acc[mf][nf][half * 2];
                const float vb = acc[mf][nf][half * 2 + 1];
                if (EPI == 1) {
                    const int h_ = col >> 6, q_ = col & 63;
                    const int b_ = row >> 10, n_ = row & 1023;
                    *(uint32_t*)&O1[(((size_t)(b_ * Hh + h_)) * Nn + n_) * QKd + q_] =
                        pack_bf2(va, vb);
                } else if (EPI == 2) {
                    const size_t off = (size_t)row * Ncols + col;
                    const float v0 = fmaxf(va, 0.f), v1 = fmaxf(vb, 0.f);
                    hs = fmaf(v0, v0, fmaf(v1, v1, hs));
                    bf16 h0, l0, h1, l1;
                    split2(v0, h0, l0); split2(v1, h1, l1);
                    bf16 hh[2] = {h0, h1}, ll[2] = {l0, l1};
                    *(uint32_t*)(O1 + off) = *(const uint32_t*)hh;
                    *(uint32_t*)(O2 + off) = *(const uint32_t*)ll;
                } else {
                    const size_t off = (size_t)row * Ncols + col;
                    float2 v = make_float2(va * alpha, vb * alpha);
                    if (accFlag) {
                        float2 o = *(const float2*)&C[off];
                        v.x += o.x; v.y += o.y;
                    }
                    *(float2*)&C[off] = v;
                }
            }
        }
    }
    if (EPI == 2) {
        sred[t] = (double)hs;
        __syncthreads();
        for (int o = 128; o > 0; o >>= 1) { if (t < o) sred[t] += sred[t + o]; __syncthreads(); }
        if (t == 0) part[blockIdx.y * gridDim.x + blockIdx.x] = sred[0];
    }
}

// ============================================================================
// lse combine: lse[n] = m_glob + log(sum exp(m_i - m_glob) * s_i); lse partials.
// ============================================================================
__global__ void __launch_bounds__(256) lse_combine(
    const float* __restrict__ pmax, const float* __restrict__ psum,
    float* __restrict__ lse, double* __restrict__ lse_part)
{
    __shared__ double sm[256];
    const int idx = blockIdx.x * 256 + threadIdx.x;   // bh*1024 + n
    const int bh = idx >> 10, n = idx & 1023;
    float ms[8], ss[8];
    float m = -CUDART_INF_F;
    #pragma unroll
    for (int i = 0; i < 8; i++) {
        ms[i] = pmax[((size_t)bh * 8 + i) * Nn + n];
        ss[i] = psum[((size_t)bh * 8 + i) * Nn + n];
        m = fmaxf(m, ms[i]);
    }
    float s = 0.f;
    #pragma unroll
    for (int i = 0; i < 8; i++) s += ss[i] * __expf(ms[i] - m);
    const float l = m + logf(s);
    lse[idx] = l;
    sm[threadIdx.x] = (double)l;
    __syncthreads();
    for (int o = 128; o > 0; o >>= 1) {
        if (threadIdx.x < o) sm[threadIdx.x] += sm[threadIdx.x + o];
        __syncthreads();
    }
    if (threadIdx.x == 0) lse_part[blockIdx.x] = sm[0];
}

// ============================================================================
// dQ-GEMM: dm[(b*N+n)][h*64+q] = bf16(-sum_m P[n][m] * Kt[q][m]),
// with P = exp(Sb - lse[n]) computed on the staged tile in smem.
// ============================================================================
#define DQ_STAGE 27648
__global__ void __launch_bounds__(256) att_dq_h(
    const bf16* __restrict__ S, const bf16* __restrict__ Kt,
    const float* __restrict__ lse, bf16* __restrict__ dm)
{
    extern __shared__ char dsm[];
    const uint32_t sbase = smem_u32(dsm);
    const int t = threadIdx.x, wid = t >> 5, lane = t & 31;
    const int bh = blockIdx.y, n0 = blockIdx.x * 128;
    const bf16* Ag = S + (size_t)bh * Nn * Nn;
    const bf16* Bg = Kt + (size_t)bh * QKd * Nn;

    float acc[8][4];
    #pragma unroll
    for (int i = 0; i < 8; i++)
        #pragma unroll
        for (int r = 0; r < 4; r++) acc[i][r] = 0.f;

    const int lrow = t >> 3, lseg = (t & 7) * 8;
    const int xr = t >> 1, xh = (t & 1) * 64;           // transform: row, byte-offset
    const float xlse = lse[bh * Nn + n0 + xr];

    auto load = [&](int kb) {
        const uint32_t ab = sbase + (uint32_t)(kb & 1) * DQ_STAGE;
        const uint32_t bb = ab + 18432;
        const size_t kEl = (size_t)(kb << 6) + lseg;
        #pragma unroll
        for (int i = 0; i < 4; i++) {
            const int row = lrow + i * 32;
            asm volatile("cp.async.cg.shared.global [%0], [%1], 16;"
                :: "r"(ab + row * ROWSTR + lseg * 2), "l"(Ag + (size_t)(n0 + row) * Nn + kEl));
        }
        #pragma unroll
        for (int i = 0; i < 2; i++) {
            const int row = lrow + i * 32;
            asm volatile("cp.async.cg.shared.global [%0], [%1], 16;"
                :: "r"(bb + row * ROWSTR + lseg * 2), "l"(Bg + (size_t)row * Nn + kEl));
        }
        asm volatile("cp.async.commit_group;" ::: "memory");
    };

    load(0);
    for (int kb = 0; kb < 16; kb++) {
        if (kb < 15) { load(kb + 1); asm volatile("cp.async.wait_group 1;" ::: "memory"); }
        else         { asm volatile("cp.async.wait_group 0;" ::: "memory"); }
        __syncthreads();
        // exp transform on staged A tile (128 rows x 64 cols)
        {
            char* abuf = dsm + (size_t)(kb & 1) * DQ_STAGE + xr * ROWSTR + xh;
            #pragma unroll
            for (int j = 0; j < 4; j++) {
                uint4 w = *(uint4*)(abuf + j * 16);
                __nv_bfloat162* p2 = (__nv_bfloat162*)&w;
                #pragma unroll
                for (int q = 0; q < 4; q++) {
                    float2 f = __bfloat1622float2(p2[q]);
                    p2[q] = __floats2bfloat162_rn(__expf(f.x - xlse), __expf(f.y - xlse));
                }
                *(uint4*)(abuf + j * 16) = w;
            }
        }
        __syncthreads();
        const uint32_t ab = sbase + (uint32_t)(kb & 1) * DQ_STAGE;
        const uint32_t bb = ab + 18432;
        const int acol = ((lane >> 4) * 8) * 2;
        const int arow = lane & 15;
        const int brow = (lane & 7) + ((lane >> 3) & 1) * 8;
        #pragma unroll
        for (int kk = 0; kk < 4; kk++) {
            const int kbyte = kk * 32 + acol;
            uint32_t a[4];
            asm volatile("ldmatrix.sync.aligned.m8n8.x4.shared.b16 {%0,%1,%2,%3}, [%4];"
                : "=r"(a[0]), "=r"(a[1]), "=r"(a[2]), "=r"(a[3])
                : "r"(ab + (wid * 16 + arow) * ROWSTR + kbyte));
            uint32_t b[8][2];
            #pragma unroll
            for (int nfp = 0; nfp < 4; nfp++) {
                uint32_t r0, r1, r2, r3;
                asm volatile("ldmatrix.sync.aligned.m8n8.x4.shared.b16 {%0,%1,%2,%3}, [%4];"
                    : "=r"(r0), "=r"(r1), "=r"(r2), "=r"(r3)
                    : "r"(bb + (nfp * 16 + brow) * ROWSTR + kbyte));
                b[nfp * 2 + 0][0] = r0; b[nfp * 2 + 0][1] = r2;
                b[nfp * 2 + 1][0] = r1; b[nfp * 2 + 1][1] = r3;
            }
            #pragma unroll
            for (int nf = 0; nf < 8; nf++)
                asm volatile(
                    "mma.sync.aligned.m16n8k16.row.col.f32.bf16.bf16.f32 "
                    "{%0,%1,%2,%3}, {%4,%5,%6,%7}, {%8,%9}, {%0,%1,%2,%3};"
                    : "+f"(acc[nf][0]), "+f"(acc[nf][1]), "+f"(acc[nf][2]), "+f"(acc[nf][3])
                    : "r"(a[0]), "r"(a[1]), "r"(a[2]), "r"(a[3]),
                      "r"(b[nf][0]), "r"(b[nf][1]));
        }
        __syncthreads();
    }
    const int gr = lane >> 2, gc = (lane & 3) * 2;
    const int b_ = bh >> 4, h_ = bh & 15;
    #pragma unroll
    for (int nf = 0; nf < 8; nf++) {
        const int col = nf * 8 + gc;
        #pragma unroll
        for (int half = 0; half < 2; half++) {
            const int n = n0 + wid * 16 + gr + half * 8;
            *(uint32_t*)&dm[((size_t)(b_ * 1024 + n)) * 2048 + h_ * 64 + col] =
                pack_bf2(-acc[nf][half * 2], -acc[nf][half * 2 + 1]);
        }
    }
}

// ============================================================================
// dK-GEMM: dm[(b*N+m)][1024 + h*64+q] = bf16(-sum_n P[n][m] * Qt[q][n]),
// P = exp(Sb - lse[n]) computed on the staged (transposed-use) tile.
// ============================================================================
#define DK_ASTR 272
#define DK_STAGE 26624
__global__ void __launch_bounds__(256) att_dk_h(
    const bf16* __restrict__ S, const bf16* __restrict__ Qt,
    const float* __restrict__ lse, bf16* __restrict__ dm)
{
    extern __shared__ char dsm[];
    const uint32_t sbase = smem_u32(dsm);
    const int t = threadIdx.x, wid = t >> 5, lane = t & 31;
    const int bh = blockIdx.y, m0 = blockIdx.x * 128;
    const bf16* Ag = S + (size_t)bh * Nn * Nn;
    const bf16* Bg = Qt + (size_t)bh * QKd * Nn;

    float acc[8][4];
    #pragma unroll
    for (int i = 0; i < 8; i++)
        #pragma unroll
        for (int r = 0; r < 4; r++) acc[i][r] = 0.f;

    const int xr = t >> 2, xq = (t & 3) * 64;          // transform: row (n-local), byte-offset

    auto load = [&](int kb) {
        const uint32_t ab = sbase + (uint32_t)(kb & 1) * DK_STAGE;
        const uint32_t bb = ab + 17408;
        const int ar = t >> 4, aseg = (t & 15) * 8;
        #pragma unroll
        for (int i = 0; i < 4; i++) {
            const int row = ar + i * 16;
            asm volatile("cp.async.cg.shared.global [%0], [%1], 16;"
                :: "r"(ab + row * DK_ASTR + aseg * 2),
                   "l"(Ag + (size_t)((kb << 6) + row) * Nn + m0 + aseg));
        }
        const int br = t >> 3, bseg = (t & 7) * 8;
        #pragma unroll
        for (int i = 0; i < 2; i++) {
            const int row = br + i * 32;
            asm volatile("cp.async.cg.shared.global [%0], [%1], 16;"
                :: "r"(bb + row * ROWSTR + bseg * 2),
                   "l"(Bg + (size_t)row * Nn + (kb << 6) + bseg));
        }
        asm volatile("cp.async.commit_group;" ::: "memory");
    };

    load(0);
    for (int kb = 0; kb < 16; kb++) {
        if (kb < 15) { load(kb + 1); asm volatile("cp.async.wait_group 1;" ::: "memory"); }
        else         { asm volatile("cp.async.wait_group 0;" ::: "memory"); }
        __syncthreads();
        // exp transform on staged A tile (64 n-rows x 128 m-cols)
        {
            const float xlse = lse[bh * Nn + (kb << 6) + xr];
            char* abuf = dsm + (size_t)(kb & 1) * DK_STAGE + xr * DK_ASTR + xq;
            #pragma unroll
            for (int j = 0; j < 4; j++) {
                uint4 w = *(uint4*)(abuf + j * 16);
                __nv_bfloat162* p2 = (__nv_bfloat162*)&w;
                #pragma unroll
                for (int q = 0; q < 4; q++) {
                    float2 f = __bfloat1622float2(p2[q]);
                    p2[q] = __floats2bfloat162_rn(__expf(f.x - xlse), __expf(f.y - xlse));
                }
                *(uint4*)(abuf + j * 16) = w;
            }
        }
        __syncthreads();
        const uint32_t ab = sbase + (uint32_t)(kb & 1) * DK_STAGE;
        const uint32_t bb = ab + 17408;
        const int tl = lane >> 3;
        const int brow = (lane & 7) + ((lane >> 3) & 1) * 8;
        const int bcol = ((lane >> 4) * 8) * 2;
        #pragma unroll
        for (int kk = 0; kk < 4; kk++) {
            uint32_t a[4];
            const uint32_t ad = ab + (kk * 16 + (tl >> 1) * 8 + (lane & 7)) * DK_ASTR
                              + (wid * 16 + (tl & 1) * 8) * 2;
            asm volatile("ldmatrix.sync.aligned.m8n8.x4.trans.shared.b16 {%0,%1,%2,%3}, [%4];"
                : "=r"(a[0]), "=r"(a[1]), "=r"(a[2]), "=r"(a[3]) : "r"(ad));
            uint32_t b[8][2];
            const int kbyte = kk * 32 + bcol;
            #pragma unroll
            for (int nfp = 0; nfp < 4; nfp++) {
                uint32_t r0, r1, r2, r3;
                asm volatile("ldmatrix.sync.aligned.m8n8.x4.shared.b16 {%0,%1,%2,%3}, [%4];"
                    : "=r"(r0), "=r"(r1), "=r"(r2), "=r"(r3)
                    : "r"(bb + (nfp * 16 + brow) * ROWSTR + kbyte));
                b[nfp * 2 + 0][0] = r0; b[nfp * 2 + 0][1] = r2;
                b[nfp * 2 + 1][0] = r1; b[nfp * 2 + 1][1] = r3;
            }
            #pragma unroll
            for (int nf = 0; nf < 8; nf++)
                asm volatile(
                    "mma.sync.aligned.m16n8k16.row.col.f32.bf16.bf16.f32 "
                    "{%0,%1,%2,%3}, {%4,%5,%6,%7}, {%8,%9}, {%0,%1,%2,%3};"
                    : "+f"(acc[nf][0]), "+f"(acc[nf][1]), "+f"(acc[nf][2]), "+f"(acc[nf][3])
                    : "r"(a[0]), "r"(a[1]), "r"(a[2]), "r"(a[3]),
                      "r"(b[nf][0]), "r"(b[nf][1]));
        }
        __syncthreads();
    }
    const int gr = lane >> 2, gc = (lane & 3) * 2;
    const int b_ = bh >> 4, h_ = bh & 15;
    #pragma unroll
    for (int nf = 0; nf < 8; nf++) {
        const int col = nf * 8 + gc;
        #pragma unroll
        for (int half = 0; half < 2; half++) {
            const int m = m0 + wid * 16 + gr + half * 8;
            *(uint32_t*)&dm[((size_t)(b_ * 1024 + m)) * 2048 + 1024 + h_ * 64 + col] =
                pack_bf2(-acc[nf][half * 2], -acc[nf][half * 2 + 1]);
        }
    }
}

// ============================================================================
// Final energy: E = -(1/BETA) * sum(lse) - 0.5 * sum(h^2). Deterministic.
// ============================================================================
__global__ void energy_final(const double* __restrict__ lse_part,
                             const double* __restrict__ h2_part,
                             float* __restrict__ out)
{
    __shared__ double sm[256];
    int t = threadIdx.x;
    double s = 0.0;
    for (int i = t; i < LSE_PARTS; i += 256) s += lse_part[i];
    double s2 = 0.0;
    for (int i = t; i < (BNr / 128) * (HIDd / 128); i += 256) s2 += h2_part[i];
    sm[t] = -8.0 * s - 0.5 * s2;
    __syncthreads();
    for (int o = 128; o > 0; o >>= 1) { if (t < o) sm[t] += sm[t + o]; __syncthreads(); }
    if (t == 0) out[(size_t)BNr * Dd] = (float)sm[0];
}

// ============================================================================
// Host launcher
// ============================================================================
extern "C" void kernel_launch(void* const* d_in, const int* in_sizes, int n_in,
                              void* d_out, int out_size)
{
    const float* x    = (const float*)d_in[0];
    const float* Wq   = (const float*)d_in[1];
    const float* Wk   = (const float*)d_in[2];
    const float* Whop = (const float*)d_in[3];
    float* out = (float*)d_out;

    bf16 *pSb;
    float *pLseV, *pPmax, *pPsum;
    double *pLse, *pH2;
    bf16 *px1, *px2, *pwq1, *pwk1, *pwt;
    bf16 *pwh1, *pwh2, *pwht1, *pwht2, *phb1, *phb2, *pdm;
    bf16 *pq1, *pk1, *pqt, *pkt;

    cudaGetSymbolAddress((void**)&pSb,  g_Sb);
    cudaGetSymbolAddress((void**)&pLseV,g_lse);
    cudaGetSymbolAddress((void**)&pPmax,g_pmax);
    cudaGetSymbolAddress((void**)&pPsum,g_psum);
    cudaGetSymbolAddress((void**)&pLse, g_lse_part);
    cudaGetSymbolAddress((void**)&pH2,  g_h2_part);
    cudaGetSymbolAddress((void**)&px1,  g_x1);  cudaGetSymbolAddress((void**)&px2,  g_x2);
    cudaGetSymbolAddress((void**)&pwq1, g_wq1);
    cudaGetSymbolAddress((void**)&pwk1, g_wk1);
    cudaGetSymbolAddress((void**)&pwt,  g_wt);
    cudaGetSymbolAddress((void**)&pwh1, g_wh1); cudaGetSymbolAddress((void**)&pwh2, g_wh2);
    cudaGetSymbolAddress((void**)&pwht1,g_wht1);cudaGetSymbolAddress((void**)&pwht2,g_wht2);
    cudaGetSymbolAddress((void**)&phb1, g_hb1); cudaGetSymbolAddress((void**)&phb2, g_hb2);
    cudaGetSymbolAddress((void**)&pdm,  g_dm);
    cudaGetSymbolAddress((void**)&pq1,  g_q1);
    cudaGetSymbolAddress((void**)&pk1,  g_k1);
    cudaGetSymbolAddress((void**)&pqt,  g_qt);  cudaGetSymbolAddress((void**)&pkt,  g_kt);

    cudaFuncSetAttribute(tgemm<0,1>, cudaFuncAttributeMaxDynamicSharedMemorySize, TG_SMEM);
    cudaFuncSetAttribute(tgemm<0,3>, cudaFuncAttributeMaxDynamicSharedMemorySize, TG_SMEM);
    cudaFuncSetAttribute(tgemm<1,1>, cudaFuncAttributeMaxDynamicSharedMemorySize, TG_SMEM);
    cudaFuncSetAttribute(tgemm<2,3>, cudaFuncAttributeMaxDynamicSharedMemorySize, TG_SMEM);
    cudaFuncSetAttribute(tgemm<4,1>, cudaFuncAttributeMaxDynamicSharedMemorySize, TG_SMEM);
    cudaFuncSetAttribute(att_dq_h, cudaFuncAttributeMaxDynamicSharedMemorySize, 2 * DQ_STAGE);
    cudaFuncSetAttribute(att_dk_h, cudaFuncAttributeMaxDynamicSharedMemorySize, 2 * DK_STAGE);

    dim3 blk(256);

    // 0. input conversions
    split_plain4<<<(BNr * Dd) / 1024, blk>>>(x, px1, px2);
    split_plain4<<<(Dd * HIDd) / 1024, blk>>>(Whop, pwh1, pwh2);
    cvt_plain4<<<(HQ * Dd) / 1024, blk>>>(Wq, pwq1);
    cvt_plain4<<<(HQ * Dd) / 1024, blk>>>(Wk, pwk1);
    trans_cvt1<<<dim3(Dd / 32, HQ / 32), blk>>>(Wq, pwt, HQ, Dd, 2048);
    trans_cvt1<<<dim3(Dd / 32, HQ / 32), blk>>>(Wk, pwt + 1024, HQ, Dd, 2048);
    trans_split<<<dim3(HIDd / 32, Dd / 32), blk>>>(Whop, pwht1, pwht2, Dd, HIDd, Dd);

    // 1-2. Q,K projections (1-sweep) -> bf16 q1/k1 scattered [bh][n][qk]
    tgemm<1,1><<<dim3(HQ / 128, BNr / 128, 1), blk, TG_SMEM>>>(
        px1, nullptr, pwq1, nullptr, nullptr, HQ, Dd, 1.f, 0, pq1, nullptr, nullptr,
        nullptr, nullptr, 0, 0, 0);
    tgemm<1,1><<<dim3(HQ / 128, BNr / 128, 1), blk, TG_SMEM>>>(
        px1, nullptr, pwk1, nullptr, nullptr, HQ, Dd, 1.f, 0, pk1, nullptr, nullptr,
        nullptr, nullptr, 0, 0, 0);

    // 3. transposes for dq/dk B-operands
    trans_qk<<<dim3(Nn / 32, QKd / 32, BH), blk>>>(pq1, pk1, pqt, pkt);

    // 4. S = BETA*QK^T -> bf16 Sb + per-block row softmax partials
    tgemm<4,1><<<dim3(Nn / 128, Nn / 128, BH), blk, TG_SMEM>>>(
        pq1, nullptr, pk1, nullptr, nullptr, Nn, QKd, BETA, 0, pSb, nullptr, nullptr,
        pPmax, pPsum, (size_t)Nn * QKd, (size_t)Nn * QKd, (size_t)Nn * Nn);

    // 5. lse combine (+ energy partials)
    lse_combine<<<LSE_PARTS, blk>>>(pPmax, pPsum, pLseV, pLse);

    // 6. dQm, dKm (exp on the fly) -> merged bf16 [b*n][2048]
    att_dq_h<<<dim3(Nn / 128, BH), blk, 2 * DQ_STAGE>>>(pSb, pkt, pLseV, pdm);
    att_dk_h<<<dim3(Nn / 128, BH), blk, 2 * DK_STAGE>>>(pSb, pqt, pLseV, pdm);

    // 7. grad = dm @ [WqT|WkT]  (one K=2048 GEMM)
    tgemm<0,1><<<dim3(Dd / 128, BNr / 128, 1), blk, TG_SMEM>>>(
        pdm, nullptr, pwt, nullptr, out, Dd, 2048, 1.f, 0, nullptr, nullptr, nullptr,
        nullptr, nullptr, 0, 0, 0);

    // 8. Hb = relu(X @ W_hop) (3-sweep); h2 partials
    tgemm<2,3><<<dim3(HIDd / 128, BNr / 128, 1), blk, TG_SMEM>>>(
        px1, px2, pwht1, pwht2, nullptr, HIDd, Dd, 1.f, 0, phb1, phb2, pH2,
        nullptr, nullptr, 0, 0, 0);

    // 9. grad -= Hb @ W_hop^T (3-sweep)
    tgemm<0,3><<<dim3(Dd / 128, BNr / 128, 1), blk, TG_SMEM>>>(
        phb1, phb2, pwh1, pwh2, out, Dd, HIDd, -1.f, 1, nullptr, nullptr, nullptr,
        nullptr, nullptr, 0, 0, 0);

    // 10. energy scalar
    if (out_size > BNr * Dd)
        energy_final<<<1, 256>>>(pLse, pH2, out);
}

// round 13
// speedup vs baseline: 1.0134x; 1.0134x over previous
#include <cuda_runtime.h>
#include <cuda_bf16.h>
#include <math_constants.h>
#include <cstdint>

#define Bsz 4
#define Nn 1024
#define Dd 1024
#define Hh 16
#define QKd 64
#define HIDd 4096
#define BH 64           // B*H
#define BNr 4096        // B*N
#define HQ 1024         // H*QK
#define BETA 0.125f
#define LSE_PARTS 256

typedef unsigned long long u64;
typedef __nv_bfloat16 bf16;

__device__ __forceinline__ uint32_t smem_u32(const void* p) {
    uint32_t a;
    asm("{ .reg .u64 t; cvta.to.shared.u64 t, %1; cvt.u32.u64 %0, t; }" : "=r"(a) : "l"(p));
    return a;
}
__device__ __forceinline__ void split2(float v, bf16& h, bf16& l) {
    h = __float2bfloat16(v);
    l = __float2bfloat16(v - __bfloat162float(h));
}
__device__ __forceinline__ uint32_t pack_bf2(float a, float b) {
    bf16 t[2] = {__float2bfloat16(a), __float2bfloat16(b)};
    return *(const uint32_t*)t;
}

// -------- device scratch --------
__device__ bf16   g_Sb [(size_t)BH * Nn * Nn];    // beta*scores bf16 (128MB)
__device__ float  g_lse [BH * Nn];
__device__ float  g_pmax[(size_t)BH * 8 * Nn];
__device__ float  g_psum[(size_t)BH * 8 * Nn];
__device__ double g_lse_part[LSE_PARTS];
__device__ double g_h2_part [(BNr / 128) * (HIDd / 128)];

__device__ bf16 g_x1 [(size_t)BNr * Dd],   g_x2 [(size_t)BNr * Dd];
__device__ bf16 g_wq1[(size_t)HQ * Dd];
__device__ bf16 g_wk1[(size_t)HQ * Dd];
__device__ bf16 g_wt [(size_t)Dd * 2048];                  // [d][ WqT | WkT ]
__device__ bf16 g_wh1[(size_t)Dd * HIDd],  g_wh2[(size_t)Dd * HIDd];
__device__ bf16 g_wht1[(size_t)HIDd * Dd], g_wht2[(size_t)HIDd * Dd];
__device__ bf16 g_hb1[(size_t)BNr * HIDd], g_hb2[(size_t)BNr * HIDd];
__device__ bf16 g_dm [(size_t)BNr * 2048];                 // [b*n][ dqm | dkm ]
__device__ bf16 g_q1[(size_t)BH * Nn * QKd];
__device__ bf16 g_k1[(size_t)BH * Nn * QKd];
__device__ bf16 g_qt[(size_t)BH * QKd * Nn], g_kt[(size_t)BH * QKd * Nn];

// ============================================================================
// Converters / transposes
// ============================================================================
__global__ void __launch_bounds__(256) split_plain4(
    const float* __restrict__ in, bf16* __restrict__ o1, bf16* __restrict__ o2)
{
    size_t i = ((size_t)blockIdx.x * 256 + threadIdx.x) * 4;
    float4 v = *(const float4*)(in + i);
    bf16 h[4], l[4];
    split2(v.x, h[0], l[0]); split2(v.y, h[1], l[1]);
    split2(v.z, h[2], l[2]); split2(v.w, h[3], l[3]);
    *(u64*)(o1 + i) = *(const u64*)h;
    *(u64*)(o2 + i) = *(const u64*)l;
}
__global__ void __launch_bounds__(256) cvt_plain4(
    const float* __restrict__ in, bf16* __restrict__ o1)
{
    size_t i = ((size_t)blockIdx.x * 256 + threadIdx.x) * 4;
    float4 v = *(const float4*)(in + i);
    bf16 h[4] = {__float2bfloat16(v.x), __float2bfloat16(v.y),
                 __float2bfloat16(v.z), __float2bfloat16(v.w)};
    *(u64*)(o1 + i) = *(const u64*)h;
}
__global__ void __launch_bounds__(256) trans_cvt1(
    const float* __restrict__ in, bf16* __restrict__ out, int R, int C, int OS)
{
    __shared__ float tile[32][33];
    const int c0 = blockIdx.x * 32, r0 = blockIdx.y * 32;
    const int tx = threadIdx.x & 31, ty = threadIdx.x >> 5;
    #pragma unroll
    for (int i = 0; i < 4; i++)
        tile[ty + i * 8][tx] = in[(size_t)(r0 + ty + i * 8) * C + c0 + tx];
    __syncthreads();
    #pragma unroll
    for (int i = 0; i < 4; i++)
        out[(size_t)(c0 + ty + i * 8) * OS + r0 + tx] = __float2bfloat16(tile[tx][ty + i * 8]);
}
__global__ void __launch_bounds__(256) trans_split(
    const float* __restrict__ in, bf16* __restrict__ o1, bf16* __restrict__ o2,
    int R, int C, int OS)
{
    __shared__ float tile[32][33];
    const int c0 = blockIdx.x * 32, r0 = blockIdx.y * 32;
    const int tx = threadIdx.x & 31, ty = threadIdx.x >> 5;
    #pragma unroll
    for (int i = 0; i < 4; i++)
        tile[ty + i * 8][tx] = in[(size_t)(r0 + ty + i * 8) * C + c0 + tx];
    __syncthreads();
    #pragma unroll
    for (int i = 0; i < 4; i++) {
        bf16 h, l; split2(tile[tx][ty + i * 8], h, l);
        size_t off = (size_t)(c0 + ty + i * 8) * OS + r0 + tx;
        o1[off] = h; o2[off] = l;
    }
}
__global__ void __launch_bounds__(256) trans_qk(
    const bf16* __restrict__ Q, const bf16* __restrict__ K,
    bf16* __restrict__ Qt, bf16* __restrict__ Kt)
{
    __shared__ bf16 tq[32][34], tk[32][34];
    const int n0 = blockIdx.x * 32, q0 = blockIdx.y * 32, bh = blockIdx.z;
    const bf16* Qb = Q + (size_t)bh * Nn * QKd;
    const bf16* Kb = K + (size_t)bh * Nn * QKd;
    const int tx = threadIdx.x & 31, ty = threadIdx.x >> 5;
    #pragma unroll
    for (int i = 0; i < 4; i++) {
        int n = ty + i * 8;
        tq[n][tx] = Qb[(size_t)(n0 + n) * QKd + q0 + tx];
        tk[n][tx] = Kb[(size_t)(n0 + n) * QKd + q0 + tx];
    }
    __syncthreads();
    #pragma unroll
    for (int i = 0; i < 4; i++) {
        int r = ty + i * 8;
        Qt[((size_t)bh * QKd + q0 + r) * Nn + n0 + tx] = tq[tx][r];
        Kt[((size_t)bh * QKd + q0 + r) * Nn + n0 + tx] = tk[tx][r];
    }
}

// ============================================================================
// HMMA GEMM, NS-sweep hi/lo split, 2-stage cp.async (72KB smem -> 2 CTAs/SM).
//   EPI=0: fp32 C (+)= alpha*D
//   EPI=1: bf16 scatter to [bh][n][qk] (O1)
//   EPI=2: relu; bf16-split to O1/O2; sum(v^2) partials
//   EPI=4: bf16 out O1 = bf16(alpha*D) + per-row (max, expsum) partials
// ============================================================================
#define TILE_B 36864
#define ROWSTR 144
#define TG_SMEM (2 * TILE_B)

template<int EPI, int NS>
__global__ void __launch_bounds__(256) tgemm(
    const bf16* __restrict__ A1, const bf16* __restrict__ A2,
    const bf16* __restrict__ B1, const bf16* __restrict__ B2,
    float* __restrict__ C, int Ncols, int Kglob, float alpha, int accFlag,
    bf16* __restrict__ O1, bf16* __restrict__ O2, double* __restrict__ part,
    float* __restrict__ pmax, float* __restrict__ psum,
    size_t zsA, size_t zsB, size_t zsC)
{
    extern __shared__ char dsm[];
    __shared__ double sred[256];
    __shared__ float smax[128][5], ssum[128][5];
    const uint32_t sbase = smem_u32(dsm);

    const size_t zA = (size_t)blockIdx.z * zsA;
    const size_t zB = (size_t)blockIdx.z * zsB;
    A1 += zA; B1 += zB;
    if (NS == 3) { A2 += zA; B2 += zB; }
    if (EPI == 1 || EPI == 4) O1 += (size_t)blockIdx.z * zsC;
    else                      C  += (size_t)blockIdx.z * zsC;

    const int t = threadIdx.x;
    const int wid = t >> 5, lane = t & 31;
    const int m0 = blockIdx.y * 128, n0 = blockIdx.x * 128;
    const int wm = wid >> 2, wn = wid & 3;

    const int KC = Kglob >> 6;
    const int TOT = NS * KC;

    float acc[4][4][4];
    #pragma unroll
    for (int i = 0; i < 4; i++)
        #pragma unroll
        for (int j = 0; j < 4; j++)
            #pragma unroll
            for (int r = 0; r < 4; r++) acc[i][j][r] = 0.f;

    const int lrow = t >> 3;
    const int lseg = (t & 7) * 8;

    auto issue_load = [&](int c) {
        const int p = (NS == 3) ? (c / KC) : 0;
        const int kb = c - p * KC;
        const bf16* Ap = (NS == 3 && p == 2) ? A2 : A1;
        const bf16* Bp = (NS == 3 && p == 1) ? B2 : B1;
        const uint32_t abase = sbase + (uint32_t)(c & 1) * TILE_B;
        const uint32_t bbase = abase + 18432;
        const size_t kEl = (size_t)(kb << 6) + lseg;
        #pragma unroll
        for (int i = 0; i < 4; i++) {
            const int row = lrow + i * 32;
            asm volatile("cp.async.cg.shared.global [%0], [%1], 16;"
                :: "r"(abase + row * ROWSTR + lseg * 2), "l"(Ap + (size_t)(m0 + row) * Kglob + kEl));
            asm volatile("cp.async.cg.shared.global [%0], [%1], 16;"
                :: "r"(bbase + row * ROWSTR + lseg * 2), "l"(Bp + (size_t)(n0 + row) * Kglob + kEl));
        }
        asm volatile("cp.async.commit_group;" ::: "memory");
    };

    issue_load(0);

    for (int c = 0; c < TOT; c++) {
        if (c + 1 < TOT) {
            issue_load(c + 1);
            asm volatile("cp.async.wait_group 1;" ::: "memory");
        } else {
            asm volatile("cp.async.wait_group 0;" ::: "memory");
        }
        __syncthreads();

        const uint32_t abase = sbase + (uint32_t)(c & 1) * TILE_B;
        const uint32_t bbase = abase + 18432;
        const int acol = ((lane >> 4) * 8) * 2;
        const int arow = (lane & 15);
        const int brow = (lane & 7) + ((lane >> 3) & 1) * 8;

        #pragma unroll
        for (int kk = 0; kk < 4; kk++) {
            const int kbyte = kk * 32 + acol;
            uint32_t a[4][4];
            #pragma unroll
            for (int mf = 0; mf < 4; mf++) {
                const uint32_t ad = abase + (wm * 64 + mf * 16 + arow) * ROWSTR + kbyte;
                asm volatile("ldmatrix.sync.aligned.m8n8.x4.shared.b16 {%0,%1,%2,%3}, [%4];"
                    : "=r"(a[mf][0]), "=r"(a[mf][1]), "=r"(a[mf][2]), "=r"(a[mf][3]) : "r"(ad));
            }
            uint32_t b[4][2];
            #pragma unroll
            for (int nfp = 0; nfp < 2; nfp++) {
                const uint32_t bd = bbase + (wn * 32 + nfp * 16 + brow) * ROWSTR + kbyte;
                uint32_t r0, r1, r2, r3;
                asm volatile("ldmatrix.sync.aligned.m8n8.x4.shared.b16 {%0,%1,%2,%3}, [%4];"
                    : "=r"(r0), "=r"(r1), "=r"(r2), "=r"(r3) : "r"(bd));
                b[nfp * 2 + 0][0] = r0; b[nfp * 2 + 0][1] = r2;
                b[nfp * 2 + 1][0] = r1; b[nfp * 2 + 1][1] = r3;
            }
            #pragma unroll
            for (int mf = 0; mf < 4; mf++)
                #pragma unroll
                for (int nf = 0; nf < 4; nf++)
                    asm volatile(
                        "mma.sync.aligned.m16n8k16.row.col.f32.bf16.bf16.f32 "
                        "{%0,%1,%2,%3}, {%4,%5,%6,%7}, {%8,%9}, {%0,%1,%2,%3};"
                        : "+f"(acc[mf][nf][0]), "+f"(acc[mf][nf][1]),
                          "+f"(acc[mf][nf][2]), "+f"(acc[mf][nf][3])
                        : "r"(a[mf][0]), "r"(a[mf][1]), "r"(a[mf][2]), "r"(a[mf][3]),
                          "r"(b[nf][0]), "r"(b[nf][1]));
        }
        __syncthreads();
    }

    const int gr = lane >> 2;
    const int gc = (lane & 3) * 2;
    float hs = 0.f;

    if (EPI == 4) {
        // store bf16(alpha*D) + per-row online-softmax partials
        float rmax[8];
        #pragma unroll
        for (int i = 0; i < 8; i++) rmax[i] = -CUDART_INF_F;
        #pragma unroll
        for (int mf = 0; mf < 4; mf++)
            #pragma unroll
            for (int nf = 0; nf < 4; nf++) {
                const int col = n0 + wn * 32 + nf * 8 + gc;
                #pragma unroll
                for (int half = 0; half < 2; half++) {
                    const int row = m0 + wm * 64 + mf * 16 + gr + half * 8;
                    bf16 ba = __float2bfloat16(acc[mf][nf][half * 2] * alpha);
                    bf16 bb = __float2bfloat16(acc[mf][nf][half * 2 + 1] * alpha);
                    bf16 pr[2] = {ba, bb};
                    *(uint32_t*)&O1[(size_t)row * Ncols + col] = *(const uint32_t*)pr;
                    float fa = __bfloat162float(ba), fb = __bfloat162float(bb);
                    acc[mf][nf][half * 2] = fa; acc[mf][nf][half * 2 + 1] = fb;
                    rmax[mf * 2 + half] = fmaxf(rmax[mf * 2 + half], fmaxf(fa, fb));
                }
            }
        float rsum[8];
        #pragma unroll
        for (int i = 0; i < 8; i++) rsum[i] = 0.f;
        #pragma unroll
        for (int mf = 0; mf < 4; mf++)
            #pragma unroll
            for (int nf = 0; nf < 4; nf++)
                #pragma unroll
                for (int half = 0; half < 2; half++)
                    rsum[mf * 2 + half] += __expf(acc[mf][nf][half * 2]     - rmax[mf * 2 + half])
                                         + __expf(acc[mf][nf][half * 2 + 1] - rmax[mf * 2 + half]);
        #pragma unroll
        for (int o = 1; o <= 2; o <<= 1)
            #pragma unroll
            for (int i = 0; i < 8; i++) {
                float m2 = __shfl_xor_sync(0xffffffffu, rmax[i], o);
                float s2 = __shfl_xor_sync(0xffffffffu, rsum[i], o);
                float nm = fmaxf(rmax[i], m2);
                rsum[i] = rsum[i] * __expf(rmax[i] - nm) + s2 * __expf(m2 - nm);
                rmax[i] = nm;
            }
        if ((lane & 3) == 0) {
            #pragma unroll
            for (int mf = 0; mf < 4; mf++)
                #pragma unroll
                for (int half = 0; half < 2; half++) {
                    int rl = wm * 64 + mf * 16 + gr + half * 8;
                    smax[rl][wn] = rmax[mf * 2 + half];
                    ssum[rl][wn] = rsum[mf * 2 + half];
                }
        }
        __syncthreads();
        if (t < 128) {
            float m = smax[t][0];
            #pragma unroll
            for (int w = 1; w < 4; w++) m = fmaxf(m, smax[t][w]);
            float s = 0.f;
            #pragma unroll
            for (int w = 0; w < 4; w++) s += ssum[t][w] * __expf(smax[t][w] - m);
            size_t pidx = ((size_t)blockIdx.z * gridDim.x + blockIdx.x) * (size_t)(gridDim.y * 128)
                        + m0 + t;
            pmax[pidx] = m; psum[pidx] = s;
        }
        return;
    }

    #pragma unroll
    for (int mf = 0; mf < 4; mf++) {
        #pragma unroll
        for (int nf = 0; nf < 4; nf++) {
            const int col = n0 + wn * 32 + nf * 8 + gc;
            #pragma unroll
            for (int half = 0; half < 2; half++) {
                const int row = m0 + wm * 64 + mf * 16 + gr + half * 8;
                const float va = acc[mf][nf][half * 2];
                const float vb = acc[mf][nf][half * 2 + 1];
                if (EPI == 1) {
                    const int h_ = col >> 6, q_ = col & 63;
                    const int b_ = row >> 10, n_ = row & 1023;
                    *(uint32_t*)&O1[(((size_t)(b_ * Hh + h_)) * Nn + n_) * QKd + q_] =
                        pack_bf2(va, vb);
                } else if (EPI == 2) {
                    const size_t off = (size_t)row * Ncols + col;
                    const float v0 = fmaxf(va, 0.f), v1 = fmaxf(vb, 0.f);
                    hs = fmaf(v0, v0, fmaf(v1, v1, hs));
                    bf16 h0, l0, h1, l1;
                    split2(v0, h0, l0); split2(v1, h1, l1);
                    bf16 hh[2] = {h0, h1}, ll[2] = {l0, l1};
                    *(uint32_t*)(O1 + off) = *(const uint32_t*)hh;
                    *(uint32_t*)(O2 + off) = *(const uint32_t*)ll;
                } else {
                    const size_t off = (size_t)row * Ncols + col;
                    float2 v = make_float2(va * alpha, vb * alpha);
                    if (accFlag) {
                        float2 o = *(const float2*)&C[off];
                        v.x += o.x; v.y += o.y;
                    }
                    *(float2*)&C[off] = v;
                }
            }
        }
    }
    if (EPI == 2) {
        sred[t] = (double)hs;
        __syncthreads();
        for (int o = 128; o > 0; o >>= 1) { if (t < o) sred[t] += sred[t + o]; __syncthreads(); }
        if (t == 0) part[blockIdx.y * gridDim.x + blockIdx.x] = sred[0];
    }
}

// ============================================================================
// lse combine: lse[n] = m_glob + log(sum exp(m_i - m_glob) * s_i); lse partials.
// ============================================================================
__global__ void __launch_bounds__(256) lse_combine(
    const float* __restrict__ pmax, const float* __restrict__ psum,
    float* __restrict__ lse, double* __restrict__ lse_part)
{
    __shared__ double sm[256];
    const int idx = blockIdx.x * 256 + threadIdx.x;   // bh*1024 + n
    const int bh = idx >> 10, n = idx & 1023;
    float ms[8], ss[8];
    float m = -CUDART_INF_F;
    #pragma unroll
    for (int i = 0; i < 8; i++) {
        ms[i] = pmax[((size_t)bh * 8 + i) * Nn + n];
        ss[i] = psum[((size_t)bh * 8 + i) * Nn + n];
        m = fmaxf(m, ms[i]);
    }
    float s = 0.f;
    #pragma unroll
    for (int i = 0; i < 8; i++) s += ss[i] * __expf(ms[i] - m);
    const float l = m + logf(s);
    lse[idx] = l;
    sm[threadIdx.x] = (double)l;
    __syncthreads();
    for (int o = 128; o > 0; o >>= 1) {
        if (threadIdx.x < o) sm[threadIdx.x] += sm[threadIdx.x + o];
        __syncthreads();
    }
    if (threadIdx.x == 0) lse_part[blockIdx.x] = sm[0];
}

// ============================================================================
// dQ-GEMM: dm[(b*N+n)][h*64+q] = bf16(-sum_m P[n][m] * Kt[q][m]),
// with P = exp(Sb - lse[n]) computed on the staged tile in smem.
// ============================================================================
#define DQ_STAGE 27648
__global__ void __launch_bounds__(256) att_dq_h(
    const bf16* __restrict__ S, const bf16* __restrict__ Kt,
    const float* __restrict__ lse, bf16* __restrict__ dm)
{
    extern __shared__ char dsm[];
    const uint32_t sbase = smem_u32(dsm);
    const int t = threadIdx.x, wid = t >> 5, lane = t & 31;
    const int bh = blockIdx.y, n0 = blockIdx.x * 128;
    const bf16* Ag = S + (size_t)bh * Nn * Nn;
    const bf16* Bg = Kt + (size_t)bh * QKd * Nn;

    float acc[8][4];
    #pragma unroll
    for (int i = 0; i < 8; i++)
        #pragma unroll
        for (int r = 0; r < 4; r++) acc[i][r] = 0.f;

    const int lrow = t >> 3, lseg = (t & 7) * 8;
    const int xr = t >> 1, xh = (t & 1) * 64;
    const float xlse = lse[bh * Nn + n0 + xr];

    auto load = [&](int kb) {
        const uint32_t ab = sbase + (uint32_t)(kb & 1) * DQ_STAGE;
        const uint32_t bb = ab + 18432;
        const size_t kEl = (size_t)(kb << 6) + lseg;
        #pragma unroll
        for (int i = 0; i < 4; i++) {
            const int row = lrow + i * 32;
            asm volatile("cp.async.cg.shared.global [%0], [%1], 16;"
                :: "r"(ab + row * ROWSTR + lseg * 2), "l"(Ag + (size_t)(n0 + row) * Nn + kEl));
        }
        #pragma unroll
        for (int i = 0; i < 2; i++) {
            const int row = lrow + i * 32;
            asm volatile("cp.async.cg.shared.global [%0], [%1], 16;"
                :: "r"(bb + row * ROWSTR + lseg * 2), "l"(Bg + (size_t)row * Nn + kEl));
        }
        asm volatile("cp.async.commit_group;" ::: "memory");
    };

    load(0);
    for (int kb = 0; kb < 16; kb++) {
        if (kb < 15) { load(kb + 1); asm volatile("cp.async.wait_group 1;" ::: "memory"); }
        else         { asm volatile("cp.async.wait_group 0;" ::: "memory"); }
        __syncthreads();
        {
            char* abuf = dsm + (size_t)(kb & 1) * DQ_STAGE + xr * ROWSTR + xh;
            #pragma unroll
            for (int j = 0; j < 4; j++) {
                uint4 w = *(uint4*)(abuf + j * 16);
                __nv_bfloat162* p2 = (__nv_bfloat162*)&w;
                #pragma unroll
                for (int q = 0; q < 4; q++) {
                    float2 f = __bfloat1622float2(p2[q]);
                    p2[q] = __floats2bfloat162_rn(__expf(f.x - xlse), __expf(f.y - xlse));
                }
                *(uint4*)(abuf + j * 16) = w;
            }
        }
        __syncthreads();
        const uint32_t ab = sbase + (uint32_t)(kb & 1) * DQ_STAGE;
        const uint32_t bb = ab + 18432;
        const int acol = ((lane >> 4) * 8) * 2;
        const int arow = lane & 15;
        const int brow = (lane & 7) + ((lane >> 3) & 1) * 8;
        #pragma unroll
        for (int kk = 0; kk < 4; kk++) {
            const int kbyte = kk * 32 + acol;
            uint32_t a[4];
            asm volatile("ldmatrix.sync.aligned.m8n8.x4.shared.b16 {%0,%1,%2,%3}, [%4];"
                : "=r"(a[0]), "=r"(a[1]), "=r"(a[2]), "=r"(a[3])
                : "r"(ab + (wid * 16 + arow) * ROWSTR + kbyte));
            uint32_t b[8][2];
            #pragma unroll
            for (int nfp = 0; nfp < 4; nfp++) {
                uint32_t r0, r1, r2, r3;
                asm volatile("ldmatrix.sync.aligned.m8n8.x4.shared.b16 {%0,%1,%2,%3}, [%4];"
                    : "=r"(r0), "=r"(r1), "=r"(r2), "=r"(r3)
                    : "r"(bb + (nfp * 16 + brow) * ROWSTR + kbyte));
                b[nfp * 2 + 0][0] = r0; b[nfp * 2 + 0][1] = r2;
                b[nfp * 2 + 1][0] = r1; b[nfp * 2 + 1][1] = r3;
            }
            #pragma unroll
            for (int nf = 0; nf < 8; nf++)
                asm volatile(
                    "mma.sync.aligned.m16n8k16.row.col.f32.bf16.bf16.f32 "
                    "{%0,%1,%2,%3}, {%4,%5,%6,%7}, {%8,%9}, {%0,%1,%2,%3};"
                    : "+f"(acc[nf][0]), "+f"(acc[nf][1]), "+f"(acc[nf][2]), "+f"(acc[nf][3])
                    : "r"(a[0]), "r"(a[1]), "r"(a[2]), "r"(a[3]),
                      "r"(b[nf][0]), "r"(b[nf][1]));
        }
        __syncthreads();
    }
    const int gr = lane >> 2, gc = (lane & 3) * 2;
    const int b_ = bh >> 4, h_ = bh & 15;
    #pragma unroll
    for (int nf = 0; nf < 8; nf++) {
        const int col = nf * 8 + gc;
        #pragma unroll
        for (int half = 0; half < 2; half++) {
            const int n = n0 + wid * 16 + gr + half * 8;
            *(uint32_t*)&dm[((size_t)(b_ * 1024 + n)) * 2048 + h_ * 64 + col] =
                pack_bf2(-acc[nf][half * 2], -acc[nf][half * 2 + 1]);
        }
    }
}

// ============================================================================
// dK-GEMM: dm[(b*N+m)][1024 + h*64+q] = bf16(-sum_n P[n][m] * Qt[q][n]),
// P = exp(Sb - lse[n]) computed on the staged (transposed-use) tile.
// ============================================================================
#define DK_ASTR 272
#define DK_STAGE 26624
__global__ void __launch_bounds__(256) att_dk_h(
    const bf16* __restrict__ S, const bf16* __restrict__ Qt,
    const float* __restrict__ lse, bf16* __restrict__ dm)
{
    extern __shared__ char dsm[];
    const uint32_t sbase = smem_u32(dsm);
    const int t = threadIdx.x, wid = t >> 5, lane = t & 31;
    const int bh = blockIdx.y, m0 = blockIdx.x * 128;
    const bf16* Ag = S + (size_t)bh * Nn * Nn;
    const bf16* Bg = Qt + (size_t)bh * QKd * Nn;

    float acc[8][4];
    #pragma unroll
    for (int i = 0; i < 8; i++)
        #pragma unroll
        for (int r = 0; r < 4; r++) acc[i][r] = 0.f;

    const int xr = t >> 2, xq = (t & 3) * 64;

    auto load = [&](int kb) {
        const uint32_t ab = sbase + (uint32_t)(kb & 1) * DK_STAGE;
        const uint32_t bb = ab + 17408;
        const int ar = t >> 4, aseg = (t & 15) * 8;
        #pragma unroll
        for (int i = 0; i < 4; i++) {
            const int row = ar + i * 16;
            asm volatile("cp.async.cg.shared.global [%0], [%1], 16;"
                :: "r"(ab + row * DK_ASTR + aseg * 2),
                   "l"(Ag + (size_t)((kb << 6) + row) * Nn + m0 + aseg));
        }
        const int br = t >> 3, bseg = (t & 7) * 8;
        #pragma unroll
        for (int i = 0; i < 2; i++) {
            const int row = br + i * 32;
            asm volatile("cp.async.cg.shared.global [%0], [%1], 16;"
                :: "r"(bb + row * ROWSTR + bseg * 2),
                   "l"(Bg + (size_t)row * Nn + (kb << 6) + bseg));
        }
        asm volatile("cp.async.commit_group;" ::: "memory");
    };

    load(0);
    for (int kb = 0; kb < 16; kb++) {
        if (kb < 15) { load(kb + 1); asm volatile("cp.async.wait_group 1;" ::: "memory"); }
        else         { asm volatile("cp.async.wait_group 0;" ::: "memory"); }
        __syncthreads();
        {
            const float xlse = lse[bh * Nn + (kb << 6) + xr];
            char* abuf = dsm + (size_t)(kb & 1) * DK_STAGE + xr * DK_ASTR + xq;
            #pragma unroll
            for (int j = 0; j < 4; j++) {
                uint4 w = *(uint4*)(abuf + j * 16);
                __nv_bfloat162* p2 = (__nv_bfloat162*)&w;
                #pragma unroll
                for (int q = 0; q < 4; q++) {
                    float2 f = __bfloat1622float2(p2[q]);
                    p2[q] = __floats2bfloat162_rn(__expf(f.x - xlse), __expf(f.y - xlse));
                }
                *(uint4*)(abuf + j * 16) = w;
            }
        }
        __syncthreads();
        const uint32_t ab = sbase + (uint32_t)(kb & 1) * DK_STAGE;
        const uint32_t bb = ab + 17408;
        const int tl = lane >> 3;
        const int brow = (lane & 7) + ((lane >> 3) & 1) * 8;
        const int bcol = ((lane >> 4) * 8) * 2;
        #pragma unroll
        for (int kk = 0; kk < 4; kk++) {
            uint32_t a[4];
            const uint32_t ad = ab + (kk * 16 + (tl >> 1) * 8 + (lane & 7)) * DK_ASTR
                              + (wid * 16 + (tl & 1) * 8) * 2;
            asm volatile("ldmatrix.sync.aligned.m8n8.x4.trans.shared.b16 {%0,%1,%2,%3}, [%4];"
                : "=r"(a[0]), "=r"(a[1]), "=r"(a[2]), "=r"(a[3]) : "r"(ad));
            uint32_t b[8][2];
            const int kbyte = kk * 32 + bcol;
            #pragma unroll
            for (int nfp = 0; nfp < 4; nfp++) {
                uint32_t r0, r1, r2, r3;
                asm volatile("ldmatrix.sync.aligned.m8n8.x4.shared.b16 {%0,%1,%2,%3}, [%4];"
                    : "=r"(r0), "=r"(r1), "=r"(r2), "=r"(r3)
                    : "r"(bb + (nfp * 16 + brow) * ROWSTR + kbyte));
                b[nfp * 2 + 0][0] = r0; b[nfp * 2 + 0][1] = r2;
                b[nfp * 2 + 1][0] = r1; b[nfp * 2 + 1][1] = r3;
            }
            #pragma unroll
            for (int nf = 0; nf < 8; nf++)
                asm volatile(
                    "mma.sync.aligned.m16n8k16.row.col.f32.bf16.bf16.f32 "
                    "{%0,%1,%2,%3}, {%4,%5,%6,%7}, {%8,%9}, {%0,%1,%2,%3};"
                    : "+f"(acc[nf][0]), "+f"(acc[nf][1]), "+f"(acc[nf][2]), "+f"(acc[nf][3])
                    : "r"(a[0]), "r"(a[1]), "r"(a[2]), "r"(a[3]),
                      "r"(b[nf][0]), "r"(b[nf][1]));
        }
        __syncthreads();
    }
    const int gr = lane >> 2, gc = (lane & 3) * 2;
    const int b_ = bh >> 4, h_ = bh & 15;
    #pragma unroll
    for (int nf = 0; nf < 8; nf++) {
        const int col = nf * 8 + gc;
        #pragma unroll
        for (int half = 0; half < 2; half++) {
            const int m = m0 + wid * 16 + gr + half * 8;
            *(uint32_t*)&dm[((size_t)(b_ * 1024 + m)) * 2048 + 1024 + h_ * 64 + col] =
                pack_bf2(-acc[nf][half * 2], -acc[nf][half * 2 + 1]);
        }
    }
}

// ============================================================================
// Final energy: E = -(1/BETA) * sum(lse) - 0.5 * sum(h^2). Deterministic.
// ============================================================================
__global__ void energy_final(const double* __restrict__ lse_part,
                             const double* __restrict__ h2_part,
                             float* __restrict__ out)
{
    __shared__ double sm[256];
    int t = threadIdx.x;
    double s = 0.0;
    for (int i = t; i < LSE_PARTS; i += 256) s += lse_part[i];
    double s2 = 0.0;
    for (int i = t; i < (BNr / 128) * (HIDd / 128); i += 256) s2 += h2_part[i];
    sm[t] = -8.0 * s - 0.5 * s2;
    __syncthreads();
    for (int o = 128; o > 0; o >>= 1) { if (t < o) sm[t] += sm[t + o]; __syncthreads(); }
    if (t == 0) out[(size_t)BNr * Dd] = (float)sm[0];
}

// ============================================================================
// Host launcher
// ============================================================================
extern "C" void kernel_launch(void* const* d_in, const int* in_sizes, int n_in,
                              void* d_out, int out_size)
{
    const float* x    = (const float*)d_in[0];
    const float* Wq   = (const float*)d_in[1];
    const float* Wk   = (const float*)d_in[2];
    const float* Whop = (const float*)d_in[3];
    float* out = (float*)d_out;

    bf16 *pSb;
    float *pLseV, *pPmax, *pPsum;
    double *pLse, *pH2;
    bf16 *px1, *px2, *pwq1, *pwk1, *pwt;
    bf16 *pwh1, *pwh2, *pwht1, *pwht2, *phb1, *phb2, *pdm;
    bf16 *pq1, *pk1, *pqt, *pkt;

    cudaGetSymbolAddress((void**)&pSb,  g_Sb);
    cudaGetSymbolAddress((void**)&pLseV,g_lse);
    cudaGetSymbolAddress((void**)&pPmax,g_pmax);
    cudaGetSymbolAddress((void**)&pPsum,g_psum);
    cudaGetSymbolAddress((void**)&pLse, g_lse_part);
    cudaGetSymbolAddress((void**)&pH2,  g_h2_part);
    cudaGetSymbolAddress((void**)&px1,  g_x1);  cudaGetSymbolAddress((void**)&px2,  g_x2);
    cudaGetSymbolAddress((void**)&pwq1, g_wq1);
    cudaGetSymbolAddress((void**)&pwk1, g_wk1);
    cudaGetSymbolAddress((void**)&pwt,  g_wt);
    cudaGetSymbolAddress((void**)&pwh1, g_wh1); cudaGetSymbolAddress((void**)&pwh2, g_wh2);
    cudaGetSymbolAddress((void**)&pwht1,g_wht1);cudaGetSymbolAddress((void**)&pwht2,g_wht2);
    cudaGetSymbolAddress((void**)&phb1, g_hb1); cudaGetSymbolAddress((void**)&phb2, g_hb2);
    cudaGetSymbolAddress((void**)&pdm,  g_dm);
    cudaGetSymbolAddress((void**)&pq1,  g_q1);
    cudaGetSymbolAddress((void**)&pk1,  g_k1);
    cudaGetSymbolAddress((void**)&pqt,  g_qt);  cudaGetSymbolAddress((void**)&pkt,  g_kt);

    cudaFuncSetAttribute(tgemm<0,1>, cudaFuncAttributeMaxDynamicSharedMemorySize, TG_SMEM);
    cudaFuncSetAttribute(tgemm<0,3>, cudaFuncAttributeMaxDynamicSharedMemorySize, TG_SMEM);
    cudaFuncSetAttribute(tgemm<1,1>, cudaFuncAttributeMaxDynamicSharedMemorySize, TG_SMEM);
    cudaFuncSetAttribute(tgemm<2,3>, cudaFuncAttributeMaxDynamicSharedMemorySize, TG_SMEM);
    cudaFuncSetAttribute(tgemm<4,1>, cudaFuncAttributeMaxDynamicSharedMemorySize, TG_SMEM);
    cudaFuncSetAttribute(att_dq_h, cudaFuncAttributeMaxDynamicSharedMemorySize, 2 * DQ_STAGE);
    cudaFuncSetAttribute(att_dk_h, cudaFuncAttributeMaxDynamicSharedMemorySize, 2 * DK_STAGE);

    dim3 blk(256);

    // 0. input conversions
    split_plain4<<<(BNr * Dd) / 1024, blk>>>(x, px1, px2);
    split_plain4<<<(Dd * HIDd) / 1024, blk>>>(Whop, pwh1, pwh2);
    cvt_plain4<<<(HQ * Dd) / 1024, blk>>>(Wq, pwq1);
    cvt_plain4<<<(HQ * Dd) / 1024, blk>>>(Wk, pwk1);
    trans_cvt1<<<dim3(Dd / 32, HQ / 32), blk>>>(Wq, pwt, HQ, Dd, 2048);
    trans_cvt1<<<dim3(Dd / 32, HQ / 32), blk>>>(Wk, pwt + 1024, HQ, Dd, 2048);
    trans_split<<<dim3(HIDd / 32, Dd / 32), blk>>>(Whop, pwht1, pwht2, Dd, HIDd, Dd);

    // 1-2. Q,K projections (1-sweep) -> bf16 q1/k1 scattered [bh][n][qk]
    tgemm<1,1><<<dim3(HQ / 128, BNr / 128, 1), blk, TG_SMEM>>>(
        px1, nullptr, pwq1, nullptr, nullptr, HQ, Dd, 1.f, 0, pq1, nullptr, nullptr,
        nullptr, nullptr, 0, 0, 0);
    tgemm<1,1><<<dim3(HQ / 128, BNr / 128, 1), blk, TG_SMEM>>>(
        px1, nullptr, pwk1, nullptr, nullptr, HQ, Dd, 1.f, 0, pk1, nullptr, nullptr,
        nullptr, nullptr, 0, 0, 0);

    // 3. transposes for dq/dk B-operands
    trans_qk<<<dim3(Nn / 32, QKd / 32, BH), blk>>>(pq1, pk1, pqt, pkt);

    // 4. S = BETA*QK^T -> bf16 Sb + per-block row softmax partials
    tgemm<4,1><<<dim3(Nn / 128, Nn / 128, BH), blk, TG_SMEM>>>(
        pq1, nullptr, pk1, nullptr, nullptr, Nn, QKd, BETA, 0, pSb, nullptr, nullptr,
        pPmax, pPsum, (size_t)Nn * QKd, (size_t)Nn * QKd, (size_t)Nn * Nn);

    // 5. lse combine (+ energy partials)
    lse_combine<<<LSE_PARTS, blk>>>(pPmax, pPsum, pLseV, pLse);

    // 6. dQm, dKm (exp on the fly) -> merged bf16 [b*n][2048]
    att_dq_h<<<dim3(Nn / 128, BH), blk, 2 * DQ_STAGE>>>(pSb, pkt, pLseV, pdm);
    att_dk_h<<<dim3(Nn / 128, BH), blk, 2 * DK_STAGE>>>(pSb, pqt, pLseV, pdm);

    // 7. grad = dm @ [WqT|WkT]  (one K=2048 GEMM)
    tgemm<0,1><<<dim3(Dd / 128, BNr / 128, 1), blk, TG_SMEM>>>(
        pdm, nullptr, pwt, nullptr, out, Dd, 2048, 1.f, 0, nullptr, nullptr, nullptr,
        nullptr, nullptr, 0, 0, 0);

    // 8. Hb = relu(X @ W_hop) (3-sweep); h2 partials
    tgemm<2,3><<<dim3(HIDd / 128, BNr / 128, 1), blk, TG_SMEM>>>(
        px1, px2, pwht1, pwht2, nullptr, HIDd, Dd, 1.f, 0, phb1, phb2, pH2,
        nullptr, nullptr, 0, 0, 0);

    // 9. grad -= Hb @ W_hop^T (3-sweep)
    tgemm<0,3><<<dim3(Dd / 128, BNr / 128, 1), blk, TG_SMEM>>>(
        phb1, phb2, pwh1, pwh2, out, Dd, HIDd, -1.f, 1, nullptr, nullptr, nullptr,
        nullptr, nullptr, 0, 0, 0);

    // 10. energy scalar
    if (out_size > BNr * Dd)
        energy_final<<<1, 256>>>(pLse, pH2, out);
}

// round 14
// speedup vs baseline: 1.2708x; 1.2540x over previous
#include <cuda_runtime.h>
#include <cuda_fp16.h>
#include <math_constants.h>
#include <cstdint>

#define Bsz 4
#define Nn 1024
#define Dd 1024
#define Hh 16
#define QKd 64
#define HIDd 4096
#define BH 64           // B*H
#define BNr 4096        // B*N
#define HQ 1024         // H*QK
#define BETA 0.125f
#define LSE_PARTS 256

typedef unsigned long long u64;
typedef __half f16;

__device__ __forceinline__ uint32_t smem_u32(const void* p) {
    uint32_t a;
    asm("{ .reg .u64 t; cvta.to.shared.u64 t, %1; cvt.u32.u64 %0, t; }" : "=r"(a) : "l"(p));
    return a;
}
__device__ __forceinline__ void split2(float v, f16& h, f16& l) {
    h = __float2half(v);
    l = __float2half(v - __half2float(h));
}
__device__ __forceinline__ uint32_t pack_h2(float a, float b) {
    f16 t[2] = {__float2half(a), __float2half(b)};
    return *(const uint32_t*)t;
}

// -------- device scratch --------
__device__ f16    g_Sb [(size_t)BH * Nn * Nn];    // beta*scores f16 (128MB)
__device__ float  g_lse [BH * Nn];
__device__ float  g_pmax[(size_t)BH * 8 * Nn];
__device__ float  g_psum[(size_t)BH * 8 * Nn];
__device__ double g_lse_part[LSE_PARTS];
__device__ double g_h2_part [(BNr / 128) * (HIDd / 128)];

__device__ f16 g_x1 [(size_t)BNr * Dd],   g_x2 [(size_t)BNr * Dd];
__device__ f16 g_wq1[(size_t)HQ * Dd];
__device__ f16 g_wk1[(size_t)HQ * Dd];
__device__ f16 g_wt [(size_t)Dd * 2048];                  // [d][ WqT | WkT ]
__device__ f16 g_wh1[(size_t)Dd * HIDd];                  // Whop hi, natural [D,HID]
__device__ f16 g_wht1[(size_t)HIDd * Dd];                 // Whop hi, transposed [HID,D]
__device__ f16 g_hb1[(size_t)BNr * HIDd], g_hb2[(size_t)BNr * HIDd];
__device__ f16 g_dm [(size_t)BNr * 2048];                 // [b*n][ dqm | dkm ]
__device__ f16 g_q1[(size_t)BH * Nn * QKd];
__device__ f16 g_k1[(size_t)BH * Nn * QKd];
__device__ f16 g_qt[(size_t)BH * QKd * Nn], g_kt[(size_t)BH * QKd * Nn];

// ============================================================================
// Converters / transposes
// ============================================================================
__global__ void __launch_bounds__(256) split_plain4(
    const float* __restrict__ in, f16* __restrict__ o1, f16* __restrict__ o2)
{
    size_t i = ((size_t)blockIdx.x * 256 + threadIdx.x) * 4;
    float4 v = *(const float4*)(in + i);
    f16 h[4], l[4];
    split2(v.x, h[0], l[0]); split2(v.y, h[1], l[1]);
    split2(v.z, h[2], l[2]); split2(v.w, h[3], l[3]);
    *(u64*)(o1 + i) = *(const u64*)h;
    *(u64*)(o2 + i) = *(const u64*)l;
}
__global__ void __launch_bounds__(256) cvt_plain4(
    const float* __restrict__ in, f16* __restrict__ o1)
{
    size_t i = ((size_t)blockIdx.x * 256 + threadIdx.x) * 4;
    float4 v = *(const float4*)(in + i);
    f16 h[4] = {__float2half(v.x), __float2half(v.y),
                __float2half(v.z), __float2half(v.w)};
    *(u64*)(o1 + i) = *(const u64*)h;
}
__global__ void __launch_bounds__(256) trans_cvt1(
    const float* __restrict__ in, f16* __restrict__ out, int R, int C, int OS)
{
    __shared__ float tile[32][33];
    const int c0 = blockIdx.x * 32, r0 = blockIdx.y * 32;
    const int tx = threadIdx.x & 31, ty = threadIdx.x >> 5;
    #pragma unroll
    for (int i = 0; i < 4; i++)
        tile[ty + i * 8][tx] = in[(size_t)(r0 + ty + i * 8) * C + c0 + tx];
    __syncthreads();
    #pragma unroll
    for (int i = 0; i < 4; i++)
        out[(size_t)(c0 + ty + i * 8) * OS + r0 + tx] = __float2half(tile[tx][ty + i * 8]);
}
__global__ void __launch_bounds__(256) trans_qk(
    const f16* __restrict__ Q, const f16* __restrict__ K,
    f16* __restrict__ Qt, f16* __restrict__ Kt)
{
    __shared__ f16 tq[32][34], tk[32][34];
    const int n0 = blockIdx.x * 32, q0 = blockIdx.y * 32, bh = blockIdx.z;
    const f16* Qb = Q + (size_t)bh * Nn * QKd;
    const f16* Kb = K + (size_t)bh * Nn * QKd;
    const int tx = threadIdx.x & 31, ty = threadIdx.x >> 5;
    #pragma unroll
    for (int i = 0; i < 4; i++) {
        int n = ty + i * 8;
        tq[n][tx] = Qb[(size_t)(n0 + n) * QKd + q0 + tx];
        tk[n][tx] = Kb[(size_t)(n0 + n) * QKd + q0 + tx];
    }
    __syncthreads();
    #pragma unroll
    for (int i = 0; i < 4; i++) {
        int r = ty + i * 8;
        Qt[((size_t)bh * QKd + q0 + r) * Nn + n0 + tx] = tq[tx][r];
        Kt[((size_t)bh * QKd + q0 + r) * Nn + n0 + tx] = tk[tx][r];
    }
}

// ============================================================================
// HMMA fp16 GEMM, NS-sweep split, 2-stage cp.async (72KB smem -> 2 CTAs/SM).
// Sweep plan:  NS=1: (A1,B1)   NS=2: (A1,B1),(A2,B1)
//   EPI=0: fp32 C (+)= alpha*D
//   EPI=1: f16 scatter to [bh][n][qk] (O1)
//   EPI=2: relu; f16-split to O1/O2; sum(v^2) partials
//   EPI=4: f16 out O1 = f16(alpha*D) + per-row (max, expsum) partials
// ============================================================================
#define TILE_B 36864
#define ROWSTR 144
#define TG_SMEM (2 * TILE_B)

template<int EPI, int NS>
__global__ void __launch_bounds__(256) tgemm(
    const f16* __restrict__ A1, const f16* __restrict__ A2,
    const f16* __restrict__ B1,
    float* __restrict__ C, int Ncols, int Kglob, float alpha, int accFlag,
    f16* __restrict__ O1, f16* __restrict__ O2, double* __restrict__ part,
    float* __restrict__ pmax, float* __restrict__ psum,
    size_t zsA, size_t zsB, size_t zsC)
{
    extern __shared__ char dsm[];
    __shared__ double sred[256];
    __shared__ float smax[128][5], ssum[128][5];
    const uint32_t sbase = smem_u32(dsm);

    const size_t zA = (size_t)blockIdx.z * zsA;
    A1 += zA; B1 += (size_t)blockIdx.z * zsB;
    if (NS == 2) A2 += zA;
    if (EPI == 1 || EPI == 4) O1 += (size_t)blockIdx.z * zsC;
    else                      C  += (size_t)blockIdx.z * zsC;

    const int t = threadIdx.x;
    const int wid = t >> 5, lane = t & 31;
    const int m0 = blockIdx.y * 128, n0 = blockIdx.x * 128;
    const int wm = wid >> 2, wn = wid & 3;

    const int KC = Kglob >> 6;
    const int TOT = NS * KC;

    float acc[4][4][4];
    #pragma unroll
    for (int i = 0; i < 4; i++)
        #pragma unroll
        for (int j = 0; j < 4; j++)
            #pragma unroll
            for (int r = 0; r < 4; r++) acc[i][j][r] = 0.f;

    const int lrow = t >> 3;
    const int lseg = (t & 7) * 8;

    auto issue_load = [&](int c) {
        const int p = (NS == 2) ? (c / KC) : 0;
        const int kb = c - p * KC;
        const f16* Ap = (NS == 2 && p == 1) ? A2 : A1;
        const uint32_t abase = sbase + (uint32_t)(c & 1) * TILE_B;
        const uint32_t bbase = abase + 18432;
        const size_t kEl = (size_t)(kb << 6) + lseg;
        #pragma unroll
        for (int i = 0; i < 4; i++) {
            const int row = lrow + i * 32;
            asm volatile("cp.async.cg.shared.global [%0], [%1], 16;"
                :: "r"(abase + row * ROWSTR + lseg * 2), "l"(Ap + (size_t)(m0 + row) * Kglob + kEl));
            asm volatile("cp.async.cg.shared.global [%0], [%1], 16;"
                :: "r"(bbase + row * ROWSTR + lseg * 2), "l"(B1 + (size_t)(n0 + row) * Kglob + kEl));
        }
        asm volatile("cp.async.commit_group;" ::: "memory");
    };

    issue_load(0);

    for (int c = 0; c < TOT; c++) {
        if (c + 1 < TOT) {
            issue_load(c + 1);
            asm volatile("cp.async.wait_group 1;" ::: "memory");
        } else {
            asm volatile("cp.async.wait_group 0;" ::: "memory");
        }
        __syncthreads();

        const uint32_t abase = sbase + (uint32_t)(c & 1) * TILE_B;
        const uint32_t bbase = abase + 18432;
        const int acol = ((lane >> 4) * 8) * 2;
        const int arow = (lane & 15);
        const int brow = (lane & 7) + ((lane >> 3) & 1) * 8;

        #pragma unroll
        for (int kk = 0; kk < 4; kk++) {
            const int kbyte = kk * 32 + acol;
            uint32_t a[4][4];
            #pragma unroll
            for (int mf = 0; mf < 4; mf++) {
                const uint32_t ad = abase + (wm * 64 + mf * 16 + arow) * ROWSTR + kbyte;
                asm volatile("ldmatrix.sync.aligned.m8n8.x4.shared.b16 {%0,%1,%2,%3}, [%4];"
                    : "=r"(a[mf][0]), "=r"(a[mf][1]), "=r"(a[mf][2]), "=r"(a[mf][3]) : "r"(ad));
            }
            uint32_t b[4][2];
            #pragma unroll
            for (int nfp = 0; nfp < 2; nfp++) {
                const uint32_t bd = bbase + (wn * 32 + nfp * 16 + brow) * ROWSTR + kbyte;
                uint32_t r0, r1, r2, r3;
                asm volatile("ldmatrix.sync.aligned.m8n8.x4.shared.b16 {%0,%1,%2,%3}, [%4];"
                    : "=r"(r0), "=r"(r1), "=r"(r2), "=r"(r3) : "r"(bd));
                b[nfp * 2 + 0][0] = r0; b[nfp * 2 + 0][1] = r2;
                b[nfp * 2 + 1][0] = r1; b[nfp * 2 + 1][1] = r3;
            }
            #pragma unroll
            for (int mf = 0; mf < 4; mf++)
                #pragma unroll
                for (int nf = 0; nf < 4; nf++)
                    asm volatile(
                        "mma.sync.aligned.m16n8k16.row.col.f32.f16.f16.f32 "
                        "{%0,%1,%2,%3}, {%4,%5,%6,%7}, {%8,%9}, {%0,%1,%2,%3};"
                        : "+f"(acc[mf][nf][0]), "+f"(acc[mf][nf][1]),
                          "+f"(acc[mf][nf][2]), "+f"(acc[mf][nf][3])
                        : "r"(a[mf][0]), "r"(a[mf][1]), "r"(a[mf][2]), "r"(a[mf][3]),
                          "r"(b[nf][0]), "r"(b[nf][1]));
        }
        __syncthreads();
    }

    const int gr = lane >> 2;
    const int gc = (lane & 3) * 2;
    float hs = 0.f;

    if (EPI == 4) {
        float rmax[8];
        #pragma unroll
        for (int i = 0; i < 8; i++) rmax[i] = -CUDART_INF_F;
        #pragma unroll
        for (int mf = 0; mf < 4; mf++)
            #pragma unroll
            for (int nf = 0; nf < 4; nf++) {
                const int col = n0 + wn * 32 + nf * 8 + gc;
                #pragma unroll
                for (int half = 0; half < 2; half++) {
                    const int row = m0 + wm * 64 + mf * 16 + gr + half * 8;
                    f16 ba = __float2half(acc[mf][nf][half * 2] * alpha);
                    f16 bb = __float2half(acc[mf][nf][half * 2 + 1] * alpha);
                    f16 pr[2] = {ba, bb};
                    *(uint32_t*)&O1[(size_t)row * Ncols + col] = *(const uint32_t*)pr;
                    float fa = __half2float(ba), fb = __half2float(bb);
                    acc[mf][nf][half * 2] = fa; acc[mf][nf][half * 2 + 1] = fb;
                    rmax[mf * 2 + half] = fmaxf(rmax[mf * 2 + half], fmaxf(fa, fb));
                }
            }
        float rsum[8];
        #pragma unroll
        for (int i = 0; i < 8; i++) rsum[i] = 0.f;
        #pragma unroll
        for (int mf = 0; mf < 4; mf++)
            #pragma unroll
            for (int nf = 0; nf < 4; nf++)
                #pragma unroll
                for (int half = 0; half < 2; half++)
                    rsum[mf * 2 + half] += __expf(acc[mf][nf][half * 2]     - rmax[mf * 2 + half])
                                         + __expf(acc[mf][nf][half * 2 + 1] - rmax[mf * 2 + half]);
        #pragma unroll
        for (int o = 1; o <= 2; o <<= 1)
            #pragma unroll
            for (int i = 0; i < 8; i++) {
                float m2 = __shfl_xor_sync(0xffffffffu, rmax[i], o);
                float s2 = __shfl_xor_sync(0xffffffffu, rsum[i], o);
                float nm = fmaxf(rmax[i], m2);
                rsum[i] = rsum[i] * __expf(rmax[i] - nm) + s2 * __expf(m2 - nm);
                rmax[i] = nm;
            }
        if ((lane & 3) == 0) {
            #pragma unroll
            for (int mf = 0; mf < 4; mf++)
                #pragma unroll
                for (int half = 0; half < 2; half++) {
                    int rl = wm * 64 + mf * 16 + gr + half * 8;
                    smax[rl][wn] = rmax[mf * 2 + half];
                    ssum[rl][wn] = rsum[mf * 2 + half];
                }
        }
        __syncthreads();
        if (t < 128) {
            float m = smax[t][0];
            #pragma unroll
            for (int w = 1; w < 4; w++) m = fmaxf(m, smax[t][w]);
            float s = 0.f;
            #pragma unroll
            for (int w = 0; w < 4; w++) s += ssum[t][w] * __expf(smax[t][w] - m);
            size_t pidx = ((size_t)blockIdx.z * gridDim.x + blockIdx.x) * (size_t)(gridDim.y * 128)
                        + m0 + t;
            pmax[pidx] = m; psum[pidx] = s;
        }
        return;
    }

    #pragma unroll
    for (int mf = 0; mf < 4; mf++) {
        #pragma unroll
        for (int nf = 0; nf < 4; nf++) {
            const int col = n0 + wn * 32 + nf * 8 + gc;
            #pragma unroll
            for (int half = 0; half < 2; half++) {
                const int row = m0 + wm * 64 + mf * 16 + gr + half * 8;
                const float va = acc[mf][nf][half * 2];
                const float vb = acc[mf][nf][half * 2 + 1];
                if (EPI == 1) {
                    const int h_ = col >> 6, q_ = col & 63;
                    const int b_ = row >> 10, n_ = row & 1023;
                    *(uint32_t*)&O1[(((size_t)(b_ * Hh + h_)) * Nn + n_) * QKd + q_] =
                        pack_h2(va, vb);
                } else if (EPI == 2) {
                    const size_t off = (size_t)row * Ncols + col;
                    const float v0 = fmaxf(va, 0.f), v1 = fmaxf(vb, 0.f);
                    hs = fmaf(v0, v0, fmaf(v1, v1, hs));
                    f16 h0, l0, h1, l1;
                    split2(v0, h0, l0); split2(v1, h1, l1);
                    f16 hh[2] = {h0, h1}, ll[2] = {l0, l1};
                    *(uint32_t*)(O1 + off) = *(const uint32_t*)hh;
                    *(uint32_t*)(O2 + off) = *(const uint32_t*)ll;
                } else {
                    const size_t off = (size_t)row * Ncols + col;
                    float2 v = make_float2(va * alpha, vb * alpha);
                    if (accFlag) {
                        float2 o = *(const float2*)&C[off];
                        v.x += o.x; v.y += o.y;
                    }
                    *(float2*)&C[off] = v;
                }
            }
        }
    }
    if (EPI == 2) {
        sred[t] = (double)hs;
        __syncthreads();
        for (int o = 128; o > 0; o >>= 1) { if (t < o) sred[t] += sred[t + o]; __syncthreads(); }
        if (t == 0) part[blockIdx.y * gridDim.x + blockIdx.x] = sred[0];
    }
}

// ============================================================================
// lse combine
// ============================================================================
__global__ void __launch_bounds__(256) lse_combine(
    const float* __restrict__ pmax, const float* __restrict__ psum,
    float* __restrict__ lse, double* __restrict__ lse_part)
{
    __shared__ double sm[256];
    const int idx = blockIdx.x * 256 + threadIdx.x;
    const int bh = idx >> 10, n = idx & 1023;
    float ms[8], ss[8];
    float m = -CUDART_INF_F;
    #pragma unroll
    for (int i = 0; i < 8; i++) {
        ms[i] = pmax[((size_t)bh * 8 + i) * Nn + n];
        ss[i] = psum[((size_t)bh * 8 + i) * Nn + n];
        m = fmaxf(m, ms[i]);
    }
    float s = 0.f;
    #pragma unroll
    for (int i = 0; i < 8; i++) s += ss[i] * __expf(ms[i] - m);
    const float l = m + logf(s);
    lse[idx] = l;
    sm[threadIdx.x] = (double)l;
    __syncthreads();
    for (int o = 128; o > 0; o >>= 1) {
        if (threadIdx.x < o) sm[threadIdx.x] += sm[threadIdx.x + o];
        __syncthreads();
    }
    if (threadIdx.x == 0) lse_part[blockIdx.x] = sm[0];
}

// ============================================================================
// dQ-GEMM: dm[(b*N+n)][h*64+q] = f16(-sum_m exp(S-lse[n]) * Kt[q][m])
// ============================================================================
#define DQ_STAGE 27648
__global__ void __launch_bounds__(256) att_dq_h(
    const f16* __restrict__ S, const f16* __restrict__ Kt,
    const float* __restrict__ lse, f16* __restrict__ dm)
{
    extern __shared__ char dsm[];
    const uint32_t sbase = smem_u32(dsm);
    const int t = threadIdx.x, wid = t >> 5, lane = t & 31;
    const int bh = blockIdx.y, n0 = blockIdx.x * 128;
    const f16* Ag = S + (size_t)bh * Nn * Nn;
    const f16* Bg = Kt + (size_t)bh * QKd * Nn;

    float acc[8][4];
    #pragma unroll
    for (int i = 0; i < 8; i++)
        #pragma unroll
        for (int r = 0; r < 4; r++) acc[i][r] = 0.f;

    const int lrow = t >> 3, lseg = (t & 7) * 8;
    const int xr = t >> 1, xh = (t & 1) * 64;
    const float xlse = lse[bh * Nn + n0 + xr];

    auto load = [&](int kb) {
        const uint32_t ab = sbase + (uint32_t)(kb & 1) * DQ_STAGE;
        const uint32_t bb = ab + 18432;
        const size_t kEl = (size_t)(kb << 6) + lseg;
        #pragma unroll
        for (int i = 0; i < 4; i++) {
            const int row = lrow + i * 32;
            asm volatile("cp.async.cg.shared.global [%0], [%1], 16;"
                :: "r"(ab + row * ROWSTR + lseg * 2), "l"(Ag + (size_t)(n0 + row) * Nn + kEl));
        }
        #pragma unroll
        for (int i = 0; i < 2; i++) {
            const int row = lrow + i * 32;
            asm volatile("cp.async.cg.shared.global [%0], [%1], 16;"
                :: "r"(bb + row * ROWSTR + lseg * 2), "l"(Bg + (size_t)row * Nn + kEl));
        }
        asm volatile("cp.async.commit_group;" ::: "memory");
    };

    load(0);
    for (int kb = 0; kb < 16; kb++) {
        if (kb < 15) { load(kb + 1); asm volatile("cp.async.wait_group 1;" ::: "memory"); }
        else         { asm volatile("cp.async.wait_group 0;" ::: "memory"); }
        __syncthreads();
        {
            char* abuf = dsm + (size_t)(kb & 1) * DQ_STAGE + xr * ROWSTR + xh;
            #pragma unroll
            for (int j = 0; j < 4; j++) {
                uint4 w = *(uint4*)(abuf + j * 16);
                __half2* p2 = (__half2*)&w;
                #pragma unroll
                for (int q = 0; q < 4; q++) {
                    float2 f = __half22float2(p2[q]);
                    p2[q] = __floats2half2_rn(__expf(f.x - xlse), __expf(f.y - xlse));
                }
                *(uint4*)(abuf + j * 16) = w;
            }
        }
        __syncthreads();
        const uint32_t ab = sbase + (uint32_t)(kb & 1) * DQ_STAGE;
        const uint32_t bb = ab + 18432;
        const int acol = ((lane >> 4) * 8) * 2;
        const int arow = lane & 15;
        const int brow = (lane & 7) + ((lane >> 3) & 1) * 8;
        #pragma unroll
        for (int kk = 0; kk < 4; kk++) {
            const int kbyte = kk * 32 + acol;
            uint32_t a[4];
            asm volatile("ldmatrix.sync.aligned.m8n8.x4.shared.b16 {%0,%1,%2,%3}, [%4];"
                : "=r"(a[0]), "=r"(a[1]), "=r"(a[2]), "=r"(a[3])
                : "r"(ab + (wid * 16 + arow) * ROWSTR + kbyte));
            uint32_t b[8][2];
            #pragma unroll
            for (int nfp = 0; nfp < 4; nfp++) {
                uint32_t r0, r1, r2, r3;
                asm volatile("ldmatrix.sync.aligned.m8n8.x4.shared.b16 {%0,%1,%2,%3}, [%4];"
                    : "=r"(r0), "=r"(r1), "=r"(r2), "=r"(r3)
                    : "r"(bb + (nfp * 16 + brow) * ROWSTR + kbyte));
                b[nfp * 2 + 0][0] = r0; b[nfp * 2 + 0][1] = r2;
                b[nfp * 2 + 1][0] = r1; b[nfp * 2 + 1][1] = r3;
            }
            #pragma unroll
            for (int nf = 0; nf < 8; nf++)
                asm volatile(
                    "mma.sync.aligned.m16n8k16.row.col.f32.f16.f16.f32 "
                    "{%0,%1,%2,%3}, {%4,%5,%6,%7}, {%8,%9}, {%0,%1,%2,%3};"
                    : "+f"(acc[nf][0]), "+f"(acc[nf][1]), "+f"(acc[nf][2]), "+f"(acc[nf][3])
                    : "r"(a[0]), "r"(a[1]), "r"(a[2]), "r"(a[3]),
                      "r"(b[nf][0]), "r"(b[nf][1]));
        }
        __syncthreads();
    }
    const int gr = lane >> 2, gc = (lane & 3) * 2;
    const int b_ = bh >> 4, h_ = bh & 15;
    #pragma unroll
    for (int nf = 0; nf < 8; nf++) {
        const int col = nf * 8 + gc;
        #pragma unroll
        for (int half = 0; half < 2; half++) {
            const int n = n0 + wid * 16 + gr + half * 8;
            *(uint32_t*)&dm[((size_t)(b_ * 1024 + n)) * 2048 + h_ * 64 + col] =
                pack_h2(-acc[nf][half * 2], -acc[nf][half * 2 + 1]);
        }
    }
}

// ============================================================================
// dK-GEMM: dm[(b*N+m)][1024 + h*64+q] = f16(-sum_n exp(S-lse[n]) * Qt[q][n])
// ============================================================================
#define DK_ASTR 272
#define DK_STAGE 26624
__global__ void __launch_bounds__(256) att_dk_h(
    const f16* __restrict__ S, const f16* __restrict__ Qt,
    const float* __restrict__ lse, f16* __restrict__ dm)
{
    extern __shared__ char dsm[];
    const uint32_t sbase = smem_u32(dsm);
    const int t = threadIdx.x, wid = t >> 5, lane = t & 31;
    const int bh = blockIdx.y, m0 = blockIdx.x * 128;
    const f16* Ag = S + (size_t)bh * Nn * Nn;
    const f16* Bg = Qt + (size_t)bh * QKd * Nn;

    float acc[8][4];
    #pragma unroll
    for (int i = 0; i < 8; i++)
        #pragma unroll
        for (int r = 0; r < 4; r++) acc[i][r] = 0.f;

    const int xr = t >> 2, xq = (t & 3) * 64;

    auto load = [&](int kb) {
        const uint32_t ab = sbase + (uint32_t)(kb & 1) * DK_STAGE;
        const uint32_t bb = ab + 17408;
        const int ar = t >> 4, aseg = (t & 15) * 8;
        #pragma unroll
        for (int i = 0; i < 4; i++) {
            const int row = ar + i * 16;
            asm volatile("cp.async.cg.shared.global [%0], [%1], 16;"
                :: "r"(ab + row * DK_ASTR + aseg * 2),
                   "l"(Ag + (size_t)((kb << 6) + row) * Nn + m0 + aseg));
        }
        const int br = t >> 3, bseg = (t & 7) * 8;
        #pragma unroll
        for (int i = 0; i < 2; i++) {
            const int row = br + i * 32;
            asm volatile("cp.async.cg.shared.global [%0], [%1], 16;"
                :: "r"(bb + row * ROWSTR + bseg * 2),
                   "l"(Bg + (size_t)row * Nn + (kb << 6) + bseg));
        }
        asm volatile("cp.async.commit_group;" ::: "memory");
    };

    load(0);
    for (int kb = 0; kb < 16; kb++) {
        if (kb < 15) { load(kb + 1); asm volatile("cp.async.wait_group 1;" ::: "memory"); }
        else         { asm volatile("cp.async.wait_group 0;" ::: "memory"); }
        __syncthreads();
        {
            const float xlse = lse[bh * Nn + (kb << 6) + xr];
            char* abuf = dsm + (size_t)(kb & 1) * DK_STAGE + xr * DK_ASTR + xq;
            #pragma unroll
            for (int j = 0; j < 4; j++) {
                uint4 w = *(uint4*)(abuf + j * 16);
                __half2* p2 = (__half2*)&w;
                #pragma unroll
                for (int q = 0; q < 4; q++) {
                    float2 f = __half22float2(p2[q]);
                    p2[q] = __floats2half2_rn(__expf(f.x - xlse), __expf(f.y - xlse));
                }
                *(uint4*)(abuf + j * 16) = w;
            }
        }
        __syncthreads();
        const uint32_t ab = sbase + (uint32_t)(kb & 1) * DK_STAGE;
        const uint32_t bb = ab + 17408;
        const int tl = lane >> 3;
        const int brow = (lane & 7) + ((lane >> 3) & 1) * 8;
        const int bcol = ((lane >> 4) * 8) * 2;
        #pragma unroll
        for (int kk = 0; kk < 4; kk++) {
            uint32_t a[4];
            const uint32_t ad = ab + (kk * 16 + (tl >> 1) * 8 + (lane & 7)) * DK_ASTR
                              + (wid * 16 + (tl & 1) * 8) * 2;
            asm volatile("ldmatrix.sync.aligned.m8n8.x4.trans.shared.b16 {%0,%1,%2,%3}, [%4];"
                : "=r"(a[0]), "=r"(a[1]), "=r"(a[2]), "=r"(a[3]) : "r"(ad));
            uint32_t b[8][2];
            const int kbyte = kk * 32 + bcol;
            #pragma unroll
            for (int nfp = 0; nfp < 4; nfp++) {
                uint32_t r0, r1, r2, r3;
                asm volatile("ldmatrix.sync.aligned.m8n8.x4.shared.b16 {%0,%1,%2,%3}, [%4];"
                    : "=r"(r0), "=r"(r1), "=r"(r2), "=r"(r3)
                    : "r"(bb + (nfp * 16 + brow) * ROWSTR + kbyte));
                b[nfp * 2 + 0][0] = r0; b[nfp * 2 + 0][1] = r2;
                b[nfp * 2 + 1][0] = r1; b[nfp * 2 + 1][1] = r3;
            }
            #pragma unroll
            for (int nf = 0; nf < 8; nf++)
                asm volatile(
                    "mma.sync.aligned.m16n8k16.row.col.f32.f16.f16.f32 "
                    "{%0,%1,%2,%3}, {%4,%5,%6,%7}, {%8,%9}, {%0,%1,%2,%3};"
                    : "+f"(acc[nf][0]), "+f"(acc[nf][1]), "+f"(acc[nf][2]), "+f"(acc[nf][3])
                    : "r"(a[0]), "r"(a[1]), "r"(a[2]), "r"(a[3]),
                      "r"(b[nf][0]), "r"(b[nf][1]));
        }
        __syncthreads();
    }
    const int gr = lane >> 2, gc = (lane & 3) * 2;
    const int b_ = bh >> 4, h_ = bh & 15;
    #pragma unroll
    for (int nf = 0; nf < 8; nf++) {
        const int col = nf * 8 + gc;
        #pragma unroll
        for (int half = 0; half < 2; half++) {
            const int m = m0 + wid * 16 + gr + half * 8;
            *(uint32_t*)&dm[((size_t)(b_ * 1024 + m)) * 2048 + 1024 + h_ * 64 + col] =
                pack_h2(-acc[nf][half * 2], -acc[nf][half * 2 + 1]);
        }
    }
}

// ============================================================================
// Final energy
// ============================================================================
__global__ void energy_final(const double* __restrict__ lse_part,
                             const double* __restrict__ h2_part,
                             float* __restrict__ out)
{
    __shared__ double sm[256];
    int t = threadIdx.x;
    double s = 0.0;
    for (int i = t; i < LSE_PARTS; i += 256) s += lse_part[i];
    double s2 = 0.0;
    for (int i = t; i < (BNr / 128) * (HIDd / 128); i += 256) s2 += h2_part[i];
    sm[t] = -8.0 * s - 0.5 * s2;
    __syncthreads();
    for (int o = 128; o > 0; o >>= 1) { if (t < o) sm[t] += sm[t + o]; __syncthreads(); }
    if (t == 0) out[(size_t)BNr * Dd] = (float)sm[0];
}

// ============================================================================
// Host launcher
// ============================================================================
extern "C" void kernel_launch(void* const* d_in, const int* in_sizes, int n_in,
                              void* d_out, int out_size)
{
    const float* x    = (const float*)d_in[0];
    const float* Wq   = (const float*)d_in[1];
    const float* Wk   = (const float*)d_in[2];
    const float* Whop = (const float*)d_in[3];
    float* out = (float*)d_out;

    f16 *pSb;
    float *pLseV, *pPmax, *pPsum;
    double *pLse, *pH2;
    f16 *px1, *px2, *pwq1, *pwk1, *pwt;
    f16 *pwh1, *pwht1, *phb1, *phb2, *pdm;
    f16 *pq1, *pk1, *pqt, *pkt;

    cudaGetSymbolAddress((void**)&pSb,  g_Sb);
    cudaGetSymbolAddress((void**)&pLseV,g_lse);
    cudaGetSymbolAddress((void**)&pPmax,g_pmax);
    cudaGetSymbolAddress((void**)&pPsum,g_psum);
    cudaGetSymbolAddress((void**)&pLse, g_lse_part);
    cudaGetSymbolAddress((void**)&pH2,  g_h2_part);
    cudaGetSymbolAddress((void**)&px1,  g_x1);  cudaGetSymbolAddress((void**)&px2,  g_x2);
    cudaGetSymbolAddress((void**)&pwq1, g_wq1);
    cudaGetSymbolAddress((void**)&pwk1, g_wk1);
    cudaGetSymbolAddress((void**)&pwt,  g_wt);
    cudaGetSymbolAddress((void**)&pwh1, g_wh1);
    cudaGetSymbolAddress((void**)&pwht1,g_wht1);
    cudaGetSymbolAddress((void**)&phb1, g_hb1); cudaGetSymbolAddress((void**)&phb2, g_hb2);
    cudaGetSymbolAddress((void**)&pdm,  g_dm);
    cudaGetSymbolAddress((void**)&pq1,  g_q1);
    cudaGetSymbolAddress((void**)&pk1,  g_k1);
    cudaGetSymbolAddress((void**)&pqt,  g_qt);  cudaGetSymbolAddress((void**)&pkt,  g_kt);

    cudaFuncSetAttribute(tgemm<0,1>, cudaFuncAttributeMaxDynamicSharedMemorySize, TG_SMEM);
    cudaFuncSetAttribute(tgemm<0,2>, cudaFuncAttributeMaxDynamicSharedMemorySize, TG_SMEM);
    cudaFuncSetAttribute(tgemm<1,1>, cudaFuncAttributeMaxDynamicSharedMemorySize, TG_SMEM);
    cudaFuncSetAttribute(tgemm<2,2>, cudaFuncAttributeMaxDynamicSharedMemorySize, TG_SMEM);
    cudaFuncSetAttribute(tgemm<4,1>, cudaFuncAttributeMaxDynamicSharedMemorySize, TG_SMEM);
    cudaFuncSetAttribute(att_dq_h, cudaFuncAttributeMaxDynamicSharedMemorySize, 2 * DQ_STAGE);
    cudaFuncSetAttribute(att_dk_h, cudaFuncAttributeMaxDynamicSharedMemorySize, 2 * DK_STAGE);

    dim3 blk(256);

    // 0. input conversions
    split_plain4<<<(BNr * Dd) / 1024, blk>>>(x, px1, px2);
    cvt_plain4<<<(Dd * HIDd) / 1024, blk>>>(Whop, pwh1);
    cvt_plain4<<<(HQ * Dd) / 1024, blk>>>(Wq, pwq1);
    cvt_plain4<<<(HQ * Dd) / 1024, blk>>>(Wk, pwk1);
    trans_cvt1<<<dim3(Dd / 32, HQ / 32), blk>>>(Wq, pwt, HQ, Dd, 2048);
    trans_cvt1<<<dim3(Dd / 32, HQ / 32), blk>>>(Wk, pwt + 1024, HQ, Dd, 2048);
    trans_cvt1<<<dim3(HIDd / 32, Dd / 32), blk>>>(Whop, pwht1, Dd, HIDd, Dd);

    // 1-2. Q,K projections (1-sweep) -> f16 q1/k1 scattered [bh][n][qk]
    tgemm<1,1><<<dim3(HQ / 128, BNr / 128, 1), blk, TG_SMEM>>>(
        px1, nullptr, pwq1, nullptr, HQ, Dd, 1.f, 0, pq1, nullptr, nullptr,
        nullptr, nullptr, 0, 0, 0);
    tgemm<1,1><<<dim3(HQ / 128, BNr / 128, 1), blk, TG_SMEM>>>(
        px1, nullptr, pwk1, nullptr, HQ, Dd, 1.f, 0, pk1, nullptr, nullptr,
        nullptr, nullptr, 0, 0, 0);

    // 3. transposes for dq/dk B-operands
    trans_qk<<<dim3(Nn / 32, QKd / 32, BH), blk>>>(pq1, pk1, pqt, pkt);

    // 4. S = BETA*QK^T -> f16 Sb + per-block row softmax partials
    tgemm<4,1><<<dim3(Nn / 128, Nn / 128, BH), blk, TG_SMEM>>>(
        pq1, nullptr, pk1, nullptr, Nn, QKd, BETA, 0, pSb, nullptr, nullptr,
        pPmax, pPsum, (size_t)Nn * QKd, (size_t)Nn * QKd, (size_t)Nn * Nn);

    // 5. lse combine (+ energy partials)
    lse_combine<<<LSE_PARTS, blk>>>(pPmax, pPsum, pLseV, pLse);

    // 6. dQm, dKm (exp on the fly) -> merged f16 [b*n][2048]
    att_dq_h<<<dim3(Nn / 128, BH), blk, 2 * DQ_STAGE>>>(pSb, pkt, pLseV, pdm);
    att_dk_h<<<dim3(Nn / 128, BH), blk, 2 * DK_STAGE>>>(pSb, pqt, pLseV, pdm);

    // 7. grad = dm @ [WqT|WkT]  (one K=2048 GEMM)
    tgemm<0,1><<<dim3(Dd / 128, BNr / 128, 1), blk, TG_SMEM>>>(
        pdm, nullptr, pwt, out, Dd, 2048, 1.f, 0, nullptr, nullptr, nullptr,
        nullptr, nullptr, 0, 0, 0);

    // 8. Hb = relu((x1+x2) @ WhopT_hi) (2-sweep); h2 partials; split Hb planes
    tgemm<2,2><<<dim3(HIDd / 128, BNr / 128, 1), blk, TG_SMEM>>>(
        px1, px2, pwht1, nullptr, HIDd, Dd, 1.f, 0, phb1, phb2, pH2,
        nullptr, nullptr, 0, 0, 0);

    // 9. grad -= (hb1+hb2) @ Whop_hi (2-sweep)
    tgemm<0,2><<<dim3(Dd / 128, BNr / 128, 1), blk, TG_SMEM>>>(
        phb1, phb2, pwh1, out, Dd, HIDd, -1.f, 1, nullptr, nullptr, nullptr,
        nullptr, nullptr, 0, 0, 0);

    // 10. energy scalar
    if (out_size > BNr * Dd)
        energy_final<<<1, 256>>>(pLse, pH2, out);
}

// round 15
// speedup vs baseline: 1.7507x; 1.3776x over previous
#include <cuda_runtime.h>
#include <cuda_fp16.h>
#include <math_constants.h>
#include <cstdint>

#define Bsz 4
#define Nn 1024
#define Dd 1024
#define Hh 16
#define QKd 64
#define HIDd 4096
#define BH 64           // B*H
#define BNr 4096        // B*N
#define HQ 1024         // H*QK
#define BETA 0.125f
#define LSE_PARTS 256

typedef unsigned long long u64;
typedef __half f16;

__device__ __forceinline__ uint32_t smem_u32(const void* p) {
    uint32_t a;
    asm("{ .reg .u64 t; cvta.to.shared.u64 t, %1; cvt.u32.u64 %0, t; }" : "=r"(a) : "l"(p));
    return a;
}
__device__ __forceinline__ uint32_t pack_h2(float a, float b) {
    f16 t[2] = {__float2half(a), __float2half(b)};
    return *(const uint32_t*)t;
}

// -------- device scratch --------
__device__ f16    g_Sb [(size_t)BH * Nn * Nn];    // beta*scores f16 (128MB)
__device__ float  g_lse [BH * Nn];
__device__ float  g_pmax[(size_t)BH * 8 * Nn];
__device__ float  g_psum[(size_t)BH * 8 * Nn];
__device__ double g_lse_part[LSE_PARTS];
__device__ double g_h2_part [(BNr / 128) * (HIDd / 128)];

__device__ f16 g_x1 [(size_t)BNr * Dd];
__device__ f16 g_wq1[(size_t)HQ * Dd];
__device__ f16 g_wk1[(size_t)HQ * Dd];
__device__ f16 g_wt [(size_t)Dd * 2048];                  // [d][ WqT | WkT ]
__device__ f16 g_wh1[(size_t)Dd * HIDd];                  // Whop hi, natural [D,HID]
__device__ f16 g_wht1[(size_t)HIDd * Dd];                 // Whop hi, transposed [HID,D]
__device__ f16 g_hb1[(size_t)BNr * HIDd];
__device__ f16 g_dm [(size_t)BNr * 2048];                 // [b*n][ dqm | dkm ]
__device__ f16 g_q1[(size_t)BH * Nn * QKd];
__device__ f16 g_k1[(size_t)BH * Nn * QKd];
__device__ f16 g_qt[(size_t)BH * QKd * Nn], g_kt[(size_t)BH * QKd * Nn];

// ============================================================================
// Converters / transposes
// ============================================================================
__global__ void __launch_bounds__(256) cvt_plain4(
    const float* __restrict__ in, f16* __restrict__ o1)
{
    size_t i = ((size_t)blockIdx.x * 256 + threadIdx.x) * 4;
    float4 v = *(const float4*)(in + i);
    f16 h[4] = {__float2half(v.x), __float2half(v.y),
                __float2half(v.z), __float2half(v.w)};
    *(u64*)(o1 + i) = *(const u64*)h;
}
__global__ void __launch_bounds__(256) trans_cvt1(
    const float* __restrict__ in, f16* __restrict__ out, int R, int C, int OS)
{
    __shared__ float tile[32][33];
    const int c0 = blockIdx.x * 32, r0 = blockIdx.y * 32;
    const int tx = threadIdx.x & 31, ty = threadIdx.x >> 5;
    #pragma unroll
    for (int i = 0; i < 4; i++)
        tile[ty + i * 8][tx] = in[(size_t)(r0 + ty + i * 8) * C + c0 + tx];
    __syncthreads();
    #pragma unroll
    for (int i = 0; i < 4; i++)
        out[(size_t)(c0 + ty + i * 8) * OS + r0 + tx] = __float2half(tile[tx][ty + i * 8]);
}
__global__ void __launch_bounds__(256) trans_qk(
    const f16* __restrict__ Q, const f16* __restrict__ K,
    f16* __restrict__ Qt, f16* __restrict__ Kt)
{
    __shared__ f16 tq[32][34], tk[32][34];
    const int n0 = blockIdx.x * 32, q0 = blockIdx.y * 32, bh = blockIdx.z;
    const f16* Qb = Q + (size_t)bh * Nn * QKd;
    const f16* Kb = K + (size_t)bh * Nn * QKd;
    const int tx = threadIdx.x & 31, ty = threadIdx.x >> 5;
    #pragma unroll
    for (int i = 0; i < 4; i++) {
        int n = ty + i * 8;
        tq[n][tx] = Qb[(size_t)(n0 + n) * QKd + q0 + tx];
        tk[n][tx] = Kb[(size_t)(n0 + n) * QKd + q0 + tx];
    }
    __syncthreads();
    #pragma unroll
    for (int i = 0; i < 4; i++) {
        int r = ty + i * 8;
        Qt[((size_t)bh * QKd + q0 + r) * Nn + n0 + tx] = tq[tx][r];
        Kt[((size_t)bh * QKd + q0 + r) * Nn + n0 + tx] = tk[tx][r];
    }
}

// ============================================================================
// HMMA fp16 GEMM, single-sweep, 2-stage cp.async (72KB smem -> 2 CTAs/SM).
//   EPI=0: fp32 C (+)= alpha*D
//   EPI=1: f16 scatter to [bh][n][qk] (O1)
//   EPI=2: relu; f16 to O1; sum(v^2) partials
//   EPI=4: f16 out O1 = f16(alpha*D) + per-row (max, expsum) partials
// ============================================================================
#define TILE_B 36864
#define ROWSTR 144
#define TG_SMEM (2 * TILE_B)

template<int EPI>
__global__ void __launch_bounds__(256) tgemm(
    const f16* __restrict__ A1, const f16* __restrict__ B1,
    float* __restrict__ C, int Ncols, int Kglob, float alpha, int accFlag,
    f16* __restrict__ O1, double* __restrict__ part,
    float* __restrict__ pmax, float* __restrict__ psum,
    size_t zsA, size_t zsB, size_t zsC)
{
    extern __shared__ char dsm[];
    __shared__ double sred[256];
    __shared__ float smax[128][5], ssum[128][5];
    const uint32_t sbase = smem_u32(dsm);

    A1 += (size_t)blockIdx.z * zsA;
    B1 += (size_t)blockIdx.z * zsB;
    if (EPI == 1 || EPI == 4) O1 += (size_t)blockIdx.z * zsC;
    else                      C  += (size_t)blockIdx.z * zsC;

    const int t = threadIdx.x;
    const int wid = t >> 5, lane = t & 31;
    const int m0 = blockIdx.y * 128, n0 = blockIdx.x * 128;
    const int wm = wid >> 2, wn = wid & 3;

    const int TOT = Kglob >> 6;

    float acc[4][4][4];
    #pragma unroll
    for (int i = 0; i < 4; i++)
        #pragma unroll
        for (int j = 0; j < 4; j++)
            #pragma unroll
            for (int r = 0; r < 4; r++) acc[i][j][r] = 0.f;

    const int lrow = t >> 3;
    const int lseg = (t & 7) * 8;

    auto issue_load = [&](int c) {
        const uint32_t abase = sbase + (uint32_t)(c & 1) * TILE_B;
        const uint32_t bbase = abase + 18432;
        const size_t kEl = (size_t)(c << 6) + lseg;
        #pragma unroll
        for (int i = 0; i < 4; i++) {
            const int row = lrow + i * 32;
            asm volatile("cp.async.cg.shared.global [%0], [%1], 16;"
                :: "r"(abase + row * ROWSTR + lseg * 2), "l"(A1 + (size_t)(m0 + row) * Kglob + kEl));
            asm volatile("cp.async.cg.shared.global [%0], [%1], 16;"
                :: "r"(bbase + row * ROWSTR + lseg * 2), "l"(B1 + (size_t)(n0 + row) * Kglob + kEl));
        }
        asm volatile("cp.async.commit_group;" ::: "memory");
    };

    issue_load(0);

    for (int c = 0; c < TOT; c++) {
        if (c + 1 < TOT) {
            issue_load(c + 1);
            asm volatile("cp.async.wait_group 1;" ::: "memory");
        } else {
            asm volatile("cp.async.wait_group 0;" ::: "memory");
        }
        __syncthreads();

        const uint32_t abase = sbase + (uint32_t)(c & 1) * TILE_B;
        const uint32_t bbase = abase + 18432;
        const int acol = ((lane >> 4) * 8) * 2;
        const int arow = (lane & 15);
        const int brow = (lane & 7) + ((lane >> 3) & 1) * 8;

        #pragma unroll
        for (int kk = 0; kk < 4; kk++) {
            const int kbyte = kk * 32 + acol;
            uint32_t a[4][4];
            #pragma unroll
            for (int mf = 0; mf < 4; mf++) {
                const uint32_t ad = abase + (wm * 64 + mf * 16 + arow) * ROWSTR + kbyte;
                asm volatile("ldmatrix.sync.aligned.m8n8.x4.shared.b16 {%0,%1,%2,%3}, [%4];"
                    : "=r"(a[mf][0]), "=r"(a[mf][1]), "=r"(a[mf][2]), "=r"(a[mf][3]) : "r"(ad));
            }
            uint32_t b[4][2];
            #pragma unroll
            for (int nfp = 0; nfp < 2; nfp++) {
                const uint32_t bd = bbase + (wn * 32 + nfp * 16 + brow) * ROWSTR + kbyte;
                uint32_t r0, r1, r2, r3;
                asm volatile("ldmatrix.sync.aligned.m8n8.x4.shared.b16 {%0,%1,%2,%3}, [%4];"
                    : "=r"(r0), "=r"(r1), "=r"(r2), "=r"(r3) : "r"(bd));
                b[nfp * 2 + 0][0] = r0; b[nfp * 2 + 0][1] = r2;
                b[nfp * 2 + 1][0] = r1; b[nfp * 2 + 1][1] = r3;
            }
            #pragma unroll
            for (int mf = 0; mf < 4; mf++)
                #pragma unroll
                for (int nf = 0; nf < 4; nf++)
                    asm volatile(
                        "mma.sync.aligned.m16n8k16.row.col.f32.f16.f16.f32 "
                        "{%0,%1,%2,%3}, {%4,%5,%6,%7}, {%8,%9}, {%0,%1,%2,%3};"
                        : "+f"(acc[mf][nf][0]), "+f"(acc[mf][nf][1]),
                          "+f"(acc[mf][nf][2]), "+f"(acc[mf][nf][3])
                        : "r"(a[mf][0]), "r"(a[mf][1]), "r"(a[mf][2]), "r"(a[mf][3]),
                          "r"(b[nf][0]), "r"(b[nf][1]));
        }
        __syncthreads();
    }

    const int gr = lane >> 2;
    const int gc = (lane & 3) * 2;
    float hs = 0.f;

    if (EPI == 4) {
        float rmax[8];
        #pragma unroll
        for (int i = 0; i < 8; i++) rmax[i] = -CUDART_INF_F;
        #pragma unroll
        for (int mf = 0; mf < 4; mf++)
            #pragma unroll
            for (int nf = 0; nf < 4; nf++) {
                const int col = n0 + wn * 32 + nf * 8 + gc;
                #pragma unroll
                for (int half = 0; half < 2; half++) {
                    const int row = m0 + wm * 64 + mf * 16 + gr + half * 8;
                    f16 ba = __float2half(acc[mf][nf][half * 2] * alpha);
                    f16 bb = __float2half(acc[mf][nf][half * 2 + 1] * alpha);
                    f16 pr[2] = {ba, bb};
                    *(uint32_t*)&O1[(size_t)row * Ncols + col] = *(const uint32_t*)pr;
                    float fa = __half2float(ba), fb = __half2float(bb);
                    acc[mf][nf][half * 2] = fa; acc[mf][nf][half * 2 + 1] = fb;
                    rmax[mf * 2 + half] = fmaxf(rmax[mf * 2 + half], fmaxf(fa, fb));
                }
            }
        float rsum[8];
        #pragma unroll
        for (int i = 0; i < 8; i++) rsum[i] = 0.f;
        #pragma unroll
        for (int mf = 0; mf < 4; mf++)
            #pragma unroll
            for (int nf = 0; nf < 4; nf++)
                #pragma unroll
                for (int half = 0; half < 2; half++)
                    rsum[mf * 2 + half] += __expf(acc[mf][nf][half * 2]     - rmax[mf * 2 + half])
                                         + __expf(acc[mf][nf][half * 2 + 1] - rmax[mf * 2 + half]);
        #pragma unroll
        for (int o = 1; o <= 2; o <<= 1)
            #pragma unroll
            for (int i = 0; i < 8; i++) {
                float m2 = __shfl_xor_sync(0xffffffffu, rmax[i], o);
                float s2 = __shfl_xor_sync(0xffffffffu, rsum[i], o);
                float nm = fmaxf(rmax[i], m2);
                rsum[i] = rsum[i] * __expf(rmax[i] - nm) + s2 * __expf(m2 - nm);
                rmax[i] = nm;
            }
        if ((lane & 3) == 0) {
            #pragma unroll
            for (int mf = 0; mf < 4; mf++)
                #pragma unroll
                for (int half = 0; half < 2; half++) {
                    int rl = wm * 64 + mf * 16 + gr + half * 8;
                    smax[rl][wn] = rmax[mf * 2 + half];
                    ssum[rl][wn] = rsum[mf * 2 + half];
                }
        }
        __syncthreads();
        if (t < 128) {
            float m = smax[t][0];
            #pragma unroll
            for (int w = 1; w < 4; w++) m = fmaxf(m, smax[t][w]);
            float s = 0.f;
            #pragma unroll
            for (int w = 0; w < 4; w++) s += ssum[t][w] * __expf(smax[t][w] - m);
            size_t pidx = ((size_t)blockIdx.z * gridDim.x + blockIdx.x) * (size_t)(gridDim.y * 128)
                        + m0 + t;
            pmax[pidx] = m; psum[pidx] = s;
        }
        return;
    }

    #pragma unroll
    for (int mf = 0; mf < 4; mf++) {
        #pragma unroll
        for (int nf = 0; nf < 4; nf++) {
            const int col = n0 + wn * 32 + nf * 8 + gc;
            #pragma unroll
            for (int half = 0; half < 2; half++) {
                const int row = m0 + wm * 64 + mf * 16 + gr + half * 8;
                const float va = acc[mf][nf][half * 2];
                const float vb = acc[mf][nf][half * 2 + 1];
                if (EPI == 1) {
                    const int h_ = col >> 6, q_ = col & 63;
                    const int b_ = row >> 10, n_ = row & 1023;
                    *(uint32_t*)&O1[(((size_t)(b_ * Hh + h_)) * Nn + n_) * QKd + q_] =
                        pack_h2(va, vb);
                } else if (EPI == 2) {
                    const size_t off = (size_t)row * Ncols + col;
                    const float v0 = fmaxf(va, 0.f), v1 = fmaxf(vb, 0.f);
                    hs = fmaf(v0, v0, fmaf(v1, v1, hs));
                    *(uint32_t*)(O1 + off) = pack_h2(v0, v1);
                } else {
                    const size_t off = (size_t)row * Ncols + col;
                    float2 v = make_float2(va * alpha, vb * alpha);
                    if (accFlag) {
                        float2 o = *(const float2*)&C[off];
                        v.x += o.x; v.y += o.y;
                    }
                    *(float2*)&C[off] = v;
                }
            }
        }
    }
    if (EPI == 2) {
        sred[t] = (double)hs;
        __syncthreads();
        for (int o = 128; o > 0; o >>= 1) { if (t < o) sred[t] += sred[t + o]; __syncthreads(); }
        if (t == 0) part[blockIdx.y * gridDim.x + blockIdx.x] = sred[0];
    }
}

// ============================================================================
// lse combine
// ============================================================================
__global__ void __launch_bounds__(256) lse_combine(
    const float* __restrict__ pmax, const float* __restrict__ psum,
    float* __restrict__ lse, double* __restrict__ lse_part)
{
    __shared__ double sm[256];
    const int idx = blockIdx.x * 256 + threadIdx.x;
    const int bh = idx >> 10, n = idx & 1023;
    float ms[8], ss[8];
    float m = -CUDART_INF_F;
    #pragma unroll
    for (int i = 0; i < 8; i++) {
        ms[i] = pmax[((size_t)bh * 8 + i) * Nn + n];
        ss[i] = psum[((size_t)bh * 8 + i) * Nn + n];
        m = fmaxf(m, ms[i]);
    }
    float s = 0.f;
    #pragma unroll
    for (int i = 0; i < 8; i++) s += ss[i] * __expf(ms[i] - m);
    const float l = m + logf(s);
    lse[idx] = l;
    sm[threadIdx.x] = (double)l;
    __syncthreads();
    for (int o = 128; o > 0; o >>= 1) {
        if (threadIdx.x < o) sm[threadIdx.x] += sm[threadIdx.x + o];
        __syncthreads();
    }
    if (threadIdx.x == 0) lse_part[blockIdx.x] = sm[0];
}

// ============================================================================
// dQ-GEMM: dm[(b*N+n)][h*64+q] = f16(-sum_m exp(S-lse[n]) * Kt[q][m])
// ============================================================================
#define DQ_STAGE 27648
__global__ void __launch_bounds__(256) att_dq_h(
    const f16* __restrict__ S, const f16* __restrict__ Kt,
    const float* __restrict__ lse, f16* __restrict__ dm)
{
    extern __shared__ char dsm[];
    const uint32_t sbase = smem_u32(dsm);
    const int t = threadIdx.x, wid = t >> 5, lane = t & 31;
    const int bh = blockIdx.y, n0 = blockIdx.x * 128;
    const f16* Ag = S + (size_t)bh * Nn * Nn;
    const f16* Bg = Kt + (size_t)bh * QKd * Nn;

    float acc[8][4];
    #pragma unroll
    for (int i = 0; i < 8; i++)
        #pragma unroll
        for (int r = 0; r < 4; r++) acc[i][r] = 0.f;

    const int lrow = t >> 3, lseg = (t & 7) * 8;
    const int xr = t >> 1, xh = (t & 1) * 64;
    const float xlse = lse[bh * Nn + n0 + xr];

    auto load = [&](int kb) {
        const uint32_t ab = sbase + (uint32_t)(kb & 1) * DQ_STAGE;
        const uint32_t bb = ab + 18432;
        const size_t kEl = (size_t)(kb << 6) + lseg;
        #pragma unroll
        for (int i = 0; i < 4; i++) {
            const int row = lrow + i * 32;
            asm volatile("cp.async.cg.shared.global [%0], [%1], 16;"
                :: "r"(ab + row * ROWSTR + lseg * 2), "l"(Ag + (size_t)(n0 + row) * Nn + kEl));
        }
        #pragma unroll
        for (int i = 0; i < 2; i++) {
            const int row = lrow + i * 32;
            asm volatile("cp.async.cg.shared.global [%0], [%1], 16;"
                :: "r"(bb + row * ROWSTR + lseg * 2), "l"(Bg + (size_t)row * Nn + kEl));
        }
        asm volatile("cp.async.commit_group;" ::: "memory");
    };

    load(0);
    for (int kb = 0; kb < 16; kb++) {
        if (kb < 15) { load(kb + 1); asm volatile("cp.async.wait_group 1;" ::: "memory"); }
        else         { asm volatile("cp.async.wait_group 0;" ::: "memory"); }
        __syncthreads();
        {
            char* abuf = dsm + (size_t)(kb & 1) * DQ_STAGE + xr * ROWSTR + xh;
            #pragma unroll
            for (int j = 0; j < 4; j++) {
                uint4 w = *(uint4*)(abuf + j * 16);
                __half2* p2 = (__half2*)&w;
                #pragma unroll
                for (int q = 0; q < 4; q++) {
                    float2 f = __half22float2(p2[q]);
                    p2[q] = __floats2half2_rn(__expf(f.x - xlse), __expf(f.y - xlse));
                }
                *(uint4*)(abuf + j * 16) = w;
            }
        }
        __syncthreads();
        const uint32_t ab = sbase + (uint32_t)(kb & 1) * DQ_STAGE;
        const uint32_t bb = ab + 18432;
        const int acol = ((lane >> 4) * 8) * 2;
        const int arow = lane & 15;
        const int brow = (lane & 7) + ((lane >> 3) & 1) * 8;
        #pragma unroll
        for (int kk = 0; kk < 4; kk++) {
            const int kbyte = kk * 32 + acol;
            uint32_t a[4];
            asm volatile("ldmatrix.sync.aligned.m8n8.x4.shared.b16 {%0,%1,%2,%3}, [%4];"
                : "=r"(a[0]), "=r"(a[1]), "=r"(a[2]), "=r"(a[3])
                : "r"(ab + (wid * 16 + arow) * ROWSTR + kbyte));
            uint32_t b[8][2];
            #pragma unroll
            for (int nfp = 0; nfp < 4; nfp++) {
                uint32_t r0, r1, r2, r3;
                asm volatile("ldmatrix.sync.aligned.m8n8.x4.shared.b16 {%0,%1,%2,%3}, [%4];"
                    : "=r"(r0), "=r"(r1), "=r"(r2), "=r"(r3)
                    : "r"(bb + (nfp * 16 + brow) * ROWSTR + kbyte));
                b[nfp * 2 + 0][0] = r0; b[nfp * 2 + 0][1] = r2;
                b[nfp * 2 + 1][0] = r1; b[nfp * 2 + 1][1] = r3;
            }
            #pragma unroll
            for (int nf = 0; nf < 8; nf++)
                asm volatile(
                    "mma.sync.aligned.m16n8k16.row.col.f32.f16.f16.f32 "
                    "{%0,%1,%2,%3}, {%4,%5,%6,%7}, {%8,%9}, {%0,%1,%2,%3};"
                    : "+f"(acc[nf][0]), "+f"(acc[nf][1]), "+f"(acc[nf][2]), "+f"(acc[nf][3])
                    : "r"(a[0]), "r"(a[1]), "r"(a[2]), "r"(a[3]),
                      "r"(b[nf][0]), "r"(b[nf][1]));
        }
        __syncthreads();
    }
    const int gr = lane >> 2, gc = (lane & 3) * 2;
    const int b_ = bh >> 4, h_ = bh & 15;
    #pragma unroll
    for (int nf = 0; nf < 8; nf++) {
        const int col = nf * 8 + gc;
        #pragma unroll
        for (int half = 0; half < 2; half++) {
            const int n = n0 + wid * 16 + gr + half * 8;
            *(uint32_t*)&dm[((size_t)(b_ * 1024 + n)) * 2048 + h_ * 64 + col] =
                pack_h2(-acc[nf][half * 2], -acc[nf][half * 2 + 1]);
        }
    }
}

// ============================================================================
// dK-GEMM: dm[(b*N+m)][1024 + h*64+q] = f16(-sum_n exp(S-lse[n]) * Qt[q][n])
// ============================================================================
#define DK_ASTR 272
#define DK_STAGE 26624
__global__ void __launch_bounds__(256) att_dk_h(
    const f16* __restrict__ S, const f16* __restrict__ Qt,
    const float* __restrict__ lse, f16* __restrict__ dm)
{
    extern __shared__ char dsm[];
    const uint32_t sbase = smem_u32(dsm);
    const int t = threadIdx.x, wid = t >> 5, lane = t & 31;
    const int bh = blockIdx.y, m0 = blockIdx.x * 128;
    const f16* Ag = S + (size_t)bh * Nn * Nn;
    const f16* Bg = Qt + (size_t)bh * QKd * Nn;

    float acc[8][4];
    #pragma unroll
    for (int i = 0; i < 8; i++)
        #pragma unroll
        for (int r = 0; r < 4; r++) acc[i][r] = 0.f;

    const int xr = t >> 2, xq = (t & 3) * 64;

    auto load = [&](int kb) {
        const uint32_t ab = sbase + (uint32_t)(kb & 1) * DK_STAGE;
        const uint32_t bb = ab + 17408;
        const int ar = t >> 4, aseg = (t & 15) * 8;
        #pragma unroll
        for (int i = 0; i < 4; i++) {
            const int row = ar + i * 16;
            asm volatile("cp.async.cg.shared.global [%0], [%1], 16;"
                :: "r"(ab + row * DK_ASTR + aseg * 2),
                   "l"(Ag + (size_t)((kb << 6) + row) * Nn + m0 + aseg));
        }
        const int br = t >> 3, bseg = (t & 7) * 8;
        #pragma unroll
        for (int i = 0; i < 2; i++) {
            const int row = br + i * 32;
            asm volatile("cp.async.cg.shared.global [%0], [%1], 16;"
                :: "r"(bb + row * ROWSTR + bseg * 2),
                   "l"(Bg + (size_t)row * Nn + (kb << 6) + bseg));
        }
        asm volatile("cp.async.commit_group;" ::: "memory");
    };

    load(0);
    for (int kb = 0; kb < 16; kb++) {
        if (kb < 15) { load(kb + 1); asm volatile("cp.async.wait_group 1;" ::: "memory"); }
        else         { asm volatile("cp.async.wait_group 0;" ::: "memory"); }
        __syncthreads();
        {
            const float xlse = lse[bh * Nn + (kb << 6) + xr];
            char* abuf = dsm + (size_t)(kb & 1) * DK_STAGE + xr * DK_ASTR + xq;
            #pragma unroll
            for (int j = 0; j < 4; j++) {
                uint4 w = *(uint4*)(abuf + j * 16);
                __half2* p2 = (__half2*)&w;
                #pragma unroll
                for (int q = 0; q < 4; q++) {
                    float2 f = __half22float2(p2[q]);
                    p2[q] = __floats2half2_rn(__expf(f.x - xlse), __expf(f.y - xlse));
                }
                *(uint4*)(abuf + j * 16) = w;
            }
        }
        __syncthreads();
        const uint32_t ab = sbase + (uint32_t)(kb & 1) * DK_STAGE;
        const uint32_t bb = ab + 17408;
        const int tl = lane >> 3;
        const int brow = (lane & 7) + ((lane >> 3) & 1) * 8;
        const int bcol = ((lane >> 4) * 8) * 2;
        #pragma unroll
        for (int kk = 0; kk < 4; kk++) {
            uint32_t a[4];
            const uint32_t ad = ab + (kk * 16 + (tl >> 1) * 8 + (lane & 7)) * DK_ASTR
                              + (wid * 16 + (tl & 1) * 8) * 2;
            asm volatile("ldmatrix.sync.aligned.m8n8.x4.trans.shared.b16 {%0,%1,%2,%3}, [%4];"
                : "=r"(a[0]), "=r"(a[1]), "=r"(a[2]), "=r"(a[3]) : "r"(ad));
            uint32_t b[8][2];
            const int kbyte = kk * 32 + bcol;
            #pragma unroll
            for (int nfp = 0; nfp < 4; nfp++) {
                uint32_t r0, r1, r2, r3;
                asm volatile("ldmatrix.sync.aligned.m8n8.x4.shared.b16 {%0,%1,%2,%3}, [%4];"
                    : "=r"(r0), "=r"(r1), "=r"(r2), "=r"(r3)
                    : "r"(bb + (nfp * 16 + brow) * ROWSTR + kbyte));
                b[nfp * 2 + 0][0] = r0; b[nfp * 2 + 0][1] = r2;
                b[nfp * 2 + 1][0] = r1; b[nfp * 2 + 1][1] = r3;
            }
            #pragma unroll
            for (int nf = 0; nf < 8; nf++)
                asm volatile(
                    "mma.sync.aligned.m16n8k16.row.col.f32.f16.f16.f32 "
                    "{%0,%1,%2,%3}, {%4,%5,%6,%7}, {%8,%9}, {%0,%1,%2,%3};"
                    : "+f"(acc[nf][0]), "+f"(acc[nf][1]), "+f"(acc[nf][2]), "+f"(acc[nf][3])
                    : "r"(a[0]), "r"(a[1]), "r"(a[2]), "r"(a[3]),
                      "r"(b[nf][0]), "r"(b[nf][1]));
        }
        __syncthreads();
    }
    const int gr = lane >> 2, gc = (lane & 3) * 2;
    const int b_ = bh >> 4, h_ = bh & 15;
    #pragma unroll
    for (int nf = 0; nf < 8; nf++) {
        const int col = nf * 8 + gc;
        #pragma unroll
        for (int half = 0; half < 2; half++) {
            const int m = m0 + wid * 16 + gr + half * 8;
            *(uint32_t*)&dm[((size_t)(b_ * 1024 + m)) * 2048 + 1024 + h_ * 64 + col] =
                pack_h2(-acc[nf][half * 2], -acc[nf][half * 2 + 1]);
        }
    }
}

// ============================================================================
// Final energy
// ============================================================================
__global__ void energy_final(const double* __restrict__ lse_part,
                             const double* __restrict__ h2_part,
                             float* __restrict__ out)
{
    __shared__ double sm[256];
    int t = threadIdx.x;
    double s = 0.0;
    for (int i = t; i < LSE_PARTS; i += 256) s += lse_part[i];
    double s2 = 0.0;
    for (int i = t; i < (BNr / 128) * (HIDd / 128); i += 256) s2 += h2_part[i];
    sm[t] = -8.0 * s - 0.5 * s2;
    __syncthreads();
    for (int o = 128; o > 0; o >>= 1) { if (t < o) sm[t] += sm[t + o]; __syncthreads(); }
    if (t == 0) out[(size_t)BNr * Dd] = (float)sm[0];
}

// ============================================================================
// Host launcher
// ============================================================================
extern "C" void kernel_launch(void* const* d_in, const int* in_sizes, int n_in,
                              void* d_out, int out_size)
{
    const float* x    = (const float*)d_in[0];
    const float* Wq   = (const float*)d_in[1];
    const float* Wk   = (const float*)d_in[2];
    const float* Whop = (const float*)d_in[3];
    float* out = (float*)d_out;

    f16 *pSb;
    float *pLseV, *pPmax, *pPsum;
    double *pLse, *pH2;
    f16 *px1, *pwq1, *pwk1, *pwt;
    f16 *pwh1, *pwht1, *phb1, *pdm;
    f16 *pq1, *pk1, *pqt, *pkt;

    cudaGetSymbolAddress((void**)&pSb,  g_Sb);
    cudaGetSymbolAddress((void**)&pLseV,g_lse);
    cudaGetSymbolAddress((void**)&pPmax,g_pmax);
    cudaGetSymbolAddress((void**)&pPsum,g_psum);
    cudaGetSymbolAddress((void**)&pLse, g_lse_part);
    cudaGetSymbolAddress((void**)&pH2,  g_h2_part);
    cudaGetSymbolAddress((void**)&px1,  g_x1);
    cudaGetSymbolAddress((void**)&pwq1, g_wq1);
    cudaGetSymbolAddress((void**)&pwk1, g_wk1);
    cudaGetSymbolAddress((void**)&pwt,  g_wt);
    cudaGetSymbolAddress((void**)&pwh1, g_wh1);
    cudaGetSymbolAddress((void**)&pwht1,g_wht1);
    cudaGetSymbolAddress((void**)&phb1, g_hb1);
    cudaGetSymbolAddress((void**)&pdm,  g_dm);
    cudaGetSymbolAddress((void**)&pq1,  g_q1);
    cudaGetSymbolAddress((void**)&pk1,  g_k1);
    cudaGetSymbolAddress((void**)&pqt,  g_qt);  cudaGetSymbolAddress((void**)&pkt,  g_kt);

    cudaFuncSetAttribute(tgemm<0>, cudaFuncAttributeMaxDynamicSharedMemorySize, TG_SMEM);
    cudaFuncSetAttribute(tgemm<1>, cudaFuncAttributeMaxDynamicSharedMemorySize, TG_SMEM);
    cudaFuncSetAttribute(tgemm<2>, cudaFuncAttributeMaxDynamicSharedMemorySize, TG_SMEM);
    cudaFuncSetAttribute(tgemm<4>, cudaFuncAttributeMaxDynamicSharedMemorySize, TG_SMEM);
    cudaFuncSetAttribute(att_dq_h, cudaFuncAttributeMaxDynamicSharedMemorySize, 2 * DQ_STAGE);
    cudaFuncSetAttribute(att_dk_h, cudaFuncAttributeMaxDynamicSharedMemorySize, 2 * DK_STAGE);

    dim3 blk(256);

    // 0. input conversions (all f16 single-plane)
    cvt_plain4<<<(BNr * Dd) / 1024, blk>>>(x, px1);
    cvt_plain4<<<(Dd * HIDd) / 1024, blk>>>(Whop, pwh1);
    cvt_plain4<<<(HQ * Dd) / 1024, blk>>>(Wq, pwq1);
    cvt_plain4<<<(HQ * Dd) / 1024, blk>>>(Wk, pwk1);
    trans_cvt1<<<dim3(Dd / 32, HQ / 32), blk>>>(Wq, pwt, HQ, Dd, 2048);
    trans_cvt1<<<dim3(Dd / 32, HQ / 32), blk>>>(Wk, pwt + 1024, HQ, Dd, 2048);
    trans_cvt1<<<dim3(HIDd / 32, Dd / 32), blk>>>(Whop, pwht1, Dd, HIDd, Dd);

    // 1-2. Q,K projections -> f16 q1/k1 scattered [bh][n][qk]
    tgemm<1><<<dim3(HQ / 128, BNr / 128, 1), blk, TG_SMEM>>>(
        px1, pwq1, nullptr, HQ, Dd, 1.f, 0, pq1, nullptr, nullptr, nullptr, 0, 0, 0);
    tgemm<1><<<dim3(HQ / 128, BNr / 128, 1), blk, TG_SMEM>>>(
        px1, pwk1, nullptr, HQ, Dd, 1.f, 0, pk1, nullptr, nullptr, nullptr, 0, 0, 0);

    // 3. transposes for dq/dk B-operands
    trans_qk<<<dim3(Nn / 32, QKd / 32, BH), blk>>>(pq1, pk1, pqt, pkt);

    // 4. S = BETA*QK^T -> f16 Sb + per-block row softmax partials
    tgemm<4><<<dim3(Nn / 128, Nn / 128, BH), blk, TG_SMEM>>>(
        pq1, pk1, nullptr, Nn, QKd, BETA, 0, pSb, nullptr,
        pPmax, pPsum, (size_t)Nn * QKd, (size_t)Nn * QKd, (size_t)Nn * Nn);

    // 5. lse combine (+ energy partials)
    lse_combine<<<LSE_PARTS, blk>>>(pPmax, pPsum, pLseV, pLse);

    // 6. dQm, dKm (exp on the fly) -> merged f16 [b*n][2048]
    att_dq_h<<<dim3(Nn / 128, BH), blk, 2 * DQ_STAGE>>>(pSb, pkt, pLseV, pdm);
    att_dk_h<<<dim3(Nn / 128, BH), blk, 2 * DK_STAGE>>>(pSb, pqt, pLseV, pdm);

    // 7. grad = dm @ [WqT|WkT]  (one K=2048 GEMM)
    tgemm<0><<<dim3(Dd / 128, BNr / 128, 1), blk, TG_SMEM>>>(
        pdm, pwt, out, Dd, 2048, 1.f, 0, nullptr, nullptr,
        nullptr, nullptr, 0, 0, 0);

    // 8. Hb = relu(x1 @ WhopT_hi) (1-sweep); h2 partials; f16 Hb
    tgemm<2><<<dim3(HIDd / 128, BNr / 128, 1), blk, TG_SMEM>>>(
        px1, pwht1, nullptr, HIDd, Dd, 1.f, 0, phb1, pH2,
        nullptr, nullptr, 0, 0, 0);

    // 9. grad -= hb1 @ Whop_hi (1-sweep)
    tgemm<0><<<dim3(Dd / 128, BNr / 128, 1), blk, TG_SMEM>>>(
        phb1, pwh1, out, Dd, HIDd, -1.f, 1, nullptr, nullptr,
        nullptr, nullptr, 0, 0, 0);

    // 10. energy scalar
    if (out_size > BNr * Dd)
        energy_final<<<1, 256>>>(pLse, pH2, out);
}

// round 16
// speedup vs baseline: 1.7854x; 1.0198x over previous
#include <cuda_runtime.h>
#include <cuda_fp16.h>
#include <math_constants.h>
#include <cstdint>

#define Bsz 4
#define Nn 1024
#define Dd 1024
#define Hh 16
#define QKd 64
#define HIDd 4096
#define BH 64           // B*H
#define BNr 4096        // B*N
#define HQ 1024         // H*QK
#define BETA 0.125f
#define LSE_PARTS 256
#define KOFF ((size_t)BH * Nn * QKd)   // q/k half offset in g_qk
#define BIGK 6144

typedef unsigned long long u64;
typedef __half f16;

__device__ __forceinline__ uint32_t smem_u32(const void* p) {
    uint32_t a;
    asm("{ .reg .u64 t; cvta.to.shared.u64 t, %1; cvt.u32.u64 %0, t; }" : "=r"(a) : "l"(p));
    return a;
}
__device__ __forceinline__ uint32_t pack_h2(float a, float b) {
    f16 t[2] = {__float2half(a), __float2half(b)};
    return *(const uint32_t*)t;
}

// -------- device scratch --------
__device__ f16    g_Sb [(size_t)BH * Nn * Nn];    // beta*scores f16 (128MB)
__device__ float  g_lse [BH * Nn];
__device__ float  g_pmax[(size_t)BH * 8 * Nn];
__device__ float  g_psum[(size_t)BH * 8 * Nn];
__device__ double g_lse_part[LSE_PARTS];
__device__ double g_h2_part [(BNr / 128) * (HIDd / 128)];

__device__ f16 g_x1 [(size_t)BNr * Dd];
__device__ f16 g_wqk[(size_t)2 * HQ * Dd];        // [ Wq1 ; Wk1 ] stacked rows
__device__ f16 g_wtb[(size_t)Dd * BIGK];          // [d][ WqT | WkT | Whop ]
__device__ f16 g_wht1[(size_t)HIDd * Dd];         // Whop transposed [HID,D]
__device__ f16 g_dm2[(size_t)BNr * BIGK];         // [b*n][ dqm | dkm | -relu(h) ]
__device__ f16 g_qk [2 * KOFF];                   // q1 | k1, each [bh][n][qk]
__device__ f16 g_qt[(size_t)BH * QKd * Nn], g_kt[(size_t)BH * QKd * Nn];

// ============================================================================
// Converters / transposes
// ============================================================================
__global__ void __launch_bounds__(256) cvt_plain4(
    const float* __restrict__ in, f16* __restrict__ o1)
{
    size_t i = ((size_t)blockIdx.x * 256 + threadIdx.x) * 4;
    float4 v = *(const float4*)(in + i);
    f16 h[4] = {__float2half(v.x), __float2half(v.y),
                __float2half(v.z), __float2half(v.w)};
    *(u64*)(o1 + i) = *(const u64*)h;
}
// Fused: read fp32 W[R][C] once; write natural f16 (stride ns) + transposed (stride ts)
__global__ void __launch_bounds__(256) cvt_trans(
    const float* __restrict__ in, int C,
    f16* __restrict__ nat, int ns, f16* __restrict__ tr, int ts)
{
    __shared__ float tile[32][33];
    const int c0 = blockIdx.x * 32, r0 = blockIdx.y * 32;
    const int tx = threadIdx.x & 31, ty = threadIdx.x >> 5;
    #pragma unroll
    for (int i = 0; i < 4; i++) {
        int r = r0 + ty + i * 8;
        float v = in[(size_t)r * C + c0 + tx];
        tile[ty + i * 8][tx] = v;
        nat[(size_t)r * ns + c0 + tx] = __float2half(v);
    }
    __syncthreads();
    #pragma unroll
    for (int i = 0; i < 4; i++)
        tr[(size_t)(c0 + ty + i * 8) * ts + r0 + tx] = __float2half(tile[tx][ty + i * 8]);
}
__global__ void __launch_bounds__(256) trans_qk(
    const f16* __restrict__ Q, const f16* __restrict__ K,
    f16* __restrict__ Qt, f16* __restrict__ Kt)
{
    __shared__ f16 tq[32][34], tk[32][34];
    const int n0 = blockIdx.x * 32, q0 = blockIdx.y * 32, bh = blockIdx.z;
    const f16* Qb = Q + (size_t)bh * Nn * QKd;
    const f16* Kb = K + (size_t)bh * Nn * QKd;
    const int tx = threadIdx.x & 31, ty = threadIdx.x >> 5;
    #pragma unroll
    for (int i = 0; i < 4; i++) {
        int n = ty + i * 8;
        tq[n][tx] = Qb[(size_t)(n0 + n) * QKd + q0 + tx];
        tk[n][tx] = Kb[(size_t)(n0 + n) * QKd + q0 + tx];
    }
    __syncthreads();
    #pragma unroll
    for (int i = 0; i < 4; i++) {
        int r = ty + i * 8;
        Qt[((size_t)bh * QKd + q0 + r) * Nn + n0 + tx] = tq[tx][r];
        Kt[((size_t)bh * QKd + q0 + r) * Nn + n0 + tx] = tk[tx][r];
    }
}

// ============================================================================
// HMMA fp16 GEMM, single-sweep, 2-stage cp.async (72KB smem -> 2 CTAs/SM).
//   EPI=0: fp32 C = alpha*D (direct write)
//   EPI=1: f16 scatter to q/k buffers (merged projection; col>=1024 -> K half)
//   EPI=2: -relu; f16 to O1 (stride Ncols); sum(v^2) partials
//   EPI=4: f16 out O1 = f16(alpha*D) + per-row (max, expsum) partials
// ============================================================================
#define TILE_B 36864
#define ROWSTR 144
#define TG_SMEM (2 * TILE_B)

template<int EPI>
__global__ void __launch_bounds__(256) tgemm(
    const f16* __restrict__ A1, const f16* __restrict__ B1,
    float* __restrict__ C, int Ncols, int Kglob, float alpha,
    f16* __restrict__ O1, double* __restrict__ part,
    float* __restrict__ pmax, float* __restrict__ psum,
    size_t zsA, size_t zsB, size_t zsC)
{
    extern __shared__ char dsm[];
    __shared__ double sred[256];
    __shared__ float smax[128][5], ssum[128][5];
    const uint32_t sbase = smem_u32(dsm);

    A1 += (size_t)blockIdx.z * zsA;
    B1 += (size_t)blockIdx.z * zsB;
    if (EPI == 1 || EPI == 4) O1 += (size_t)blockIdx.z * zsC;
    else                      C  += (size_t)blockIdx.z * zsC;

    const int t = threadIdx.x;
    const int wid = t >> 5, lane = t & 31;
    const int m0 = blockIdx.y * 128, n0 = blockIdx.x * 128;
    const int wm = wid >> 2, wn = wid & 3;

    const int TOT = Kglob >> 6;

    float acc[4][4][4];
    #pragma unroll
    for (int i = 0; i < 4; i++)
        #pragma unroll
        for (int j = 0; j < 4; j++)
            #pragma unroll
            for (int r = 0; r < 4; r++) acc[i][j][r] = 0.f;

    const int lrow = t >> 3;
    const int lseg = (t & 7) * 8;

    auto issue_load = [&](int c) {
        const uint32_t abase = sbase + (uint32_t)(c & 1) * TILE_B;
        const uint32_t bbase = abase + 18432;
        const size_t kEl = (size_t)(c << 6) + lseg;
        #pragma unroll
        for (int i = 0; i < 4; i++) {
            const int row = lrow + i * 32;
            asm volatile("cp.async.cg.shared.global [%0], [%1], 16;"
                :: "r"(abase + row * ROWSTR + lseg * 2), "l"(A1 + (size_t)(m0 + row) * Kglob + kEl));
            asm volatile("cp.async.cg.shared.global [%0], [%1], 16;"
                :: "r"(bbase + row * ROWSTR + lseg * 2), "l"(B1 + (size_t)(n0 + row) * Kglob + kEl));
        }
        asm volatile("cp.async.commit_group;" ::: "memory");
    };

    issue_load(0);

    for (int c = 0; c < TOT; c++) {
        if (c + 1 < TOT) {
            issue_load(c + 1);
            asm volatile("cp.async.wait_group 1;" ::: "memory");
        } else {
            asm volatile("cp.async.wait_group 0;" ::: "memory");
        }
        __syncthreads();

        const uint32_t abase = sbase + (uint32_t)(c & 1) * TILE_B;
        const uint32_t bbase = abase + 18432;
        const int acol = ((lane >> 4) * 8) * 2;
        const int arow = (lane & 15);
        const int brow = (lane & 7) + ((lane >> 3) & 1) * 8;

        #pragma unroll
        for (int kk = 0; kk < 4; kk++) {
            const int kbyte = kk * 32 + acol;
            uint32_t a[4][4];
            #pragma unroll
            for (int mf = 0; mf < 4; mf++) {
                const uint32_t ad = abase + (wm * 64 + mf * 16 + arow) * ROWSTR + kbyte;
                asm volatile("ldmatrix.sync.aligned.m8n8.x4.shared.b16 {%0,%1,%2,%3}, [%4];"
                    : "=r"(a[mf][0]), "=r"(a[mf][1]), "=r"(a[mf][2]), "=r"(a[mf][3]) : "r"(ad));
            }
            uint32_t b[4][2];
            #pragma unroll
            for (int nfp = 0; nfp < 2; nfp++) {
                const uint32_t bd = bbase + (wn * 32 + nfp * 16 + brow) * ROWSTR + kbyte;
                uint32_t r0, r1, r2, r3;
                asm volatile("ldmatrix.sync.aligned.m8n8.x4.shared.b16 {%0,%1,%2,%3}, [%4];"
                    : "=r"(r0), "=r"(r1), "=r"(r2), "=r"(r3) : "r"(bd));
                b[nfp * 2 + 0][0] = r0; b[nfp * 2 + 0][1] = r2;
                b[nfp * 2 + 1][0] = r1; b[nfp * 2 + 1][1] = r3;
            }
            #pragma unroll
            for (int mf = 0; mf < 4; mf++)
                #pragma unroll
                for (int nf = 0; nf < 4; nf++)
                    asm volatile(
                        "mma.sync.aligned.m16n8k16.row.col.f32.f16.f16.f32 "
                        "{%0,%1,%2,%3}, {%4,%5,%6,%7}, {%8,%9}, {%0,%1,%2,%3};"
                        : "+f"(acc[mf][nf][0]), "+f"(acc[mf][nf][1]),
                          "+f"(acc[mf][nf][2]), "+f"(acc[mf][nf][3])
                        : "r"(a[mf][0]), "r"(a[mf][1]), "r"(a[mf][2]), "r"(a[mf][3]),
                          "r"(b[nf][0]), "r"(b[nf][1]));
        }
        __syncthreads();
    }

    const int gr = lane >> 2;
    const int gc = (lane & 3) * 2;
    float hs = 0.f;

    if (EPI == 4) {
        float rmax[8];
        #pragma unroll
        for (int i = 0; i < 8; i++) rmax[i] = -CUDART_INF_F;
        #pragma unroll
        for (int mf = 0; mf < 4; mf++)
            #pragma unroll
            for (int nf = 0; nf < 4; nf++) {
                const int col = n0 + wn * 32 + nf * 8 + gc;
                #pragma unroll
                for (int half = 0; half < 2; half++) {
                    const int row = m0 + wm * 64 + mf * 16 + gr + half * 8;
                    f16 ba = __float2half(acc[mf][nf][half * 2] * alpha);
                    f16 bb = __float2half(acc[mf][nf][half * 2 + 1] * alpha);
                    f16 pr[2] = {ba, bb};
                    *(uint32_t*)&O1[(size_t)row * Ncols + col] = *(const uint32_t*)pr;
                    float fa = __half2float(ba), fb = __half2float(bb);
                    acc[mf][nf][half * 2] = fa; acc[mf][nf][half * 2 + 1] = fb;
                    rmax[mf * 2 + half] = fmaxf(rmax[mf * 2 + half], fmaxf(fa, fb));
                }
            }
        float rsum[8];
        #pragma unroll
        for (int i = 0; i < 8; i++) rsum[i] = 0.f;
        #pragma unroll
        for (int mf = 0; mf < 4; mf++)
            #pragma unroll
            for (int nf = 0; nf < 4; nf++)
                #pragma unroll
                for (int half = 0; half < 2; half++)
                    rsum[mf * 2 + half] += __expf(acc[mf][nf][half * 2]     - rmax[mf * 2 + half])
                                         + __expf(acc[mf][nf][half * 2 + 1] - rmax[mf * 2 + half]);
        #pragma unroll
        for (int o = 1; o <= 2; o <<= 1)
            #pragma unroll
            for (int i = 0; i < 8; i++) {
                float m2 = __shfl_xor_sync(0xffffffffu, rmax[i], o);
                float s2 = __shfl_xor_sync(0xffffffffu, rsum[i], o);
                float nm = fmaxf(rmax[i], m2);
                rsum[i] = rsum[i] * __expf(rmax[i] - nm) + s2 * __expf(m2 - nm);
                rmax[i] = nm;
            }
        if ((lane & 3) == 0) {
            #pragma unroll
            for (int mf = 0; mf < 4; mf++)
                #pragma unroll
                for (int half = 0; half < 2; half++) {
                    int rl = wm * 64 + mf * 16 + gr + half * 8;
                    smax[rl][wn] = rmax[mf * 2 + half];
                    ssum[rl][wn] = rsum[mf * 2 + half];
                }
        }
        __syncthreads();
        if (t < 128) {
            float m = smax[t][0];
            #pragma unroll
            for (int w = 1; w < 4; w++) m = fmaxf(m, smax[t][w]);
            float s = 0.f;
            #pragma unroll
            for (int w = 0; w < 4; w++) s += ssum[t][w] * __expf(smax[t][w] - m);
            size_t pidx = ((size_t)blockIdx.z * gridDim.x + blockIdx.x) * (size_t)(gridDim.y * 128)
                        + m0 + t;
            pmax[pidx] = m; psum[pidx] = s;
        }
        return;
    }

    #pragma unroll
    for (int mf = 0; mf < 4; mf++) {
        #pragma unroll
        for (int nf = 0; nf < 4; nf++) {
            const int col = n0 + wn * 32 + nf * 8 + gc;
            #pragma unroll
            for (int half = 0; half < 2; half++) {
                const int row = m0 + wm * 64 + mf * 16 + gr + half * 8;
                const float va = acc[mf][nf][half * 2];
                const float vb = acc[mf][nf][half * 2 + 1];
                if (EPI == 1) {
                    // merged Q/K scatter: col in [0,2048)
                    const size_t half_off = (size_t)(col >> 10) * KOFF;
                    const int hq = col & 1023;
                    const int h_ = hq >> 6, q_ = hq & 63;
                    const int b_ = row >> 10, n_ = row & 1023;
                    *(uint32_t*)&O1[half_off + (((size_t)(b_ * Hh + h_)) * Nn + n_) * QKd + q_] =
                        pack_h2(va, vb);
                } else if (EPI == 2) {
                    const size_t off = (size_t)row * Ncols + col;
                    const float v0 = fmaxf(va, 0.f), v1 = fmaxf(vb, 0.f);
                    hs = fmaf(v0, v0, fmaf(v1, v1, hs));
                    *(uint32_t*)(O1 + off) = pack_h2(-v0, -v1);
                } else {
                    const size_t off = (size_t)row * Ncols + col;
                    float2 v = make_float2(va * alpha, vb * alpha);
                    *(float2*)&C[off] = v;
                }
            }
        }
    }
    if (EPI == 2) {
        sred[t] = (double)hs;
        __syncthreads();
        for (int o = 128; o > 0; o >>= 1) { if (t < o) sred[t] += sred[t + o]; __syncthreads(); }
        if (t == 0) part[blockIdx.y * gridDim.x + blockIdx.x] = sred[0];
    }
}

// ============================================================================
// lse combine
// ============================================================================
__global__ void __launch_bounds__(256) lse_combine(
    const float* __restrict__ pmax, const float* __restrict__ psum,
    float* __restrict__ lse, double* __restrict__ lse_part)
{
    __shared__ double sm[256];
    const int idx = blockIdx.x * 256 + threadIdx.x;
    const int bh = idx >> 10, n = idx & 1023;
    float ms[8], ss[8];
    float m = -CUDART_INF_F;
    #pragma unroll
    for (int i = 0; i < 8; i++) {
        ms[i] = pmax[((size_t)bh * 8 + i) * Nn + n];
        ss[i] = psum[((size_t)bh * 8 + i) * Nn + n];
        m = fmaxf(m, ms[i]);
    }
    float s = 0.f;
    #pragma unroll
    for (int i = 0; i < 8; i++) s += ss[i] * __expf(ms[i] - m);
    const float l = m + logf(s);
    lse[idx] = l;
    sm[threadIdx.x] = (double)l;
    __syncthreads();
    for (int o = 128; o > 0; o >>= 1) {
        if (threadIdx.x < o) sm[threadIdx.x] += sm[threadIdx.x + o];
        __syncthreads();
    }
    if (threadIdx.x == 0) lse_part[blockIdx.x] = sm[0];
}

// ============================================================================
// dQ-GEMM: dm2[(b*N+n)][h*64+q] = f16(-sum_m exp(S-lse[n]) * Kt[q][m])
// ============================================================================
#define DQ_STAGE 27648
__global__ void __launch_bounds__(256) att_dq_h(
    const f16* __restrict__ S, const f16* __restrict__ Kt,
    const float* __restrict__ lse, f16* __restrict__ dm)
{
    extern __shared__ char dsm[];
    const uint32_t sbase = smem_u32(dsm);
    const int t = threadIdx.x, wid = t >> 5, lane = t & 31;
    const int bh = blockIdx.y, n0 = blockIdx.x * 128;
    const f16* Ag = S + (size_t)bh * Nn * Nn;
    const f16* Bg = Kt + (size_t)bh * QKd * Nn;

    float acc[8][4];
    #pragma unroll
    for (int i = 0; i < 8; i++)
        #pragma unroll
        for (int r = 0; r < 4; r++) acc[i][r] = 0.f;

    const int lrow = t >> 3, lseg = (t & 7) * 8;
    const int xr = t >> 1, xh = (t & 1) * 64;
    const float xlse = lse[bh * Nn + n0 + xr];

    auto load = [&](int kb) {
        const uint32_t ab = sbase + (uint32_t)(kb & 1) * DQ_STAGE;
        const uint32_t bb = ab + 18432;
        const size_t kEl = (size_t)(kb << 6) + lseg;
        #pragma unroll
        for (int i = 0; i < 4; i++) {
            const int row = lrow + i * 32;
            asm volatile("cp.async.cg.shared.global [%0], [%1], 16;"
                :: "r"(ab + row * ROWSTR + lseg * 2), "l"(Ag + (size_t)(n0 + row) * Nn + kEl));
        }
        #pragma unroll
        for (int i = 0; i < 2; i++) {
            const int row = lrow + i * 32;
            asm volatile("cp.async.cg.shared.global [%0], [%1], 16;"
                :: "r"(bb + row * ROWSTR + lseg * 2), "l"(Bg + (size_t)row * Nn + kEl));
        }
        asm volatile("cp.async.commit_group;" ::: "memory");
    };

    load(0);
    for (int kb = 0; kb < 16; kb++) {
        if (kb < 15) { load(kb + 1); asm volatile("cp.async.wait_group 1;" ::: "memory"); }
        else         { asm volatile("cp.async.wait_group 0;" ::: "memory"); }
        __syncthreads();
        {
            char* abuf = dsm + (size_t)(kb & 1) * DQ_STAGE + xr * ROWSTR + xh;
            #pragma unroll
            for (int j = 0; j < 4; j++) {
                uint4 w = *(uint4*)(abuf + j * 16);
                __half2* p2 = (__half2*)&w;
                #pragma unroll
                for (int q = 0; q < 4; q++) {
                    float2 f = __half22float2(p2[q]);
                    p2[q] = __floats2half2_rn(__expf(f.x - xlse), __expf(f.y - xlse));
                }
                *(uint4*)(abuf + j * 16) = w;
            }
        }
        __syncthreads();
        const uint32_t ab = sbase + (uint32_t)(kb & 1) * DQ_STAGE;
        const uint32_t bb = ab + 18432;
        const int acol = ((lane >> 4) * 8) * 2;
        const int arow = lane & 15;
        const int brow = (lane & 7) + ((lane >> 3) & 1) * 8;
        #pragma unroll
        for (int kk = 0; kk < 4; kk++) {
            const int kbyte = kk * 32 + acol;
            uint32_t a[4];
            asm volatile("ldmatrix.sync.aligned.m8n8.x4.shared.b16 {%0,%1,%2,%3}, [%4];"
                : "=r"(a[0]), "=r"(a[1]), "=r"(a[2]), "=r"(a[3])
                : "r"(ab + (wid * 16 + arow) * ROWSTR + kbyte));
            uint32_t b[8][2];
            #pragma unroll
            for (int nfp = 0; nfp < 4; nfp++) {
                uint32_t r0, r1, r2, r3;
                asm volatile("ldmatrix.sync.aligned.m8n8.x4.shared.b16 {%0,%1,%2,%3}, [%4];"
                    : "=r"(r0), "=r"(r1), "=r"(r2), "=r"(r3)
                    : "r"(bb + (nfp * 16 + brow) * ROWSTR + kbyte));
                b[nfp * 2 + 0][0] = r0; b[nfp * 2 + 0][1] = r2;
                b[nfp * 2 + 1][0] = r1; b[nfp * 2 + 1][1] = r3;
            }
            #pragma unroll
            for (int nf = 0; nf < 8; nf++)
                asm volatile(
                    "mma.sync.aligned.m16n8k16.row.col.f32.f16.f16.f32 "
                    "{%0,%1,%2,%3}, {%4,%5,%6,%7}, {%8,%9}, {%0,%1,%2,%3};"
                    : "+f"(acc[nf][0]), "+f"(acc[nf][1]), "+f"(acc[nf][2]), "+f"(acc[nf][3])
                    : "r"(a[0]), "r"(a[1]), "r"(a[2]), "r"(a[3]),
                      "r"(b[nf][0]), "r"(b[nf][1]));
        }
        __syncthreads();
    }
    const int gr = lane >> 2, gc = (lane & 3) * 2;
    const int b_ = bh >> 4, h_ = bh & 15;
    #pragma unroll
    for (int nf = 0; nf < 8; nf++) {
        const int col = nf * 8 + gc;
        #pragma unroll
        for (int half = 0; half < 2; half++) {
            const int n = n0 + wid * 16 + gr + half * 8;
            *(uint32_t*)&dm[((size_t)(b_ * 1024 + n)) * BIGK + h_ * 64 + col] =
                pack_h2(-acc[nf][half * 2], -acc[nf][half * 2 + 1]);
        }
    }
}

// ============================================================================
// dK-GEMM: dm2[(b*N+m)][1024 + h*64+q] = f16(-sum_n exp(S-lse[n]) * Qt[q][n])
// ============================================================================
#define DK_ASTR 272
#define DK_STAGE 26624
__global__ void __launch_bounds__(256) att_dk_h(
    const f16* __restrict__ S, const f16* __restrict__ Qt,
    const float* __restrict__ lse, f16* __restrict__ dm)
{
    extern __shared__ char dsm[];
    const uint32_t sbase = smem_u32(dsm);
    const int t = threadIdx.x, wid = t >> 5, lane = t & 31;
    const int bh = blockIdx.y, m0 = blockIdx.x * 128;
    const f16* Ag = S + (size_t)bh * Nn * Nn;
    const f16* Bg = Qt + (size_t)bh * QKd * Nn;

    float acc[8][4];
    #pragma unroll
    for (int i = 0; i < 8; i++)
        #pragma unroll
        for (int r = 0; r < 4; r++) acc[i][r] = 0.f;

    const int xr = t >> 2, xq = (t & 3) * 64;

    auto load = [&](int kb) {
        const uint32_t ab = sbase + (uint32_t)(kb & 1) * DK_STAGE;
        const uint32_t bb = ab + 17408;
        const int ar = t >> 4, aseg = (t & 15) * 8;
        #pragma unroll
        for (int i = 0; i < 4; i++) {
            const int row = ar + i * 16;
            asm volatile("cp.async.cg.shared.global [%0], [%1], 16;"
                :: "r"(ab + row * DK_ASTR + aseg * 2),
                   "l"(Ag + (size_t)((kb << 6) + row) * Nn + m0 + aseg));
        }
        const int br = t >> 3, bseg = (t & 7) * 8;
        #pragma unroll
        for (int i = 0; i < 2; i++) {
            const int row = br + i * 32;
            asm volatile("cp.async.cg.shared.global [%0], [%1], 16;"
                :: "r"(bb + row * ROWSTR + bseg * 2),
                   "l"(Bg + (size_t)row * Nn + (kb << 6) + bseg));
        }
        asm volatile("cp.async.commit_group;" ::: "memory");
    };

    load(0);
    for (int kb = 0; kb < 16; kb++) {
        if (kb < 15) { load(kb + 1); asm volatile("cp.async.wait_group 1;" ::: "memory"); }
        else         { asm volatile("cp.async.wait_group 0;" ::: "memory"); }
        __syncthreads();
        {
            const float xlse = lse[bh * Nn + (kb << 6) + xr];
            char* abuf = dsm + (size_t)(kb & 1) * DK_STAGE + xr * DK_ASTR + xq;
            #pragma unroll
            for (int j = 0; j < 4; j++) {
                uint4 w = *(uint4*)(abuf + j * 16);
                __half2* p2 = (__half2*)&w;
                #pragma unroll
                for (int q = 0; q < 4; q++) {
                    float2 f = __half22float2(p2[q]);
                    p2[q] = __floats2half2_rn(__expf(f.x - xlse), __expf(f.y - xlse));
                }
                *(uint4*)(abuf + j * 16) = w;
            }
        }
        __syncthreads();
        const uint32_t ab = sbase + (uint32_t)(kb & 1) * DK_STAGE;
        const uint32_t bb = ab + 17408;
        const int tl = lane >> 3;
        const int brow = (lane & 7) + ((lane >> 3) & 1) * 8;
        const int bcol = ((lane >> 4) * 8) * 2;
        #pragma unroll
        for (int kk = 0; kk < 4; kk++) {
            uint32_t a[4];
            const uint32_t ad = ab + (kk * 16 + (tl >> 1) * 8 + (lane & 7)) * DK_ASTR
                              + (wid * 16 + (tl & 1) * 8) * 2;
            asm volatile("ldmatrix.sync.aligned.m8n8.x4.trans.shared.b16 {%0,%1,%2,%3}, [%4];"
                : "=r"(a[0]), "=r"(a[1]), "=r"(a[2]), "=r"(a[3]) : "r"(ad));
            uint32_t b[8][2];
            const int kbyte = kk * 32 + bcol;
            #pragma unroll
            for (int nfp = 0; nfp < 4; nfp++) {
                uint32_t r0, r1, r2, r3;
                asm volatile("ldmatrix.sync.aligned.m8n8.x4.shared.b16 {%0,%1,%2,%3}, [%4];"
                    : "=r"(r0), "=r"(r1), "=r"(r2), "=r"(r3)
                    : "r"(bb + (nfp * 16 + brow) * ROWSTR + kbyte));
                b[nfp * 2 + 0][0] = r0; b[nfp * 2 + 0][1] = r2;
                b[nfp * 2 + 1][0] = r1; b[nfp * 2 + 1][1] = r3;
            }
            #pragma unroll
            for (int nf = 0; nf < 8; nf++)
                asm volatile(
                    "mma.sync.aligned.m16n8k16.row.col.f32.f16.f16.f32 "
                    "{%0,%1,%2,%3}, {%4,%5,%6,%7}, {%8,%9}, {%0,%1,%2,%3};"
                    : "+f"(acc[nf][0]), "+f"(acc[nf][1]), "+f"(acc[nf][2]), "+f"(acc[nf][3])
                    : "r"(a[0]), "r"(a[1]), "r"(a[2]), "r"(a[3]),
                      "r"(b[nf][0]), "r"(b[nf][1]));
        }
        __syncthreads();
    }
    const int gr = lane >> 2, gc = (lane & 3) * 2;
    const int b_ = bh >> 4, h_ = bh & 15;
    #pragma unroll
    for (int nf = 0; nf < 8; nf++) {
        const int col = nf * 8 + gc;
        #pragma unroll
        for (int half = 0; half < 2; half++) {
            const int m = m0 + wid * 16 + gr + half * 8;
            *(uint32_t*)&dm[((size_t)(b_ * 1024 + m)) * BIGK + 1024 + h_ * 64 + col] =
                pack_h2(-acc[nf][half * 2], -acc[nf][half * 2 + 1]);
        }
    }
}

// ============================================================================
// Final energy
// ============================================================================
__global__ void energy_final(const double* __restrict__ lse_part,
                             const double* __restrict__ h2_part,
                             float* __restrict__ out)
{
    __shared__ double sm[256];
    int t = threadIdx.x;
    double s = 0.0;
    for (int i = t; i < LSE_PARTS; i += 256) s += lse_part[i];
    double s2 = 0.0;
    for (int i = t; i < (BNr / 128) * (HIDd / 128); i += 256) s2 += h2_part[i];
    sm[t] = -8.0 * s - 0.5 * s2;
    __syncthreads();
    for (int o = 128; o > 0; o >>= 1) { if (t < o) sm[t] += sm[t + o]; __syncthreads(); }
    if (t == 0) out[(size_t)BNr * Dd] = (float)sm[0];
}

// ============================================================================
// Host launcher
// ============================================================================
extern "C" void kernel_launch(void* const* d_in, const int* in_sizes, int n_in,
                              void* d_out, int out_size)
{
    const float* x    = (const float*)d_in[0];
    const float* Wq   = (const float*)d_in[1];
    const float* Wk   = (const float*)d_in[2];
    const float* Whop = (const float*)d_in[3];
    float* out = (float*)d_out;

    f16 *pSb;
    float *pLseV, *pPmax, *pPsum;
    double *pLse, *pH2;
    f16 *px1, *pwqk, *pwtb, *pwht1, *pdm2, *pqk, *pqt, *pkt;

    cudaGetSymbolAddress((void**)&pSb,  g_Sb);
    cudaGetSymbolAddress((void**)&pLseV,g_lse);
    cudaGetSymbolAddress((void**)&pPmax,g_pmax);
    cudaGetSymbolAddress((void**)&pPsum,g_psum);
    cudaGetSymbolAddress((void**)&pLse, g_lse_part);
    cudaGetSymbolAddress((void**)&pH2,  g_h2_part);
    cudaGetSymbolAddress((void**)&px1,  g_x1);
    cudaGetSymbolAddress((void**)&pwqk, g_wqk);
    cudaGetSymbolAddress((void**)&pwtb, g_wtb);
    cudaGetSymbolAddress((void**)&pwht1,g_wht1);
    cudaGetSymbolAddress((void**)&pdm2, g_dm2);
    cudaGetSymbolAddress((void**)&pqk,  g_qk);
    cudaGetSymbolAddress((void**)&pqt,  g_qt);  cudaGetSymbolAddress((void**)&pkt,  g_kt);

    cudaFuncSetAttribute(tgemm<0>, cudaFuncAttributeMaxDynamicSharedMemorySize, TG_SMEM);
    cudaFuncSetAttribute(tgemm<1>, cudaFuncAttributeMaxDynamicSharedMemorySize, TG_SMEM);
    cudaFuncSetAttribute(tgemm<2>, cudaFuncAttributeMaxDynamicSharedMemorySize, TG_SMEM);
    cudaFuncSetAttribute(tgemm<4>, cudaFuncAttributeMaxDynamicSharedMemorySize, TG_SMEM);
    cudaFuncSetAttribute(att_dq_h, cudaFuncAttributeMaxDynamicSharedMemorySize, 2 * DQ_STAGE);
    cudaFuncSetAttribute(att_dk_h, cudaFuncAttributeMaxDynamicSharedMemorySize, 2 * DK_STAGE);

    dim3 blk(256);

    // 0. input conversions: x cvt; fused cvt+trans per weight (single fp32 read)
    cvt_plain4<<<(BNr * Dd) / 1024, blk>>>(x, px1);
    cvt_trans<<<dim3(Dd / 32, HQ / 32), blk>>>(Wq, Dd, pwqk, Dd, pwtb, BIGK);
    cvt_trans<<<dim3(Dd / 32, HQ / 32), blk>>>(Wk, Dd, pwqk + (size_t)HQ * Dd, Dd,
                                               pwtb + 1024, BIGK);
    cvt_trans<<<dim3(HIDd / 32, Dd / 32), blk>>>(Whop, HIDd, pwtb + 2048, BIGK, pwht1, Dd);

    // 1. merged Q/K projection (N=2048) -> f16 qk scattered [q|k][bh][n][qk]
    tgemm<1><<<dim3(2048 / 128, BNr / 128, 1), blk, TG_SMEM>>>(
        px1, pwqk, nullptr, 0, Dd, 1.f, pqk, nullptr, nullptr, nullptr, 0, 0, 0);

    // 2. transposes for dq/dk B-operands
    trans_qk<<<dim3(Nn / 32, QKd / 32, BH), blk>>>(pqk, pqk + KOFF, pqt, pkt);

    // 3. S = BETA*QK^T -> f16 Sb + per-block row softmax partials
    tgemm<4><<<dim3(Nn / 128, Nn / 128, BH), blk, TG_SMEM>>>(
        pqk, pqk + KOFF, nullptr, Nn, QKd, BETA, pSb, nullptr,
        pPmax, pPsum, (size_t)Nn * QKd, (size_t)Nn * QKd, (size_t)Nn * Nn);

    // 4. lse combine (+ energy partials)
    lse_combine<<<LSE_PARTS, blk>>>(pPmax, pPsum, pLseV, pLse);

    // 5. dQm, dKm (exp on the fly) -> dm2 cols [0,2048)
    att_dq_h<<<dim3(Nn / 128, BH), blk, 2 * DQ_STAGE>>>(pSb, pkt, pLseV, pdm2);
    att_dk_h<<<dim3(Nn / 128, BH), blk, 2 * DK_STAGE>>>(pSb, pqt, pLseV, pdm2);

    // 6. Hb: -relu(x1 @ WhopT) -> dm2 cols [2048,6144); h2 partials
    tgemm<2><<<dim3(HIDd / 128, BNr / 128, 1), blk, TG_SMEM>>>(
        px1, pwht1, nullptr, BIGK, Dd, 1.f, pdm2 + 2048, pH2,
        nullptr, nullptr, 0, 0, 0);

    // 7. grad = dm2 @ [WqT|WkT|Whop]  (single K=6144 GEMM, writes out once)
    tgemm<0><<<dim3(Dd / 128, BNr / 128, 1), blk, TG_SMEM>>>(
        pdm2, pwtb, out, Dd, BIGK, 1.f, nullptr, nullptr,
        nullptr, nullptr, 0, 0, 0);

    // 8. energy scalar
    if (out_size > BNr * Dd)
        energy_final<<<1, 256>>>(pLse, pH2, out);
}

// round 17
// speedup vs baseline: 1.8375x; 1.0292x over previous
#include <cuda_runtime.h>
#include <cuda_fp16.h>
#include <math_constants.h>
#include <cstdint>

#define Bsz 4
#define Nn 1024
#define Dd 1024
#define Hh 16
#define QKd 64
#define HIDd 4096
#define BH 64           // B*H
#define BNr 4096        // B*N
#define HQ 1024         // H*QK
#define BETA 0.125f
#define LSE_PARTS 256
#define KOFF ((size_t)BH * Nn * QKd)   // q/k half offset in g_qk
#define BIGK 6144

typedef unsigned long long u64;
typedef __half f16;

__device__ __forceinline__ uint32_t smem_u32(const void* p) {
    uint32_t a;
    asm("{ .reg .u64 t; cvta.to.shared.u64 t, %1; cvt.u32.u64 %0, t; }" : "=r"(a) : "l"(p));
    return a;
}
__device__ __forceinline__ uint32_t pack_h2(float a, float b) {
    f16 t[2] = {__float2half(a), __float2half(b)};
    return *(const uint32_t*)t;
}

// -------- device scratch --------
__device__ f16    g_Pb [(size_t)BH * Nn * Nn];    // exp(s - blockmax) f16 (128MB)
__device__ float  g_lse [BH * Nn];
__device__ float  g_pmax[(size_t)BH * 8 * Nn];
__device__ float  g_psum[(size_t)BH * 8 * Nn];
__device__ double g_lse_part[LSE_PARTS];
__device__ double g_h2_part [(BNr / 128) * (HIDd / 128)];

__device__ f16 g_x1 [(size_t)BNr * Dd];
__device__ f16 g_wqk[(size_t)2 * HQ * Dd];        // [ Wq1 ; Wk1 ] stacked rows
__device__ f16 g_wtb[(size_t)Dd * BIGK];          // [d][ WqT | WkT | Whop ]
__device__ f16 g_wht1[(size_t)HIDd * Dd];         // Whop transposed [HID,D]
__device__ f16 g_dm2[(size_t)BNr * BIGK];         // [b*n][ dqm | dkm | -relu(h) ]
__device__ f16 g_qk [2 * KOFF];                   // q1 | k1, each [bh][n][qk]
__device__ f16 g_qt[(size_t)BH * QKd * Nn], g_kt[(size_t)BH * QKd * Nn];

// ============================================================================
// Converters / transposes
// ============================================================================
__global__ void __launch_bounds__(256) cvt_plain4(
    const float* __restrict__ in, f16* __restrict__ o1)
{
    size_t i = ((size_t)blockIdx.x * 256 + threadIdx.x) * 4;
    float4 v = *(const float4*)(in + i);
    f16 h[4] = {__float2half(v.x), __float2half(v.y),
                __float2half(v.z), __float2half(v.w)};
    *(u64*)(o1 + i) = *(const u64*)h;
}
__global__ void __launch_bounds__(256) cvt_trans(
    const float* __restrict__ in, int C,
    f16* __restrict__ nat, int ns, f16* __restrict__ tr, int ts)
{
    __shared__ float tile[32][33];
    const int c0 = blockIdx.x * 32, r0 = blockIdx.y * 32;
    const int tx = threadIdx.x & 31, ty = threadIdx.x >> 5;
    #pragma unroll
    for (int i = 0; i < 4; i++) {
        int r = r0 + ty + i * 8;
        float v = in[(size_t)r * C + c0 + tx];
        tile[ty + i * 8][tx] = v;
        nat[(size_t)r * ns + c0 + tx] = __float2half(v);
    }
    __syncthreads();
    #pragma unroll
    for (int i = 0; i < 4; i++)
        tr[(size_t)(c0 + ty + i * 8) * ts + r0 + tx] = __float2half(tile[tx][ty + i * 8]);
}
__global__ void __launch_bounds__(256) trans_qk(
    const f16* __restrict__ Q, const f16* __restrict__ K,
    f16* __restrict__ Qt, f16* __restrict__ Kt)
{
    __shared__ f16 tq[32][34], tk[32][34];
    const int n0 = blockIdx.x * 32, q0 = blockIdx.y * 32, bh = blockIdx.z;
    const f16* Qb = Q + (size_t)bh * Nn * QKd;
    const f16* Kb = K + (size_t)bh * Nn * QKd;
    const int tx = threadIdx.x & 31, ty = threadIdx.x >> 5;
    #pragma unroll
    for (int i = 0; i < 4; i++) {
        int n = ty + i * 8;
        tq[n][tx] = Qb[(size_t)(n0 + n) * QKd + q0 + tx];
        tk[n][tx] = Kb[(size_t)(n0 + n) * QKd + q0 + tx];
    }
    __syncthreads();
    #pragma unroll
    for (int i = 0; i < 4; i++) {
        int r = ty + i * 8;
        Qt[((size_t)bh * QKd + q0 + r) * Nn + n0 + tx] = tq[tx][r];
        Kt[((size_t)bh * QKd + q0 + r) * Nn + n0 + tx] = tk[tx][r];
    }
}

// ============================================================================
// HMMA fp16 GEMM, single-sweep, 2-stage cp.async (72KB smem -> 2 CTAs/SM).
//   EPI=0: fp32 C = alpha*D (direct write)
//   EPI=1: f16 scatter to q/k buffers (merged projection; col>=1024 -> K half)
//   EPI=2: -relu; f16 to O1 (stride Ncols); sum(v^2) partials
//   EPI=4: block-softmax: O1 = f16(exp(alpha*D - blockrowmax)); pmax/psum out
// ============================================================================
#define TILE_B 36864
#define ROWSTR 144
#define TG_SMEM (2 * TILE_B)

template<int EPI>
__global__ void __launch_bounds__(256) tgemm(
    const f16* __restrict__ A1, const f16* __restrict__ B1,
    float* __restrict__ C, int Ncols, int Kglob, float alpha,
    f16* __restrict__ O1, double* __restrict__ part,
    float* __restrict__ pmax, float* __restrict__ psum,
    size_t zsA, size_t zsB, size_t zsC)
{
    extern __shared__ char dsm[];
    __shared__ double sred[256];
    __shared__ float smax[128][5], ssum[128][5];
    const uint32_t sbase = smem_u32(dsm);

    A1 += (size_t)blockIdx.z * zsA;
    B1 += (size_t)blockIdx.z * zsB;
    if (EPI == 1 || EPI == 4) O1 += (size_t)blockIdx.z * zsC;
    else                      C  += (size_t)blockIdx.z * zsC;

    const int t = threadIdx.x;
    const int wid = t >> 5, lane = t & 31;
    const int m0 = blockIdx.y * 128, n0 = blockIdx.x * 128;
    const int wm = wid >> 2, wn = wid & 3;

    const int TOT = Kglob >> 6;

    float acc[4][4][4];
    #pragma unroll
    for (int i = 0; i < 4; i++)
        #pragma unroll
        for (int j = 0; j < 4; j++)
            #pragma unroll
            for (int r = 0; r < 4; r++) acc[i][j][r] = 0.f;

    const int lrow = t >> 3;
    const int lseg = (t & 7) * 8;

    auto issue_load = [&](int c) {
        const uint32_t abase = sbase + (uint32_t)(c & 1) * TILE_B;
        const uint32_t bbase = abase + 18432;
        const size_t kEl = (size_t)(c << 6) + lseg;
        #pragma unroll
        for (int i = 0; i < 4; i++) {
            const int row = lrow + i * 32;
            asm volatile("cp.async.cg.shared.global [%0], [%1], 16;"
                :: "r"(abase + row * ROWSTR + lseg * 2), "l"(A1 + (size_t)(m0 + row) * Kglob + kEl));
            asm volatile("cp.async.cg.shared.global [%0], [%1], 16;"
                :: "r"(bbase + row * ROWSTR + lseg * 2), "l"(B1 + (size_t)(n0 + row) * Kglob + kEl));
        }
        asm volatile("cp.async.commit_group;" ::: "memory");
    };

    issue_load(0);

    for (int c = 0; c < TOT; c++) {
        if (c + 1 < TOT) {
            issue_load(c + 1);
            asm volatile("cp.async.wait_group 1;" ::: "memory");
        } else {
            asm volatile("cp.async.wait_group 0;" ::: "memory");
        }
        __syncthreads();

        const uint32_t abase = sbase + (uint32_t)(c & 1) * TILE_B;
        const uint32_t bbase = abase + 18432;
        const int acol = ((lane >> 4) * 8) * 2;
        const int arow = (lane & 15);
        const int brow = (lane & 7) + ((lane >> 3) & 1) * 8;

        #pragma unroll
        for (int kk = 0; kk < 4; kk++) {
            const int kbyte = kk * 32 + acol;
            uint32_t a[4][4];
            #pragma unroll
            for (int mf = 0; mf < 4; mf++) {
                const uint32_t ad = abase + (wm * 64 + mf * 16 + arow) * ROWSTR + kbyte;
                asm volatile("ldmatrix.sync.aligned.m8n8.x4.shared.b16 {%0,%1,%2,%3}, [%4];"
                    : "=r"(a[mf][0]), "=r"(a[mf][1]), "=r"(a[mf][2]), "=r"(a[mf][3]) : "r"(ad));
            }
            uint32_t b[4][2];
            #pragma unroll
            for (int nfp = 0; nfp < 2; nfp++) {
                const uint32_t bd = bbase + (wn * 32 + nfp * 16 + brow) * ROWSTR + kbyte;
                uint32_t r0, r1, r2, r3;
                asm volatile("ldmatrix.sync.aligned.m8n8.x4.shared.b16 {%0,%1,%2,%3}, [%4];"
                    : "=r"(r0), "=r"(r1), "=r"(r2), "=r"(r3) : "r"(bd));
                b[nfp * 2 + 0][0] = r0; b[nfp * 2 + 0][1] = r2;
                b[nfp * 2 + 1][0] = r1; b[nfp * 2 + 1][1] = r3;
            }
            #pragma unroll
            for (int mf = 0; mf < 4; mf++)
                #pragma unroll
                for (int nf = 0; nf < 4; nf++)
                    asm volatile(
                        "mma.sync.aligned.m16n8k16.row.col.f32.f16.f16.f32 "
                        "{%0,%1,%2,%3}, {%4,%5,%6,%7}, {%8,%9}, {%0,%1,%2,%3};"
                        : "+f"(acc[mf][nf][0]), "+f"(acc[mf][nf][1]),
                          "+f"(acc[mf][nf][2]), "+f"(acc[mf][nf][3])
                        : "r"(a[mf][0]), "r"(a[mf][1]), "r"(a[mf][2]), "r"(a[mf][3]),
                          "r"(b[nf][0]), "r"(b[nf][1]));
        }
        __syncthreads();
    }

    const int gr = lane >> 2;
    const int gc = (lane & 3) * 2;
    float hs = 0.f;

    if (EPI == 4) {
        // 1. scale by alpha + per-row thread-local max
        float rmax[8];
        #pragma unroll
        for (int i = 0; i < 8; i++) rmax[i] = -CUDART_INF_F;
        #pragma unroll
        for (int mf = 0; mf < 4; mf++)
            #pragma unroll
            for (int nf = 0; nf < 4; nf++)
                #pragma unroll
                for (int half = 0; half < 2; half++) {
                    float fa = acc[mf][nf][half * 2] * alpha;
                    float fb = acc[mf][nf][half * 2 + 1] * alpha;
                    acc[mf][nf][half * 2] = fa; acc[mf][nf][half * 2 + 1] = fb;
                    rmax[mf * 2 + half] = fmaxf(rmax[mf * 2 + half], fmaxf(fa, fb));
                }
        // 2. lane-group (4 lanes/row) max
        #pragma unroll
        for (int o = 1; o <= 2; o <<= 1)
            #pragma unroll
            for (int i = 0; i < 8; i++)
                rmax[i] = fmaxf(rmax[i], __shfl_xor_sync(0xffffffffu, rmax[i], o));
        if ((lane & 3) == 0) {
            #pragma unroll
            for (int mf = 0; mf < 4; mf++)
                #pragma unroll
                for (int half = 0; half < 2; half++) {
                    int rl = wm * 64 + mf * 16 + gr + half * 8;
                    smax[rl][wn] = rmax[mf * 2 + half];
                }
        }
        __syncthreads();
        if (t < 128) {
            float m = smax[t][0];
            #pragma unroll
            for (int w = 1; w < 4; w++) m = fmaxf(m, smax[t][w]);
            smax[t][4] = m;
        }
        __syncthreads();
        // 3. p'' = exp(s - blockmax); store f16; accumulate rsum
        float bm[8];
        #pragma unroll
        for (int mf = 0; mf < 4; mf++)
            #pragma unroll
            for (int half = 0; half < 2; half++)
                bm[mf * 2 + half] = smax[wm * 64 + mf * 16 + gr + half * 8][4];
        float rsum[8];
        #pragma unroll
        for (int i = 0; i < 8; i++) rsum[i] = 0.f;
        #pragma unroll
        for (int mf = 0; mf < 4; mf++)
            #pragma unroll
            for (int nf = 0; nf < 4; nf++) {
                const int col = n0 + wn * 32 + nf * 8 + gc;
                #pragma unroll
                for (int half = 0; half < 2; half++) {
                    const int row = m0 + wm * 64 + mf * 16 + gr + half * 8;
                    float pa = __expf(acc[mf][nf][half * 2]     - bm[mf * 2 + half]);
                    float pb = __expf(acc[mf][nf][half * 2 + 1] - bm[mf * 2 + half]);
                    *(uint32_t*)&O1[(size_t)row * Ncols + col] = pack_h2(pa, pb);
                    rsum[mf * 2 + half] += pa + pb;
                }
            }
        #pragma unroll
        for (int o = 1; o <= 2; o <<= 1)
            #pragma unroll
            for (int i = 0; i < 8; i++)
                rsum[i] += __shfl_xor_sync(0xffffffffu, rsum[i], o);
        if ((lane & 3) == 0) {
            #pragma unroll
            for (int mf = 0; mf < 4; mf++)
                #pragma unroll
                for (int half = 0; half < 2; half++) {
                    int rl = wm * 64 + mf * 16 + gr + half * 8;
                    ssum[rl][wn] = rsum[mf * 2 + half];
                }
        }
        __syncthreads();
        if (t < 128) {
            float s = 0.f;
            #pragma unroll
            for (int w = 0; w < 4; w++) s += ssum[t][w];
            size_t pidx = ((size_t)blockIdx.z * gridDim.x + blockIdx.x) * (size_t)(gridDim.y * 128)
                        + m0 + t;
            pmax[pidx] = smax[t][4]; psum[pidx] = s;
        }
        return;
    }

    #pragma unroll
    for (int mf = 0; mf < 4; mf++) {
        #pragma unroll
        for (int nf = 0; nf < 4; nf++) {
            const int col = n0 + wn * 32 + nf * 8 + gc;
            #pragma unroll
            for (int half = 0; half < 2; half++) {
                const int row = m0 + wm * 64 + mf * 16 + gr + half * 8;
                const float va = acc[mf][nf][half * 2];
                const float vb = acc[mf][nf][half * 2 + 1];
                if (EPI == 1) {
                    const size_t half_off = (size_t)(col >> 10) * KOFF;
                    const int hq = col & 1023;
                    const int h_ = hq >> 6, q_ = hq & 63;
                    const int b_ = row >> 10, n_ = row & 1023;
                    *(uint32_t*)&O1[half_off + (((size_t)(b_ * Hh + h_)) * Nn + n_) * QKd + q_] =
                        pack_h2(va, vb);
                } else if (EPI == 2) {
                    const size_t off = (size_t)row * Ncols + col;
                    const float v0 = fmaxf(va, 0.f), v1 = fmaxf(vb, 0.f);
                    hs = fmaf(v0, v0, fmaf(v1, v1, hs));
                    *(uint32_t*)(O1 + off) = pack_h2(-v0, -v1);
                } else {
                    const size_t off = (size_t)row * Ncols + col;
                    float2 v = make_float2(va * alpha, vb * alpha);
                    *(float2*)&C[off] = v;
                }
            }
        }
    }
    if (EPI == 2) {
        sred[t] = (double)hs;
        __syncthreads();
        for (int o = 128; o > 0; o >>= 1) { if (t < o) sred[t] += sred[t + o]; __syncthreads(); }
        if (t == 0) part[blockIdx.y * gridDim.x + blockIdx.x] = sred[0];
    }
}

// ============================================================================
// lse combine
// ============================================================================
__global__ void __launch_bounds__(256) lse_combine(
    const float* __restrict__ pmax, const float* __restrict__ psum,
    float* __restrict__ lse, double* __restrict__ lse_part)
{
    __shared__ double sm[256];
    const int idx = blockIdx.x * 256 + threadIdx.x;
    const int bh = idx >> 10, n = idx & 1023;
    float ms[8], ss[8];
    float m = -CUDART_INF_F;
    #pragma unroll
    for (int i = 0; i < 8; i++) {
        ms[i] = pmax[((size_t)bh * 8 + i) * Nn + n];
        ss[i] = psum[((size_t)bh * 8 + i) * Nn + n];
        m = fmaxf(m, ms[i]);
    }
    float s = 0.f;
    #pragma unroll
    for (int i = 0; i < 8; i++) s += ss[i] * __expf(ms[i] - m);
    const float l = m + logf(s);
    lse[idx] = l;
    sm[threadIdx.x] = (double)l;
    __syncthreads();
    for (int o = 128; o > 0; o >>= 1) {
        if (threadIdx.x < o) sm[threadIdx.x] += sm[threadIdx.x + o];
        __syncthreads();
    }
    if (threadIdx.x == 0) lse_part[blockIdx.x] = sm[0];
}

// ============================================================================
// dQ-GEMM: dm2[(b*N+n)][h*64+q] = f16(-sum_m scale[n,blk]*P''[n][m] * Kt[q][m])
//   scale[n,blk] = exp(pmax[n,blk] - lse[n]); applied as per-row h2 multiply.
// ============================================================================
#define DQ_STAGE 27648
__global__ void __launch_bounds__(256) att_dq_h(
    const f16* __restrict__ P, const f16* __restrict__ Kt,
    const float* __restrict__ pmax, const float* __restrict__ lse,
    f16* __restrict__ dm)
{
    extern __shared__ char dsm[];
    const uint32_t sbase = smem_u32(dsm);
    const int t = threadIdx.x, wid = t >> 5, lane = t & 31;
    const int bh = blockIdx.y, n0 = blockIdx.x * 128;
    const f16* Ag = P + (size_t)bh * Nn * Nn;
    const f16* Bg = Kt + (size_t)bh * QKd * Nn;

    float acc[8][4];
    #pragma unroll
    for (int i = 0; i < 8; i++)
        #pragma unroll
        for (int r = 0; r < 4; r++) acc[i][r] = 0.f;

    const int lrow = t >> 3, lseg = (t & 7) * 8;
    const int xr = t >> 1, xh = (t & 1) * 64;
    const float xlse = lse[bh * Nn + n0 + xr];
    const float* pmrow = pmax + (size_t)bh * 8 * Nn + n0 + xr;

    auto load = [&](int kb) {
        const uint32_t ab = sbase + (uint32_t)(kb & 1) * DQ_STAGE;
        const uint32_t bb = ab + 18432;
        const size_t kEl = (size_t)(kb << 6) + lseg;
        #pragma unroll
        for (int i = 0; i < 4; i++) {
            const int row = lrow + i * 32;
            asm volatile("cp.async.cg.shared.global [%0], [%1], 16;"
                :: "r"(ab + row * ROWSTR + lseg * 2), "l"(Ag + (size_t)(n0 + row) * Nn + kEl));
        }
        #pragma unroll
        for (int i = 0; i < 2; i++) {
            const int row = lrow + i * 32;
            asm volatile("cp.async.cg.shared.global [%0], [%1], 16;"
                :: "r"(bb + row * ROWSTR + lseg * 2), "l"(Bg + (size_t)row * Nn + kEl));
        }
        asm volatile("cp.async.commit_group;" ::: "memory");
    };

    load(0);
    for (int kb = 0; kb < 16; kb++) {
        if (kb < 15) { load(kb + 1); asm volatile("cp.async.wait_group 1;" ::: "memory"); }
        else         { asm volatile("cp.async.wait_group 0;" ::: "memory"); }
        __syncthreads();
        {
            const float sc = __expf(pmrow[(size_t)(kb >> 1) * Nn] - xlse);
            const __half2 s2 = __float2half2_rn(sc);
            char* abuf = dsm + (size_t)(kb & 1) * DQ_STAGE + xr * ROWSTR + xh;
            #pragma unroll
            for (int j = 0; j < 4; j++) {
                uint4 w = *(uint4*)(abuf + j * 16);
                __half2* p2 = (__half2*)&w;
                #pragma unroll
                for (int q = 0; q < 4; q++) p2[q] = __hmul2(p2[q], s2);
                *(uint4*)(abuf + j * 16) = w;
            }
        }
        __syncthreads();
        const uint32_t ab = sbase + (uint32_t)(kb & 1) * DQ_STAGE;
        const uint32_t bb = ab + 18432;
        const int acol = ((lane >> 4) * 8) * 2;
        const int arow = lane & 15;
        const int brow = (lane & 7) + ((lane >> 3) & 1) * 8;
        #pragma unroll
        for (int kk = 0; kk < 4; kk++) {
            const int kbyte = kk * 32 + acol;
            uint32_t a[4];
            asm volatile("ldmatrix.sync.aligned.m8n8.x4.shared.b16 {%0,%1,%2,%3}, [%4];"
                : "=r"(a[0]), "=r"(a[1]), "=r"(a[2]), "=r"(a[3])
                : "r"(ab + (wid * 16 + arow) * ROWSTR + kbyte));
            uint32_t b[8][2];
            #pragma unroll
            for (int nfp = 0; nfp < 4; nfp++) {
                uint32_t r0, r1, r2, r3;
                asm volatile("ldmatrix.sync.aligned.m8n8.x4.shared.b16 {%0,%1,%2,%3}, [%4];"
                    : "=r"(r0), "=r"(r1), "=r"(r2), "=r"(r3)
                    : "r"(bb + (nfp * 16 + brow) * ROWSTR + kbyte));
                b[nfp * 2 + 0][0] = r0; b[nfp * 2 + 0][1] = r2;
                b[nfp * 2 + 1][0] = r1; b[nfp * 2 + 1][1] = r3;
            }
            #pragma unroll
            for (int nf = 0; nf < 8; nf++)
                asm volatile(
                    "mma.sync.aligned.m16n8k16.row.col.f32.f16.f16.f32 "
                    "{%0,%1,%2,%3}, {%4,%5,%6,%7}, {%8,%9}, {%0,%1,%2,%3};"
                    : "+f"(acc[nf][0]), "+f"(acc[nf][1]), "+f"(acc[nf][2]), "+f"(acc[nf][3])
                    : "r"(a[0]), "r"(a[1]), "r"(a[2]), "r"(a[3]),
                      "r"(b[nf][0]), "r"(b[nf][1]));
        }
        __syncthreads();
    }
    const int gr = lane >> 2, gc = (lane & 3) * 2;
    const int b_ = bh >> 4, h_ = bh & 15;
    #pragma unroll
    for (int nf = 0; nf < 8; nf++) {
        const int col = nf * 8 + gc;
        #pragma unroll
        for (int half = 0; half < 2; half++) {
            const int n = n0 + wid * 16 + gr + half * 8;
            *(uint32_t*)&dm[((size_t)(b_ * 1024 + n)) * BIGK + h_ * 64 + col] =
                pack_h2(-acc[nf][half * 2], -acc[nf][half * 2 + 1]);
        }
    }
}

// ============================================================================
// dK-GEMM: dm2[(b*N+m)][1024+h*64+q] = f16(-sum_n scale[n]*P''[n][m]*Qt[q][n])
//   block index = blockIdx.x (m-block); scale per n-row of each staged tile.
// ============================================================================
#define DK_ASTR 272
#define DK_STAGE 26624
__global__ void __launch_bounds__(256) att_dk_h(
    const f16* __restrict__ P, const f16* __restrict__ Qt,
    const float* __restrict__ pmax, const float* __restrict__ lse,
    f16* __restrict__ dm)
{
    extern __shared__ char dsm[];
    const uint32_t sbase = smem_u32(dsm);
    const int t = threadIdx.x, wid = t >> 5, lane = t & 31;
    const int bh = blockIdx.y, m0 = blockIdx.x * 128;
    const f16* Ag = P + (size_t)bh * Nn * Nn;
    const f16* Bg = Qt + (size_t)bh * QKd * Nn;
    const float* pmb = pmax + ((size_t)bh * 8 + blockIdx.x) * Nn;
    const float* lseb = lse + bh * Nn;

    float acc[8][4];
    #pragma unroll
    for (int i = 0; i < 8; i++)
        #pragma unroll
        for (int r = 0; r < 4; r++) acc[i][r] = 0.f;

    const int xr = t >> 2, xq = (t & 3) * 64;

    auto load = [&](int kb) {
        const uint32_t ab = sbase + (uint32_t)(kb & 1) * DK_STAGE;
        const uint32_t bb = ab + 17408;
        const int ar = t >> 4, aseg = (t & 15) * 8;
        #pragma unroll
        for (int i = 0; i < 4; i++) {
            const int row = ar + i * 16;
            asm volatile("cp.async.cg.shared.global [%0], [%1], 16;"
                :: "r"(ab + row * DK_ASTR + aseg * 2),
                   "l"(Ag + (size_t)((kb << 6) + row) * Nn + m0 + aseg));
        }
        const int br = t >> 3, bseg = (t & 7) * 8;
        #pragma unroll
        for (int i = 0; i < 2; i++) {
            const int row = br + i * 32;
            asm volatile("cp.async.cg.shared.global [%0], [%1], 16;"
                :: "r"(bb + row * ROWSTR + bseg * 2),
                   "l"(Bg + (size_t)row * Nn + (kb << 6) + bseg));
        }
        asm volatile("cp.async.commit_group;" ::: "memory");
    };

    load(0);
    for (int kb = 0; kb < 16; kb++) {
        if (kb < 15) { load(kb + 1); asm volatile("cp.async.wait_group 1;" ::: "memory"); }
        else         { asm volatile("cp.async.wait_group 0;" ::: "memory"); }
        __syncthreads();
        {
            const int n = (kb << 6) + xr;
            const float sc = __expf(pmb[n] - lseb[n]);
            const __half2 s2 = __float2half2_rn(sc);
            char* abuf = dsm + (size_t)(kb & 1) * DK_STAGE + xr * DK_ASTR + xq;
            #pragma unroll
            for (int j = 0; j < 4; j++) {
                uint4 w = *(uint4*)(abuf + j * 16);
                __half2* p2 = (__half2*)&w;
                #pragma unroll
                for (int q = 0; q < 4; q++) p2[q] = __hmul2(p2[q], s2);
                *(uint4*)(abuf + j * 16) = w;
            }
        }
        __syncthreads();
        const uint32_t ab = sbase + (uint32_t)(kb & 1) * DK_STAGE;
        const uint32_t bb = ab + 17408;
        const int tl = lane >> 3;
        const int brow = (lane & 7) + ((lane >> 3) & 1) * 8;
        const int bcol = ((lane >> 4) * 8) * 2;
        #pragma unroll
        for (int kk = 0; kk < 4; kk++) {
            uint32_t a[4];
            const uint32_t ad = ab + (kk * 16 + (tl >> 1) * 8 + (lane & 7)) * DK_ASTR
                              + (wid * 16 + (tl & 1) * 8) * 2;
            asm volatile("ldmatrix.sync.aligned.m8n8.x4.trans.shared.b16 {%0,%1,%2,%3}, [%4];"
                : "=r"(a[0]), "=r"(a[1]), "=r"(a[2]), "=r"(a[3]) : "r"(ad));
            uint32_t b[8][2];
            const int kbyte = kk * 32 + bcol;
            #pragma unroll
            for (int nfp = 0; nfp < 4; nfp++) {
                uint32_t r0, r1, r2, r3;
                asm volatile("ldmatrix.sync.aligned.m8n8.x4.shared.b16 {%0,%1,%2,%3}, [%4];"
                    : "=r"(r0), "=r"(r1), "=r"(r2), "=r"(r3)
                    : "r"(bb + (nfp * 16 + brow) * ROWSTR + kbyte));
                b[nfp * 2 + 0][0] = r0; b[nfp * 2 + 0][1] = r2;
                b[nfp * 2 + 1][0] = r1; b[nfp * 2 + 1][1] = r3;
            }
            #pragma unroll
            for (int nf = 0; nf < 8; nf++)
                asm volatile(
                    "mma.sync.aligned.m16n8k16.row.col.f32.f16.f16.f32 "
                    "{%0,%1,%2,%3}, {%4,%5,%6,%7}, {%8,%9}, {%0,%1,%2,%3};"
                    : "+f"(acc[nf][0]), "+f"(acc[nf][1]), "+f"(acc[nf][2]), "+f"(acc[nf][3])
                    : "r"(a[0]), "r"(a[1]), "r"(a[2]), "r"(a[3]),
                      "r"(b[nf][0]), "r"(b[nf][1]));
        }
        __syncthreads();
    }
    const int gr = lane >> 2, gc = (lane & 3) * 2;
    const int b_ = bh >> 4, h_ = bh & 15;
    #pragma unroll
    for (int nf = 0; nf < 8; nf++) {
        const int col = nf * 8 + gc;
        #pragma unroll
        for (int half = 0; half < 2; half++) {
            const int m = m0 + wid * 16 + gr + half * 8;
            *(uint32_t*)&dm[((size_t)(b_ * 1024 + m)) * BIGK + 1024 + h_ * 64 + col] =
                pack_h2(-acc[nf][half * 2], -acc[nf][half * 2 + 1]);
        }
    }
}

// ============================================================================
// Final energy
// ============================================================================
__global__ void energy_final(const double* __restrict__ lse_part,
                             const double* __restrict__ h2_part,
                             float* __restrict__ out)
{
    __shared__ double sm[256];
    int t = threadIdx.x;
    double s = 0.0;
    for (int i = t; i < LSE_PARTS; i += 256) s += lse_part[i];
    double s2 = 0.0;
    for (int i = t; i < (BNr / 128) * (HIDd / 128); i += 256) s2 += h2_part[i];
    sm[t] = -8.0 * s - 0.5 * s2;
    __syncthreads();
    for (int o = 128; o > 0; o >>= 1) { if (t < o) sm[t] += sm[t + o]; __syncthreads(); }
    if (t == 0) out[(size_t)BNr * Dd] = (float)sm[0];
}

// ============================================================================
// Host launcher
// ============================================================================
extern "C" void kernel_launch(void* const* d_in, const int* in_sizes, int n_in,
                              void* d_out, int out_size)
{
    const float* x    = (const float*)d_in[0];
    const float* Wq   = (const float*)d_in[1];
    const float* Wk   = (const float*)d_in[2];
    const float* Whop = (const float*)d_in[3];
    float* out = (float*)d_out;

    f16 *pPb;
    float *pLseV, *pPmax, *pPsum;
    double *pLse, *pH2;
    f16 *px1, *pwqk, *pwtb, *pwht1, *pdm2, *pqk, *pqt, *pkt;

    cudaGetSymbolAddress((void**)&pPb,  g_Pb);
    cudaGetSymbolAddress((void**)&pLseV,g_lse);
    cudaGetSymbolAddress((void**)&pPmax,g_pmax);
    cudaGetSymbolAddress((void**)&pPsum,g_psum);
    cudaGetSymbolAddress((void**)&pLse, g_lse_part);
    cudaGetSymbolAddress((void**)&pH2,  g_h2_part);
    cudaGetSymbolAddress((void**)&px1,  g_x1);
    cudaGetSymbolAddress((void**)&pwqk, g_wqk);
    cudaGetSymbolAddress((void**)&pwtb, g_wtb);
    cudaGetSymbolAddress((void**)&pwht1,g_wht1);
    cudaGetSymbolAddress((void**)&pdm2, g_dm2);
    cudaGetSymbolAddress((void**)&pqk,  g_qk);
    cudaGetSymbolAddress((void**)&pqt,  g_qt);  cudaGetSymbolAddress((void**)&pkt,  g_kt);

    cudaFuncSetAttribute(tgemm<0>, cudaFuncAttributeMaxDynamicSharedMemorySize, TG_SMEM);
    cudaFuncSetAttribute(tgemm<1>, cudaFuncAttributeMaxDynamicSharedMemorySize, TG_SMEM);
    cudaFuncSetAttribute(tgemm<2>, cudaFuncAttributeMaxDynamicSharedMemorySize, TG_SMEM);
    cudaFuncSetAttribute(tgemm<4>, cudaFuncAttributeMaxDynamicSharedMemorySize, TG_SMEM);
    cudaFuncSetAttribute(att_dq_h, cudaFuncAttributeMaxDynamicSharedMemorySize, 2 * DQ_STAGE);
    cudaFuncSetAttribute(att_dk_h, cudaFuncAttributeMaxDynamicSharedMemorySize, 2 * DK_STAGE);

    dim3 blk(256);

    // 0. input conversions: x cvt; fused cvt+trans per weight
    cvt_plain4<<<(BNr * Dd) / 1024, blk>>>(x, px1);
    cvt_trans<<<dim3(Dd / 32, HQ / 32), blk>>>(Wq, Dd, pwqk, Dd, pwtb, BIGK);
    cvt_trans<<<dim3(Dd / 32, HQ / 32), blk>>>(Wk, Dd, pwqk + (size_t)HQ * Dd, Dd,
                                               pwtb + 1024, BIGK);
    cvt_trans<<<dim3(HIDd / 32, Dd / 32), blk>>>(Whop, HIDd, pwtb + 2048, BIGK, pwht1, Dd);

    // 1. merged Q/K projection (N=2048) -> f16 qk scattered [q|k][bh][n][qk]
    tgemm<1><<<dim3(2048 / 128, BNr / 128, 1), blk, TG_SMEM>>>(
        px1, pwqk, nullptr, 0, Dd, 1.f, pqk, nullptr, nullptr, nullptr, 0, 0, 0);

    // 2. transposes for dq/dk B-operands
    trans_qk<<<dim3(Nn / 32, QKd / 32, BH), blk>>>(pqk, pqk + KOFF, pqt, pkt);

    // 3. P'' = exp(BETA*QK^T - blockmax) -> f16 Pb + pmax/psum
    tgemm<4><<<dim3(Nn / 128, Nn / 128, BH), blk, TG_SMEM>>>(
        pqk, pqk + KOFF, nullptr, Nn, QKd, BETA, pPb, nullptr,
        pPmax, pPsum, (size_t)Nn * QKd, (size_t)Nn * QKd, (size_t)Nn * Nn);

    // 4. lse combine (+ energy partials)
    lse_combine<<<LSE_PARTS, blk>>>(pPmax, pPsum, pLseV, pLse);

    // 5. dQm, dKm (scale-multiply, no exp) -> dm2 cols [0,2048)
    att_dq_h<<<dim3(Nn / 128, BH), blk, 2 * DQ_STAGE>>>(pPb, pkt, pPmax, pLseV, pdm2);
    att_dk_h<<<dim3(Nn / 128, BH), blk, 2 * DK_STAGE>>>(pPb, pqt, pPmax, pLseV, pdm2);

    // 6. Hb: -relu(x1 @ WhopT) -> dm2 cols [2048,6144); h2 partials
    tgemm<2><<<dim3(HIDd / 128, BNr / 128, 1), blk, TG_SMEM>>>(
        px1, pwht1, nullptr, BIGK, Dd, 1.f, pdm2 + 2048, pH2,
        nullptr, nullptr, 0, 0, 0);

    // 7. grad = dm2 @ [WqT|WkT|Whop]  (single K=6144 GEMM)
    tgemm<0><<<dim3(Dd / 128, BNr / 128, 1), blk, TG_SMEM>>>(
        pdm2, pwtb, out, Dd, BIGK, 1.f, nullptr, nullptr,
        nullptr, nullptr, 0, 0, 0);

    // 8. energy scalar
    if (out_size > BNr * Dd)
        energy_final<<<1, 256>>>(pLse, pH2, out);
}